// round 1
// baseline (speedup 1.0000x reference)
#include <cuda_runtime.h>
#include <cuda_bf16.h>
#include <math.h>

// Problem constants
#define NB   4
#define LEN  5440
#define NTOK (NB * LEN)          // 21760
#define CCH  256
#define NH   8
#define DH   32
#define NL   4
#define NP   4
#define DFF  1024
#define LN_EPS 1e-5f

// Scratch (device globals — no allocation allowed)
__device__ float g_q   [NTOK * CCH];   // q = src + pos ; later reused for attn_out
__device__ float g_off [NTOK * CCH];   // sampling offsets ; later reused for ffn out
__device__ float g_aw  [NTOK * 128];   // attn logits -> softmaxed weights
__device__ float g_val [NTOK * CCH];   // value projection
__device__ float g_msda[NTOK * CCH];   // msda output
__device__ float g_x   [NTOK * CCH];   // post-LN1
__device__ float g_h   [NTOK * DFF];   // ffn hidden

// ---------------------------------------------------------------------------
// elementwise add (q = src + pos), float4
// ---------------------------------------------------------------------------
__global__ void add_kernel(const float* __restrict__ a, const float* __restrict__ b,
                           float* __restrict__ o, int n4) {
    int i = blockIdx.x * blockDim.x + threadIdx.x;
    if (i >= n4) return;
    float4 va = ((const float4*)a)[i];
    float4 vb = ((const float4*)b)[i];
    float4 vo = make_float4(va.x + vb.x, va.y + vb.y, va.z + vb.z, va.w + vb.w);
    ((float4*)o)[i] = vo;
}

// ---------------------------------------------------------------------------
// Tiled SGEMM: C[M,N] = A[M,K] @ B[K,N] + bias[N], optional ReLU.
// BM=BN=128, BK=16, 256 threads, 8x8 per thread. M%128==0, N%128==0, K%16==0.
// ---------------------------------------------------------------------------
#define BM 128
#define BN 128
#define BK 16
#define TM 8
#define TN 8

__global__ __launch_bounds__(256, 2)
void sgemm_kernel(const float* __restrict__ A, const float* __restrict__ Bm,
                  const float* __restrict__ bias, float* __restrict__ C,
                  int M, int N, int K, int act) {
    __shared__ float As[BK][BM];
    __shared__ float Bs[BK][BN];

    const int bx = blockIdx.x, by = blockIdx.y;
    const int tid = threadIdx.x;
    const int tcol = tid & 15;   // 0..15  (BN/TN)
    const int trow = tid >> 4;   // 0..15  (BM/TM)

    float acc[TM][TN];
    #pragma unroll
    for (int i = 0; i < TM; i++)
        #pragma unroll
        for (int j = 0; j < TN; j++) acc[i][j] = 0.f;

    const float* Aptr = A + (size_t)by * BM * K;
    const float* Bptr = Bm + (size_t)bx * BN;

    // A tile loader: 128x16 floats = 512 float4; 2 per thread
    const int aRow = tid >> 2;           // 0..63
    const int aCol = (tid & 3) * 4;      // 0,4,8,12
    // B tile loader: 16x128 floats = 512 float4; 2 per thread
    const int bRow = tid >> 5;           // 0..7
    const int bCol = (tid & 31) * 4;     // 0..124

    for (int k0 = 0; k0 < K; k0 += BK) {
        #pragma unroll
        for (int i = 0; i < 2; i++) {
            int r = aRow + i * 64;
            float4 v = *(const float4*)(Aptr + (size_t)r * K + k0 + aCol);
            As[aCol + 0][r] = v.x;
            As[aCol + 1][r] = v.y;
            As[aCol + 2][r] = v.z;
            As[aCol + 3][r] = v.w;
        }
        #pragma unroll
        for (int i = 0; i < 2; i++) {
            int r = bRow + i * 8;
            float4 v = *(const float4*)(Bptr + (size_t)(k0 + r) * N + bCol);
            *(float4*)&Bs[r][bCol] = v;
        }
        __syncthreads();

        #pragma unroll
        for (int kk = 0; kk < BK; kk++) {
            float a[TM], b[TN];
            #pragma unroll
            for (int i = 0; i < TM; i++) a[i] = As[kk][trow * TM + i];
            #pragma unroll
            for (int j = 0; j < TN; j++) b[j] = Bs[kk][tcol * TN + j];
            #pragma unroll
            for (int i = 0; i < TM; i++)
                #pragma unroll
                for (int j = 0; j < TN; j++)
                    acc[i][j] = fmaf(a[i], b[j], acc[i][j]);
        }
        __syncthreads();
    }

    const int col0 = bx * BN + tcol * TN;
    #pragma unroll
    for (int i = 0; i < TM; i++) {
        int row = by * BM + trow * TM + i;
        float out[TN];
        #pragma unroll
        for (int j = 0; j < TN; j++) {
            float v = acc[i][j] + bias[col0 + j];
            if (act) v = fmaxf(v, 0.f);
            out[j] = v;
        }
        *(float4*)(C + (size_t)row * N + col0)     = *(float4*)&out[0];
        *(float4*)(C + (size_t)row * N + col0 + 4) = *(float4*)&out[4];
    }
}

// ---------------------------------------------------------------------------
// softmax over groups of 16 (per token, per head)
// ---------------------------------------------------------------------------
__global__ void softmax16_kernel(float* __restrict__ aw, int ngroups) {
    int i = blockIdx.x * blockDim.x + threadIdx.x;
    if (i >= ngroups) return;
    float* p = aw + (size_t)i * 16;
    float v[16];
    float mx = -1e30f;
    #pragma unroll
    for (int j = 0; j < 16; j++) { v[j] = p[j]; mx = fmaxf(mx, v[j]); }
    float s = 0.f;
    #pragma unroll
    for (int j = 0; j < 16; j++) { v[j] = __expf(v[j] - mx); s += v[j]; }
    float inv = 1.f / s;
    #pragma unroll
    for (int j = 0; j < 16; j++) p[j] = v[j] * inv;
}

// ---------------------------------------------------------------------------
// MSDA core: warp per (token, head), lane = channel within head (DH=32).
// ---------------------------------------------------------------------------
__global__ void msda_kernel(const float* __restrict__ value,
                            const float* __restrict__ off,
                            const float* __restrict__ aw,
                            const float* __restrict__ refp,
                            float* __restrict__ out) {
    const int gtid = blockIdx.x * blockDim.x + threadIdx.x;
    const int warp = gtid >> 5;
    const int lane = gtid & 31;
    const int total = NTOK * NH;
    if (warp >= total) return;

    const int h = warp & (NH - 1);
    const int t = warp >> 3;            // b*LEN + q
    const int b = t / LEN;

    const float* off_row = off + (size_t)t * CCH + h * (NL * NP * 2);
    const float* aw_row  = aw  + (size_t)t * 128 + h * (NL * NP);
    const float* ref_row = refp + (size_t)t * (NL * 2);
    const float* vbase   = value + ((size_t)b * LEN) * CCH + h * DH + lane;

    const int   dims[NL]   = {64, 32, 16, 8};
    const int   starts[NL] = {0, 4096, 5120, 5376};

    float acc = 0.f;

    #pragma unroll
    for (int l = 0; l < NL; l++) {
        const int Wl = dims[l];
        const int Hl = dims[l];
        const float fW = (float)Wl, fH = (float)Hl;
        const float rx = ref_row[2 * l];
        const float ry = ref_row[2 * l + 1];
        const float* vl = vbase + (size_t)starts[l] * CCH;

        #pragma unroll
        for (int p = 0; p < NP; p++) {
            const float ox = off_row[(l * NP + p) * 2];
            const float oy = off_row[(l * NP + p) * 2 + 1];
            const float px = (rx + ox / fW) * fW - 0.5f;
            const float py = (ry + oy / fH) * fH - 0.5f;
            const float fx = floorf(px), fy = floorf(py);
            const int x0 = (int)fx, y0 = (int)fy;
            const int x1 = x0 + 1,  y1 = y0 + 1;
            const float wx1 = px - fx, wy1 = py - fy;
            const float wx0 = 1.f - wx1, wy0 = 1.f - wy1;
            const float a = aw_row[l * NP + p];
            const float w00 = a * wx0 * wy0, w10 = a * wx1 * wy0;
            const float w01 = a * wx0 * wy1, w11 = a * wx1 * wy1;

            const bool vx0 = (x0 >= 0) & (x0 < Wl);
            const bool vx1 = (x1 >= 0) & (x1 < Wl);
            const bool vy0 = (y0 >= 0) & (y0 < Hl);
            const bool vy1 = (y1 >= 0) & (y1 < Hl);
            const int cx0 = min(max(x0, 0), Wl - 1);
            const int cx1 = min(max(x1, 0), Wl - 1);
            const int cy0 = min(max(y0, 0), Hl - 1);
            const int cy1 = min(max(y1, 0), Hl - 1);

            if (vy0 & vx0) acc = fmaf(w00, vl[(size_t)(cy0 * Wl + cx0) * CCH], acc);
            if (vy0 & vx1) acc = fmaf(w10, vl[(size_t)(cy0 * Wl + cx1) * CCH], acc);
            if (vy1 & vx0) acc = fmaf(w01, vl[(size_t)(cy1 * Wl + cx0) * CCH], acc);
            if (vy1 & vx1) acc = fmaf(w11, vl[(size_t)(cy1 * Wl + cx1) * CCH], acc);
        }
    }
    out[(size_t)t * CCH + h * DH + lane] = acc;
}

// ---------------------------------------------------------------------------
// LayerNorm over C=256 of (a+b): warp per row, 8 elems per lane.
// ---------------------------------------------------------------------------
__global__ void ln_kernel(const float* __restrict__ a, const float* __restrict__ b,
                          const float* __restrict__ g, const float* __restrict__ be,
                          float* __restrict__ out, int rows) {
    const int row = blockIdx.x * (blockDim.x >> 5) + (threadIdx.x >> 5);
    const int lane = threadIdx.x & 31;
    if (row >= rows) return;

    const float* pa = a + (size_t)row * CCH;
    const float* pb = b + (size_t)row * CCH;
    float v[8];
    float s = 0.f;
    #pragma unroll
    for (int j = 0; j < 8; j++) {
        int c = lane + 32 * j;
        v[j] = pa[c] + pb[c];
        s += v[j];
    }
    #pragma unroll
    for (int o = 16; o > 0; o >>= 1) s += __shfl_xor_sync(0xffffffffu, s, o);
    const float mean = s * (1.f / CCH);
    float s2 = 0.f;
    #pragma unroll
    for (int j = 0; j < 8; j++) { float d = v[j] - mean; s2 += d * d; }
    #pragma unroll
    for (int o = 16; o > 0; o >>= 1) s2 += __shfl_xor_sync(0xffffffffu, s2, o);
    const float inv = rsqrtf(s2 * (1.f / CCH) + LN_EPS);

    float* po = out + (size_t)row * CCH;
    #pragma unroll
    for (int j = 0; j < 8; j++) {
        int c = lane + 32 * j;
        po[c] = (v[j] - mean) * inv * g[c] + be[c];
    }
}

// ---------------------------------------------------------------------------
// launch
// ---------------------------------------------------------------------------
extern "C" void kernel_launch(void* const* d_in, const int* in_sizes, int n_in,
                              void* d_out, int out_size) {
    const float* src   = (const float*)d_in[0];
    const float* pos   = (const float*)d_in[1];
    const float* refp  = (const float*)d_in[2];
    // d_in[3] spatial_shapes, d_in[4] level_start_index, d_in[5] valid_ratios: compile-time constants / unused
    const float* w_off  = (const float*)d_in[6];
    const float* b_off  = (const float*)d_in[7];
    const float* w_attn = (const float*)d_in[8];
    const float* b_attn = (const float*)d_in[9];
    const float* w_val  = (const float*)d_in[10];
    const float* b_val  = (const float*)d_in[11];
    const float* w_out  = (const float*)d_in[12];
    const float* b_out  = (const float*)d_in[13];
    const float* g1     = (const float*)d_in[14];
    const float* be1    = (const float*)d_in[15];
    const float* w1     = (const float*)d_in[16];
    const float* b1     = (const float*)d_in[17];
    const float* w2     = (const float*)d_in[18];
    const float* b2     = (const float*)d_in[19];
    const float* g2     = (const float*)d_in[20];
    const float* be2    = (const float*)d_in[21];
    float* out = (float*)d_out;

    float *p_q, *p_off, *p_aw, *p_val, *p_msda, *p_x, *p_h;
    cudaGetSymbolAddress((void**)&p_q,    g_q);
    cudaGetSymbolAddress((void**)&p_off,  g_off);
    cudaGetSymbolAddress((void**)&p_aw,   g_aw);
    cudaGetSymbolAddress((void**)&p_val,  g_val);
    cudaGetSymbolAddress((void**)&p_msda, g_msda);
    cudaGetSymbolAddress((void**)&p_x,    g_x);
    cudaGetSymbolAddress((void**)&p_h,    g_h);

    const int M = NTOK;                     // 21760 = 170 * 128
    const dim3 blk(256);

    // 1. q = src + pos
    {
        int n4 = NTOK * CCH / 4;
        add_kernel<<<(n4 + 255) / 256, blk>>>(src, pos, p_q, n4);
    }
    // 2. off = q @ w_off + b_off        [M,256]x[256,256]
    sgemm_kernel<<<dim3(CCH / BN, M / BM), blk>>>(p_q, w_off, b_off, p_off, M, CCH, CCH, 0);
    // 3. logits = q @ w_attn + b_attn   [M,256]x[256,128]
    sgemm_kernel<<<dim3(128 / BN, M / BM), blk>>>(p_q, w_attn, b_attn, p_aw, M, 128, CCH, 0);
    // 4. softmax over each 16-group
    {
        int ngroups = NTOK * NH;
        softmax16_kernel<<<(ngroups + 255) / 256, blk>>>(p_aw, ngroups);
    }
    // 5. value = src @ w_val + b_val
    sgemm_kernel<<<dim3(CCH / BN, M / BM), blk>>>(src, w_val, b_val, p_val, M, CCH, CCH, 0);
    // 6. MSDA gather
    {
        int nthreads = NTOK * NH * 32;
        msda_kernel<<<nthreads / 256, blk>>>(p_val, p_off, p_aw, refp, p_msda);
    }
    // 7. attn_out = msda @ w_out + b_out   (reuse g_q)
    sgemm_kernel<<<dim3(CCH / BN, M / BM), blk>>>(p_msda, w_out, b_out, p_q, M, CCH, CCH, 0);
    // 8. x = LN(src + attn_out)
    ln_kernel<<<(NTOK + 7) / 8, blk>>>(src, p_q, g1, be1, p_x, NTOK);
    // 9. h = relu(x @ w1 + b1)          [M,256]x[256,1024]
    sgemm_kernel<<<dim3(DFF / BN, M / BM), blk>>>(p_x, w1, b1, p_h, M, DFF, CCH, 1);
    // 10. ffn = h @ w2 + b2             [M,1024]x[1024,256]  (reuse g_off)
    sgemm_kernel<<<dim3(CCH / BN, M / BM), blk>>>(p_h, w2, b2, p_off, M, CCH, DFF, 0);
    // 11. out = LN(x + ffn)
    ln_kernel<<<(NTOK + 7) / 8, blk>>>(p_x, p_off, g2, be2, out, NTOK);
}

// round 2
// speedup vs baseline: 1.5133x; 1.5133x over previous
#include <cuda_runtime.h>
#include <cuda_bf16.h>
#include <math.h>

// Problem constants
#define NB   4
#define LEN  5440
#define NTOK (NB * LEN)          // 21760
#define CCH  256
#define NH   8
#define DH   32
#define NL   4
#define NP   4
#define DFF  1024
#define LN_EPS 1e-5f

// ---------------------------------------------------------------------------
// Scratch (device globals — no allocation allowed)
// Activations as bf16 "triples": [M][3K] = [hi | lo | hi]
// Weights transposed triples:    [N][3K] = [hi | hi | lo]
// ---------------------------------------------------------------------------
__device__ __nv_bfloat16 g_q3   [NTOK * 3 * CCH];   // q = src+pos (triple)
__device__ __nv_bfloat16 g_src3 [NTOK * 3 * CCH];   // src (triple)
__device__ __nv_bfloat16 g_msda3[NTOK * 3 * CCH];   // msda out (triple)
__device__ __nv_bfloat16 g_x3   [NTOK * 3 * CCH];   // post-LN1 (triple)
__device__ __nv_bfloat16 g_h3   [NTOK * 3 * DFF];   // ffn hidden (triple)

__device__ float g_off [NTOK * CCH];    // sampling offsets (fp32)
__device__ float g_aw  [NTOK * 128];    // attn logits -> softmax weights
__device__ float g_val [NTOK * CCH];    // value projection (fp32)
__device__ float g_attn[NTOK * CCH];    // attn_out (fp32)
__device__ float g_x   [NTOK * CCH];    // post-LN1 (fp32, residual)
__device__ float g_ffn [NTOK * CCH];    // ffn out (fp32)

// transposed weight triples
__device__ __nv_bfloat16 g_woff3 [CCH * 3 * CCH];
__device__ __nv_bfloat16 g_wattn3[128 * 3 * CCH];
__device__ __nv_bfloat16 g_wval3 [CCH * 3 * CCH];
__device__ __nv_bfloat16 g_wout3 [CCH * 3 * CCH];
__device__ __nv_bfloat16 g_w13   [DFF * 3 * CCH];
__device__ __nv_bfloat16 g_w23   [CCH * 3 * DFF];

// ---------------------------------------------------------------------------
// helpers
// ---------------------------------------------------------------------------
__device__ __forceinline__ void store_triple(__nv_bfloat16* p, int N, float a, float b) {
    __nv_bfloat16 ah = __float2bfloat16(a), bh = __float2bfloat16(b);
    float ar = a - __bfloat162float(ah);
    float br = b - __bfloat162float(bh);
    __nv_bfloat162 hi = __halves2bfloat162(ah, bh);
    __nv_bfloat162 lo = __halves2bfloat162(__float2bfloat16(ar), __float2bfloat16(br));
    *(__nv_bfloat162*)(p)         = hi;
    *(__nv_bfloat162*)(p + N)     = lo;
    *(__nv_bfloat162*)(p + 2 * N) = hi;
}

__device__ __forceinline__ void store_triple1(__nv_bfloat16* p, int N, float a) {
    __nv_bfloat16 ah = __float2bfloat16(a);
    float ar = a - __bfloat162float(ah);
    p[0]     = ah;
    p[N]     = __float2bfloat16(ar);
    p[2 * N] = ah;
}

__device__ __forceinline__ void cp_async16(unsigned int dst, const void* src) {
    asm volatile("cp.async.cg.shared.global [%0], [%1], 16;\n" :: "r"(dst), "l"(src));
}

__device__ __forceinline__ void mma_bf16(float c[4],
                                         unsigned a0, unsigned a1, unsigned a2, unsigned a3,
                                         unsigned b0, unsigned b1) {
    asm volatile(
        "mma.sync.aligned.m16n8k16.row.col.f32.bf16.bf16.f32 "
        "{%0,%1,%2,%3},{%4,%5,%6,%7},{%8,%9},{%0,%1,%2,%3};"
        : "+f"(c[0]), "+f"(c[1]), "+f"(c[2]), "+f"(c[3])
        : "r"(a0), "r"(a1), "r"(a2), "r"(a3), "r"(b0), "r"(b1));
}

// ---------------------------------------------------------------------------
// activation triple conversion: O[row][3K] from A (optionally + B)
// ---------------------------------------------------------------------------
__global__ void act3_kernel(const float* __restrict__ A, const float* __restrict__ B,
                            __nv_bfloat16* __restrict__ O, int K, int n2) {
    int i = blockIdx.x * blockDim.x + threadIdx.x;
    if (i >= n2) return;
    float2 v = ((const float2*)A)[i];
    if (B) { float2 w = ((const float2*)B)[i]; v.x += w.x; v.y += w.y; }
    int row = i / (K / 2);
    int c2  = i % (K / 2);
    store_triple(O + (size_t)row * 3 * K + c2 * 2, K, v.x, v.y);
}

// ---------------------------------------------------------------------------
// weight triple conversion: W[K][N] fp32 -> Bt[N][3K] bf16 [hi|hi|lo]
// ---------------------------------------------------------------------------
__global__ void wt3_kernel(const float* __restrict__ W, __nv_bfloat16* __restrict__ Bt,
                           int K, int N) {
    int i = blockIdx.x * blockDim.x + threadIdx.x;
    if (i >= K * N) return;
    int k = i / N, n = i % N;
    float v = W[i];
    __nv_bfloat16 h = __float2bfloat16(v);
    __nv_bfloat16 l = __float2bfloat16(v - __bfloat162float(h));
    __nv_bfloat16* p = Bt + (size_t)n * 3 * K + k;
    p[0]     = h;
    p[K]     = h;
    p[2 * K] = l;
}

// ---------------------------------------------------------------------------
// bf16 tensor-core GEMM: C[M,N] = A3[M,K3] @ B3t[N,K3]^T + bias
// BM=BN=128, BK=32, 256 threads, 8 warps (2m x 4n), mma m16n8k16.
// mode 0: fp32 out. mode 1: relu + bf16-triple out (row length 3N).
// ---------------------------------------------------------------------------
#define GBM 128
#define GBN 128
#define GBK 32
#define SSTR 20   // u32 per smem row (40 bf16 = 80B; conflict-free stride)

__global__ __launch_bounds__(256, 2)
void bgemm_kernel(const __nv_bfloat16* __restrict__ A,
                  const __nv_bfloat16* __restrict__ Bt,
                  const float* __restrict__ bias,
                  float* __restrict__ Cf,
                  __nv_bfloat16* __restrict__ C3,
                  int M, int N, int K3, int mode) {
    __shared__ unsigned int As[2][GBM * SSTR];
    __shared__ unsigned int Bs[2][GBM * SSTR];

    const int tid  = threadIdx.x;
    const int bx   = blockIdx.x, by = blockIdx.y;
    const int warp = tid >> 5, lane = tid & 31;
    const int wm = warp & 1, wn = warp >> 1;   // 2 x 4 warp grid
    const int g  = lane >> 2, t = lane & 3;

    float acc[4][4][4];
    #pragma unroll
    for (int i = 0; i < 4; i++)
        #pragma unroll
        for (int j = 0; j < 4; j++)
            #pragma unroll
            for (int r = 0; r < 4; r++) acc[i][j][r] = 0.f;

    const __nv_bfloat16* Ablk = A  + (size_t)by * GBM * K3;
    const __nv_bfloat16* Bblk = Bt + (size_t)bx * GBN * K3;

    unsigned int asBase = (unsigned int)__cvta_generic_to_shared(&As[0][0]);
    unsigned int bsBase = (unsigned int)__cvta_generic_to_shared(&Bs[0][0]);

    const int r0 = tid >> 2;          // 0..63
    const int c8 = tid & 3;           // 16B chunk within 64B row

    const int KT = K3 / GBK;

    // prologue: stage 0
    {
        #pragma unroll
        for (int i = 0; i < 2; i++) {
            int r = r0 + i * 64;
            unsigned int off = (unsigned int)((r * SSTR + c8 * 4) * 4);
            cp_async16(asBase + off, Ablk + (size_t)r * K3 + c8 * 8);
            cp_async16(bsBase + off, Bblk + (size_t)r * K3 + c8 * 8);
        }
        asm volatile("cp.async.commit_group;\n");
    }

    for (int kt = 0; kt < KT; kt++) {
        const int cur = kt & 1;
        if (kt + 1 < KT) {
            const int nxt = cur ^ 1;
            const int k0 = (kt + 1) * GBK;
            #pragma unroll
            for (int i = 0; i < 2; i++) {
                int r = r0 + i * 64;
                unsigned int off = (unsigned int)((nxt * GBM * SSTR + r * SSTR + c8 * 4) * 4);
                cp_async16(asBase + off, Ablk + (size_t)r * K3 + k0 + c8 * 8);
                cp_async16(bsBase + off, Bblk + (size_t)r * K3 + k0 + c8 * 8);
            }
            asm volatile("cp.async.commit_group;\n");
            asm volatile("cp.async.wait_group 1;\n");
        } else {
            asm volatile("cp.async.wait_group 0;\n");
        }
        __syncthreads();

        const unsigned int* as = As[cur];
        const unsigned int* bs = Bs[cur];

        #pragma unroll
        for (int ks = 0; ks < 2; ks++) {
            const int kc = ks * 8;  // u32 col offset (16 bf16)
            unsigned int af[4][4], bfr[4][2];
            #pragma unroll
            for (int mi = 0; mi < 4; mi++) {
                int rm = wm * 64 + mi * 16 + g;
                af[mi][0] = as[rm * SSTR + kc + t];
                af[mi][1] = as[(rm + 8) * SSTR + kc + t];
                af[mi][2] = as[rm * SSTR + kc + t + 4];
                af[mi][3] = as[(rm + 8) * SSTR + kc + t + 4];
            }
            #pragma unroll
            for (int ni = 0; ni < 4; ni++) {
                int rn = wn * 32 + ni * 8 + g;
                bfr[ni][0] = bs[rn * SSTR + kc + t];
                bfr[ni][1] = bs[rn * SSTR + kc + t + 4];
            }
            #pragma unroll
            for (int mi = 0; mi < 4; mi++)
                #pragma unroll
                for (int ni = 0; ni < 4; ni++)
                    mma_bf16(acc[mi][ni], af[mi][0], af[mi][1], af[mi][2], af[mi][3],
                             bfr[ni][0], bfr[ni][1]);
        }
        __syncthreads();
    }

    // epilogue
    const int colb = bx * GBN + wn * 32;
    #pragma unroll
    for (int mi = 0; mi < 4; mi++) {
        int row0 = by * GBM + wm * 64 + mi * 16 + g;
        #pragma unroll
        for (int ni = 0; ni < 4; ni++) {
            int col = colb + ni * 8 + 2 * t;
            float b0 = bias[col], b1 = bias[col + 1];
            float v00 = acc[mi][ni][0] + b0, v01 = acc[mi][ni][1] + b1;
            float v10 = acc[mi][ni][2] + b0, v11 = acc[mi][ni][3] + b1;
            if (mode == 0) {
                *(float2*)(Cf + (size_t)row0 * N + col)       = make_float2(v00, v01);
                *(float2*)(Cf + (size_t)(row0 + 8) * N + col) = make_float2(v10, v11);
            } else {
                v00 = fmaxf(v00, 0.f); v01 = fmaxf(v01, 0.f);
                v10 = fmaxf(v10, 0.f); v11 = fmaxf(v11, 0.f);
                store_triple(C3 + (size_t)row0 * 3 * N + col, N, v00, v01);
                store_triple(C3 + (size_t)(row0 + 8) * 3 * N + col, N, v10, v11);
            }
        }
    }
}

// ---------------------------------------------------------------------------
// softmax over groups of 16 (per token, per head)
// ---------------------------------------------------------------------------
__global__ void softmax16_kernel(float* __restrict__ aw, int ngroups) {
    int i = blockIdx.x * blockDim.x + threadIdx.x;
    if (i >= ngroups) return;
    float* p = aw + (size_t)i * 16;
    float v[16];
    float mx = -1e30f;
    #pragma unroll
    for (int j = 0; j < 16; j++) { v[j] = p[j]; mx = fmaxf(mx, v[j]); }
    float s = 0.f;
    #pragma unroll
    for (int j = 0; j < 16; j++) { v[j] = __expf(v[j] - mx); s += v[j]; }
    float inv = 1.f / s;
    #pragma unroll
    for (int j = 0; j < 16; j++) p[j] = v[j] * inv;
}

// ---------------------------------------------------------------------------
// MSDA core: warp per (token, head), lane = channel. Writes bf16 triple.
// ---------------------------------------------------------------------------
__global__ void msda_kernel(const float* __restrict__ value,
                            const float* __restrict__ off,
                            const float* __restrict__ aw,
                            const float* __restrict__ refp,
                            __nv_bfloat16* __restrict__ out3) {
    const int gtid = blockIdx.x * blockDim.x + threadIdx.x;
    const int warp = gtid >> 5;
    const int lane = gtid & 31;
    if (warp >= NTOK * NH) return;

    const int h = warp & (NH - 1);
    const int t = warp >> 3;
    const int b = t / LEN;

    const float* off_row = off + (size_t)t * CCH + h * (NL * NP * 2);
    const float* aw_row  = aw  + (size_t)t * 128 + h * (NL * NP);
    const float* ref_row = refp + (size_t)t * (NL * 2);
    const float* vbase   = value + ((size_t)b * LEN) * CCH + h * DH + lane;

    const int dims[NL]   = {64, 32, 16, 8};
    const int starts[NL] = {0, 4096, 5120, 5376};

    float acc = 0.f;

    #pragma unroll
    for (int l = 0; l < NL; l++) {
        const int Wl = dims[l], Hl = dims[l];
        const float fW = (float)Wl, fH = (float)Hl;
        const float rx = ref_row[2 * l];
        const float ry = ref_row[2 * l + 1];
        const float* vl = vbase + (size_t)starts[l] * CCH;

        #pragma unroll
        for (int p = 0; p < NP; p++) {
            const float ox = off_row[(l * NP + p) * 2];
            const float oy = off_row[(l * NP + p) * 2 + 1];
            const float px = (rx + ox / fW) * fW - 0.5f;
            const float py = (ry + oy / fH) * fH - 0.5f;
            const float fx = floorf(px), fy = floorf(py);
            const int x0 = (int)fx, y0 = (int)fy;
            const int x1 = x0 + 1,  y1 = y0 + 1;
            const float wx1 = px - fx, wy1 = py - fy;
            const float wx0 = 1.f - wx1, wy0 = 1.f - wy1;
            const float a = aw_row[l * NP + p];
            const float w00 = a * wx0 * wy0, w10 = a * wx1 * wy0;
            const float w01 = a * wx0 * wy1, w11 = a * wx1 * wy1;

            const bool vx0 = (x0 >= 0) & (x0 < Wl);
            const bool vx1 = (x1 >= 0) & (x1 < Wl);
            const bool vy0 = (y0 >= 0) & (y0 < Hl);
            const bool vy1 = (y1 >= 0) & (y1 < Hl);
            const int cx0 = min(max(x0, 0), Wl - 1);
            const int cx1 = min(max(x1, 0), Wl - 1);
            const int cy0 = min(max(y0, 0), Hl - 1);
            const int cy1 = min(max(y1, 0), Hl - 1);

            if (vy0 & vx0) acc = fmaf(w00, vl[(size_t)(cy0 * Wl + cx0) * CCH], acc);
            if (vy0 & vx1) acc = fmaf(w10, vl[(size_t)(cy0 * Wl + cx1) * CCH], acc);
            if (vy1 & vx0) acc = fmaf(w01, vl[(size_t)(cy1 * Wl + cx0) * CCH], acc);
            if (vy1 & vx1) acc = fmaf(w11, vl[(size_t)(cy1 * Wl + cx1) * CCH], acc);
        }
    }
    const int c = h * DH + lane;
    store_triple1(out3 + (size_t)t * 3 * CCH + c, CCH, acc);
}

// ---------------------------------------------------------------------------
// LayerNorm over C=256 of (a+b): warp per row. Optional bf16-triple output.
// ---------------------------------------------------------------------------
__global__ void ln_kernel(const float* __restrict__ a, const float* __restrict__ b,
                          const float* __restrict__ g, const float* __restrict__ be,
                          float* __restrict__ out, __nv_bfloat16* __restrict__ out3,
                          int rows) {
    const int row = blockIdx.x * (blockDim.x >> 5) + (threadIdx.x >> 5);
    const int lane = threadIdx.x & 31;
    if (row >= rows) return;

    const float* pa = a + (size_t)row * CCH;
    const float* pb = b + (size_t)row * CCH;
    float v[8];
    float s = 0.f;
    #pragma unroll
    for (int j = 0; j < 8; j++) {
        int c = lane + 32 * j;
        v[j] = pa[c] + pb[c];
        s += v[j];
    }
    #pragma unroll
    for (int o = 16; o > 0; o >>= 1) s += __shfl_xor_sync(0xffffffffu, s, o);
    const float mean = s * (1.f / CCH);
    float s2 = 0.f;
    #pragma unroll
    for (int j = 0; j < 8; j++) { float d = v[j] - mean; s2 += d * d; }
    #pragma unroll
    for (int o = 16; o > 0; o >>= 1) s2 += __shfl_xor_sync(0xffffffffu, s2, o);
    const float inv = rsqrtf(s2 * (1.f / CCH) + LN_EPS);

    #pragma unroll
    for (int j = 0; j < 8; j++) {
        int c = lane + 32 * j;
        float y = (v[j] - mean) * inv * g[c] + be[c];
        if (out)  out[(size_t)row * CCH + c] = y;
        if (out3) store_triple1(out3 + (size_t)row * 3 * CCH + c, CCH, y);
    }
}

// ---------------------------------------------------------------------------
// launch
// ---------------------------------------------------------------------------
extern "C" void kernel_launch(void* const* d_in, const int* in_sizes, int n_in,
                              void* d_out, int out_size) {
    const float* src   = (const float*)d_in[0];
    const float* pos   = (const float*)d_in[1];
    const float* refp  = (const float*)d_in[2];
    const float* w_off  = (const float*)d_in[6];
    const float* b_off  = (const float*)d_in[7];
    const float* w_attn = (const float*)d_in[8];
    const float* b_attn = (const float*)d_in[9];
    const float* w_val  = (const float*)d_in[10];
    const float* b_val  = (const float*)d_in[11];
    const float* w_out  = (const float*)d_in[12];
    const float* b_out  = (const float*)d_in[13];
    const float* g1     = (const float*)d_in[14];
    const float* be1    = (const float*)d_in[15];
    const float* w1     = (const float*)d_in[16];
    const float* b1     = (const float*)d_in[17];
    const float* w2     = (const float*)d_in[18];
    const float* b2     = (const float*)d_in[19];
    const float* g2     = (const float*)d_in[20];
    const float* be2    = (const float*)d_in[21];
    float* out = (float*)d_out;

    __nv_bfloat16 *p_q3, *p_src3, *p_msda3, *p_x3, *p_h3;
    __nv_bfloat16 *p_woff3, *p_wattn3, *p_wval3, *p_wout3, *p_w13, *p_w23;
    float *p_off, *p_aw, *p_val, *p_attn, *p_x, *p_ffn;
    cudaGetSymbolAddress((void**)&p_q3,    g_q3);
    cudaGetSymbolAddress((void**)&p_src3,  g_src3);
    cudaGetSymbolAddress((void**)&p_msda3, g_msda3);
    cudaGetSymbolAddress((void**)&p_x3,    g_x3);
    cudaGetSymbolAddress((void**)&p_h3,    g_h3);
    cudaGetSymbolAddress((void**)&p_woff3, g_woff3);
    cudaGetSymbolAddress((void**)&p_wattn3,g_wattn3);
    cudaGetSymbolAddress((void**)&p_wval3, g_wval3);
    cudaGetSymbolAddress((void**)&p_wout3, g_wout3);
    cudaGetSymbolAddress((void**)&p_w13,   g_w13);
    cudaGetSymbolAddress((void**)&p_w23,   g_w23);
    cudaGetSymbolAddress((void**)&p_off,   g_off);
    cudaGetSymbolAddress((void**)&p_aw,    g_aw);
    cudaGetSymbolAddress((void**)&p_val,   g_val);
    cudaGetSymbolAddress((void**)&p_attn,  g_attn);
    cudaGetSymbolAddress((void**)&p_x,     g_x);
    cudaGetSymbolAddress((void**)&p_ffn,   g_ffn);

    const int M = NTOK;  // 21760 = 170 * 128
    const dim3 blk(256);

    // weight conversions (graph-captured; cheap)
    wt3_kernel<<<(CCH * CCH + 255) / 256, blk>>>(w_off,  p_woff3,  CCH, CCH);
    wt3_kernel<<<(CCH * 128 + 255) / 256, blk>>>(w_attn, p_wattn3, CCH, 128);
    wt3_kernel<<<(CCH * CCH + 255) / 256, blk>>>(w_val,  p_wval3,  CCH, CCH);
    wt3_kernel<<<(CCH * CCH + 255) / 256, blk>>>(w_out,  p_wout3,  CCH, CCH);
    wt3_kernel<<<(CCH * DFF + 255) / 256, blk>>>(w1,     p_w13,    CCH, DFF);
    wt3_kernel<<<(DFF * CCH + 255) / 256, blk>>>(w2,     p_w23,    DFF, CCH);

    // q3 = triple(src + pos), src3 = triple(src)
    {
        int n2 = NTOK * CCH / 2;
        act3_kernel<<<(n2 + 255) / 256, blk>>>(src, pos,     p_q3,   CCH, n2);
        act3_kernel<<<(n2 + 255) / 256, blk>>>(src, nullptr, p_src3, CCH, n2);
    }

    // off = q @ w_off + b_off
    bgemm_kernel<<<dim3(CCH / GBN, M / GBM), blk>>>(p_q3, p_woff3, b_off, p_off, nullptr, M, CCH, 3 * CCH, 0);
    // logits = q @ w_attn + b_attn
    bgemm_kernel<<<dim3(1, M / GBM), blk>>>(p_q3, p_wattn3, b_attn, p_aw, nullptr, M, 128, 3 * CCH, 0);
    // softmax over 16-groups
    softmax16_kernel<<<(NTOK * NH + 255) / 256, blk>>>(p_aw, NTOK * NH);
    // value = src @ w_val + b_val
    bgemm_kernel<<<dim3(CCH / GBN, M / GBM), blk>>>(p_src3, p_wval3, b_val, p_val, nullptr, M, CCH, 3 * CCH, 0);
    // MSDA gather -> msda3 (bf16 triple)
    msda_kernel<<<NTOK * NH * 32 / 256, blk>>>(p_val, p_off, p_aw, refp, p_msda3);
    // attn_out = msda @ w_out + b_out
    bgemm_kernel<<<dim3(CCH / GBN, M / GBM), blk>>>(p_msda3, p_wout3, b_out, p_attn, nullptr, M, CCH, 3 * CCH, 0);
    // x = LN(src + attn_out) -> fp32 + triple
    ln_kernel<<<(NTOK + 7) / 8, blk>>>(src, p_attn, g1, be1, p_x, p_x3, NTOK);
    // h = relu(x @ w1 + b1) -> bf16 triple
    bgemm_kernel<<<dim3(DFF / GBN, M / GBM), blk>>>(p_x3, p_w13, b1, nullptr, p_h3, M, DFF, 3 * CCH, 1);
    // ffn = h @ w2 + b2
    bgemm_kernel<<<dim3(CCH / GBN, M / GBM), blk>>>(p_h3, p_w23, b2, p_ffn, nullptr, M, CCH, 3 * DFF, 0);
    // out = LN(x + ffn)
    ln_kernel<<<(NTOK + 7) / 8, blk>>>(p_x, p_ffn, g2, be2, out, nullptr, NTOK);
}

// round 4
// speedup vs baseline: 1.8670x; 1.2337x over previous
#include <cuda_runtime.h>
#include <cuda_bf16.h>
#include <math.h>

// Problem constants
#define NB   4
#define LEN  5440
#define NTOK (NB * LEN)          // 21760
#define CCH  256
#define NH   8
#define DH   32
#define NL   4
#define NP   4
#define DFF  1024
#define LN_EPS 1e-5f

// ---------------------------------------------------------------------------
// Scratch (device globals — no allocation allowed)
// Activations as bf16 "triples": [M][3K] = [hi | lo | hi]
// Weights transposed triples:    [N][3K] = [hi | hi | lo]
// ---------------------------------------------------------------------------
__device__ __nv_bfloat16 g_q3   [NTOK * 3 * CCH];
__device__ __nv_bfloat16 g_src3 [NTOK * 3 * CCH];
__device__ __nv_bfloat16 g_msda3[NTOK * 3 * CCH];
__device__ __nv_bfloat16 g_x3   [NTOK * 3 * CCH];
__device__ __nv_bfloat16 g_h3   [NTOK * 3 * DFF];

__device__ float g_off [NTOK * CCH];
__device__ float g_aw  [NTOK * 128];    // attn logits (softmax fused into msda)
__device__ float g_val [NTOK * CCH];
__device__ float g_attn[NTOK * CCH];
__device__ float g_x   [NTOK * CCH];
__device__ float g_ffn [NTOK * CCH];

__device__ __nv_bfloat16 g_woff3 [CCH * 3 * CCH];
__device__ __nv_bfloat16 g_wattn3[128 * 3 * CCH];
__device__ __nv_bfloat16 g_wval3 [CCH * 3 * CCH];
__device__ __nv_bfloat16 g_wout3 [CCH * 3 * CCH];
__device__ __nv_bfloat16 g_w13   [DFF * 3 * CCH];
__device__ __nv_bfloat16 g_w23   [CCH * 3 * DFF];

// ---------------------------------------------------------------------------
// helpers
// ---------------------------------------------------------------------------
__device__ __forceinline__ void store_triple(__nv_bfloat16* p, int N, float a, float b) {
    __nv_bfloat16 ah = __float2bfloat16(a), bh = __float2bfloat16(b);
    float ar = a - __bfloat162float(ah);
    float br = b - __bfloat162float(bh);
    __nv_bfloat162 hi = __halves2bfloat162(ah, bh);
    __nv_bfloat162 lo = __halves2bfloat162(__float2bfloat16(ar), __float2bfloat16(br));
    *(__nv_bfloat162*)(p)         = hi;
    *(__nv_bfloat162*)(p + N)     = lo;
    *(__nv_bfloat162*)(p + 2 * N) = hi;
}

__device__ __forceinline__ void store_triple1(__nv_bfloat16* p, int N, float a) {
    __nv_bfloat16 ah = __float2bfloat16(a);
    float ar = a - __bfloat162float(ah);
    p[0]     = ah;
    p[N]     = __float2bfloat16(ar);
    p[2 * N] = ah;
}

__device__ __forceinline__ unsigned smem_u32(const void* p) {
    unsigned a;
    asm("{ .reg .u64 t; cvta.to.shared.u64 t, %1; cvt.u32.u64 %0, t; }" : "=r"(a) : "l"(p));
    return a;
}

__device__ __forceinline__ void cp_async16(unsigned dst, const void* src) {
    asm volatile("cp.async.cg.shared.global [%0], [%1], 16;\n" :: "r"(dst), "l"(src));
}
__device__ __forceinline__ void cp_commit() {
    asm volatile("cp.async.commit_group;\n" ::: "memory");
}
template<int N>
__device__ __forceinline__ void cp_wait() {
    asm volatile("cp.async.wait_group %0;\n" :: "n"(N) : "memory");
}

__device__ __forceinline__ void ldm4(unsigned& r0, unsigned& r1, unsigned& r2, unsigned& r3,
                                     unsigned a) {
    asm volatile("ldmatrix.sync.aligned.m8n8.x4.shared.b16 {%0,%1,%2,%3}, [%4];"
                 : "=r"(r0), "=r"(r1), "=r"(r2), "=r"(r3) : "r"(a));
}

__device__ __forceinline__ void mma_bf16(float c[4],
                                         unsigned a0, unsigned a1, unsigned a2, unsigned a3,
                                         unsigned b0, unsigned b1) {
    asm volatile(
        "mma.sync.aligned.m16n8k16.row.col.f32.bf16.bf16.f32 "
        "{%0,%1,%2,%3},{%4,%5,%6,%7},{%8,%9},{%0,%1,%2,%3};"
        : "+f"(c[0]), "+f"(c[1]), "+f"(c[2]), "+f"(c[3])
        : "r"(a0), "r"(a1), "r"(a2), "r"(a3), "r"(b0), "r"(b1));
}

// ---------------------------------------------------------------------------
// HMMA GEMM: C[M,N] = A3[M,K3] @ B3t[N,K3]^T + bias
// BM=BN=128, BK=64 bf16 (128B rows, XOR-swizzled), 3-stage cp.async,
// 256 threads (8 warps, 2m x 4n), warp tile 64x32, ldmatrix fragments.
// OUT_MODE 0: fp32 out. 1: relu + bf16-triple out (row stride 3N).
// ---------------------------------------------------------------------------
#define NST 3
#define STAGE_A (128 * 128)          // bytes (128 rows x 128B)
#define STAGE_SZ (2 * STAGE_A)       // 32 KB

__device__ __forceinline__ void gemm_load_stage(unsigned sb, int stage,
                                                const __nv_bfloat16* Ab,
                                                const __nv_bfloat16* Bb,
                                                int K3, int kt, int tid) {
    const unsigned abase = sb + stage * STAGE_SZ;
    const unsigned bbase = abase + STAGE_A;
    const __nv_bfloat16* ag = Ab + kt * 64;
    const __nv_bfloat16* bg = Bb + kt * 64;
    #pragma unroll
    for (int i = 0; i < 4; i++) {
        int id = tid + i * 256;
        int r = id >> 3, c = id & 7;
        unsigned off = (unsigned)(r * 128 + ((c ^ (r & 7)) << 4));
        cp_async16(abase + off, ag + (size_t)r * K3 + c * 8);
    }
    #pragma unroll
    for (int i = 0; i < 4; i++) {
        int id = tid + i * 256;
        int r = id >> 3, c = id & 7;
        unsigned off = (unsigned)(r * 128 + ((c ^ (r & 7)) << 4));
        cp_async16(bbase + off, bg + (size_t)r * K3 + c * 8);
    }
    cp_commit();
}

template<int OUT_MODE>
__global__ __launch_bounds__(256, 2)
void mma_gemm(const __nv_bfloat16* __restrict__ A, const __nv_bfloat16* __restrict__ Bt,
              const float* __restrict__ bias, float* __restrict__ Cf,
              __nv_bfloat16* __restrict__ C3, int N, int K3) {
    extern __shared__ __align__(1024) char smem[];
    const unsigned sb = smem_u32(smem);

    const int tid = threadIdx.x;
    const int warp = tid >> 5, lane = tid & 31;
    const int wm = warp & 1, wn = warp >> 1;
    const int bx = blockIdx.x, by = blockIdx.y;

    const __nv_bfloat16* Ab = A  + (size_t)by * 128 * K3;
    const __nv_bfloat16* Bb = Bt + (size_t)bx * 128 * (size_t)K3;
    const int KT = K3 >> 6;

    float acc[4][4][4];
    #pragma unroll
    for (int i = 0; i < 4; i++)
        #pragma unroll
        for (int j = 0; j < 4; j++)
            #pragma unroll
            for (int r = 0; r < 4; r++) acc[i][j][r] = 0.f;

    gemm_load_stage(sb, 0, Ab, Bb, K3, 0, tid);
    gemm_load_stage(sb, 1, Ab, Bb, K3, 1, tid);

    // per-lane ldmatrix address components (constant across kt)
    const int a_row  = (lane & 15);          // + wm*64 + mi*16
    const int a_csel = (lane >> 4);          // 0/1 -> k chunk within k16
    const int b_rsel = ((lane >> 4) << 3) + (lane & 7);  // + wn*32 + nj2*16
    const int b_csel = ((lane >> 3) & 1);

    for (int kt = 0; kt < KT; kt++) {
        const int stage = kt % NST;
        cp_wait<NST - 2>();
        __syncthreads();
        if (kt + NST - 1 < KT)
            gemm_load_stage(sb, (kt + NST - 1) % NST, Ab, Bb, K3, kt + NST - 1, tid);
        else
            cp_commit();

        const unsigned abase = sb + stage * STAGE_SZ;
        const unsigned bbase = abase + STAGE_A;

        #pragma unroll
        for (int kk = 0; kk < 4; kk++) {
            unsigned af[4][4];
            #pragma unroll
            for (int mi = 0; mi < 4; mi++) {
                int row = wm * 64 + mi * 16 + a_row;
                int c = kk * 2 + a_csel;
                unsigned addr = abase + (unsigned)(row * 128 + ((c ^ (row & 7)) << 4));
                ldm4(af[mi][0], af[mi][1], af[mi][2], af[mi][3], addr);
            }
            unsigned bfr[2][4];
            #pragma unroll
            for (int nj2 = 0; nj2 < 2; nj2++) {
                int nrow = wn * 32 + nj2 * 16 + b_rsel;
                int c = kk * 2 + b_csel;
                unsigned addr = bbase + (unsigned)(nrow * 128 + ((c ^ (nrow & 7)) << 4));
                ldm4(bfr[nj2][0], bfr[nj2][1], bfr[nj2][2], bfr[nj2][3], addr);
            }
            #pragma unroll
            for (int mi = 0; mi < 4; mi++)
                #pragma unroll
                for (int nj = 0; nj < 4; nj++) {
                    const unsigned* b = bfr[nj >> 1];
                    unsigned b0 = (nj & 1) ? b[2] : b[0];
                    unsigned b1 = (nj & 1) ? b[3] : b[1];
                    mma_bf16(acc[mi][nj], af[mi][0], af[mi][1], af[mi][2], af[mi][3], b0, b1);
                }
        }
    }

    // epilogue
    const int col0 = bx * 128 + wn * 32 + (lane & 3) * 2;
    #pragma unroll
    for (int mi = 0; mi < 4; mi++) {
        int row = by * 128 + wm * 64 + mi * 16 + (lane >> 2);
        #pragma unroll
        for (int nj = 0; nj < 4; nj++) {
            int col = col0 + nj * 8;
            float b0v = bias[col], b1v = bias[col + 1];
            float v00 = acc[mi][nj][0] + b0v, v01 = acc[mi][nj][1] + b1v;
            float v10 = acc[mi][nj][2] + b0v, v11 = acc[mi][nj][3] + b1v;
            if (OUT_MODE == 0) {
                *(float2*)(Cf + (size_t)row * N + col)       = make_float2(v00, v01);
                *(float2*)(Cf + (size_t)(row + 8) * N + col) = make_float2(v10, v11);
            } else {
                v00 = fmaxf(v00, 0.f); v01 = fmaxf(v01, 0.f);
                v10 = fmaxf(v10, 0.f); v11 = fmaxf(v11, 0.f);
                store_triple(C3 + (size_t)row * 3 * N + col, N, v00, v01);
                store_triple(C3 + (size_t)(row + 8) * 3 * N + col, N, v10, v11);
            }
        }
    }
}

// ---------------------------------------------------------------------------
// activation triple conversion: O[row][3K] from A (optionally + B)
// ---------------------------------------------------------------------------
__global__ void act3_kernel(const float* __restrict__ A, const float* __restrict__ B,
                            __nv_bfloat16* __restrict__ O, int K, int n2) {
    int i = blockIdx.x * blockDim.x + threadIdx.x;
    if (i >= n2) return;
    float2 v = ((const float2*)A)[i];
    if (B) { float2 w = ((const float2*)B)[i]; v.x += w.x; v.y += w.y; }
    int row = i / (K / 2);
    int c2  = i % (K / 2);
    store_triple(O + (size_t)row * 3 * K + c2 * 2, K, v.x, v.y);
}

// weight triple conversion: W[K][N] fp32 -> Bt[N][3K] bf16 [hi|hi|lo]
__global__ void wt3_kernel(const float* __restrict__ W, __nv_bfloat16* __restrict__ Bt,
                           int K, int N) {
    int i = blockIdx.x * blockDim.x + threadIdx.x;
    if (i >= K * N) return;
    int k = i / N, n = i % N;
    float v = W[i];
    __nv_bfloat16 h = __float2bfloat16(v);
    __nv_bfloat16 l = __float2bfloat16(v - __bfloat162float(h));
    __nv_bfloat16* p = Bt + (size_t)n * 3 * K + k;
    p[0]     = h;
    p[K]     = h;
    p[2 * K] = l;
}

// ---------------------------------------------------------------------------
// MSDA core with fused softmax: warp per (token, head), lane = channel.
// ---------------------------------------------------------------------------
__global__ void msda_kernel(const float* __restrict__ value,
                            const float* __restrict__ off,
                            const float* __restrict__ logits,
                            const float* __restrict__ refp,
                            __nv_bfloat16* __restrict__ out3) {
    const int gtid = blockIdx.x * blockDim.x + threadIdx.x;
    const int warp = gtid >> 5;
    const int lane = gtid & 31;
    if (warp >= NTOK * NH) return;

    const int h = warp & (NH - 1);
    const int t = warp >> 3;
    const int b = t / LEN;

    // fused softmax over 16 logits (lanes 0-15 own one each; 16-31 mirror)
    const float* lg = logits + (size_t)t * 128 + h * 16;
    float l0 = lg[lane & 15];
    float mx = l0;
    #pragma unroll
    for (int o = 1; o < 16; o <<= 1) mx = fmaxf(mx, __shfl_xor_sync(0xffffffffu, mx, o));
    float e = __expf(l0 - mx);
    float s = e;
    #pragma unroll
    for (int o = 1; o < 16; o <<= 1) s += __shfl_xor_sync(0xffffffffu, s, o);
    const float wgt = e / s;

    const float* off_row = off + (size_t)t * CCH + h * (NL * NP * 2);
    const float* ref_row = refp + (size_t)t * (NL * 2);
    const float* vbase   = value + ((size_t)b * LEN) * CCH + h * DH + lane;

    const int dims[NL]   = {64, 32, 16, 8};
    const int starts[NL] = {0, 4096, 5120, 5376};

    float acc = 0.f;

    #pragma unroll
    for (int l = 0; l < NL; l++) {
        const int Wl = dims[l], Hl = dims[l];
        const float fW = (float)Wl, fH = (float)Hl;
        const float rx = ref_row[2 * l];
        const float ry = ref_row[2 * l + 1];
        const float* vl = vbase + (size_t)starts[l] * CCH;

        #pragma unroll
        for (int p = 0; p < NP; p++) {
            const float ox = off_row[(l * NP + p) * 2];
            const float oy = off_row[(l * NP + p) * 2 + 1];
            const float px = (rx + ox / fW) * fW - 0.5f;
            const float py = (ry + oy / fH) * fH - 0.5f;
            const float fx = floorf(px), fy = floorf(py);
            const int x0 = (int)fx, y0 = (int)fy;
            const int x1 = x0 + 1,  y1 = y0 + 1;
            const float wx1 = px - fx, wy1 = py - fy;
            const float wx0 = 1.f - wx1, wy0 = 1.f - wy1;
            const float a = __shfl_sync(0xffffffffu, wgt, l * NP + p);
            const float w00 = a * wx0 * wy0, w10 = a * wx1 * wy0;
            const float w01 = a * wx0 * wy1, w11 = a * wx1 * wy1;

            const bool vx0 = (x0 >= 0) & (x0 < Wl);
            const bool vx1 = (x1 >= 0) & (x1 < Wl);
            const bool vy0 = (y0 >= 0) & (y0 < Hl);
            const bool vy1 = (y1 >= 0) & (y1 < Hl);
            const int cx0 = min(max(x0, 0), Wl - 1);
            const int cx1 = min(max(x1, 0), Wl - 1);
            const int cy0 = min(max(y0, 0), Hl - 1);
            const int cy1 = min(max(y1, 0), Hl - 1);

            if (vy0 & vx0) acc = fmaf(w00, vl[(size_t)(cy0 * Wl + cx0) * CCH], acc);
            if (vy0 & vx1) acc = fmaf(w10, vl[(size_t)(cy0 * Wl + cx1) * CCH], acc);
            if (vy1 & vx0) acc = fmaf(w01, vl[(size_t)(cy1 * Wl + cx0) * CCH], acc);
            if (vy1 & vx1) acc = fmaf(w11, vl[(size_t)(cy1 * Wl + cx1) * CCH], acc);
        }
    }
    const int c = h * DH + lane;
    store_triple1(out3 + (size_t)t * 3 * CCH + c, CCH, acc);
}

// ---------------------------------------------------------------------------
// LayerNorm over C=256 of (a+b): warp per row. Optional bf16-triple output.
// ---------------------------------------------------------------------------
__global__ void ln_kernel(const float* __restrict__ a, const float* __restrict__ b,
                          const float* __restrict__ g, const float* __restrict__ be,
                          float* __restrict__ out, __nv_bfloat16* __restrict__ out3,
                          int rows) {
    const int row = blockIdx.x * (blockDim.x >> 5) + (threadIdx.x >> 5);
    const int lane = threadIdx.x & 31;
    if (row >= rows) return;

    const float* pa = a + (size_t)row * CCH;
    const float* pb = b + (size_t)row * CCH;
    float v[8];
    float s = 0.f;
    #pragma unroll
    for (int j = 0; j < 8; j++) {
        int c = lane + 32 * j;
        v[j] = pa[c] + pb[c];
        s += v[j];
    }
    #pragma unroll
    for (int o = 16; o > 0; o >>= 1) s += __shfl_xor_sync(0xffffffffu, s, o);
    const float mean = s * (1.f / CCH);
    float s2 = 0.f;
    #pragma unroll
    for (int j = 0; j < 8; j++) { float d = v[j] - mean; s2 += d * d; }
    #pragma unroll
    for (int o = 16; o > 0; o >>= 1) s2 += __shfl_xor_sync(0xffffffffu, s2, o);
    const float inv = rsqrtf(s2 * (1.f / CCH) + LN_EPS);

    #pragma unroll
    for (int j = 0; j < 8; j++) {
        int c = lane + 32 * j;
        float y = (v[j] - mean) * inv * g[c] + be[c];
        if (out)  out[(size_t)row * CCH + c] = y;
        if (out3) store_triple1(out3 + (size_t)row * 3 * CCH + c, CCH, y);
    }
}

// ---------------------------------------------------------------------------
// launch
// ---------------------------------------------------------------------------
extern "C" void kernel_launch(void* const* d_in, const int* in_sizes, int n_in,
                              void* d_out, int out_size) {
    const float* src   = (const float*)d_in[0];
    const float* pos   = (const float*)d_in[1];
    const float* refp  = (const float*)d_in[2];
    const float* w_off  = (const float*)d_in[6];
    const float* b_off  = (const float*)d_in[7];
    const float* w_attn = (const float*)d_in[8];
    const float* b_attn = (const float*)d_in[9];
    const float* w_val  = (const float*)d_in[10];
    const float* b_val  = (const float*)d_in[11];
    const float* w_out  = (const float*)d_in[12];
    const float* b_out  = (const float*)d_in[13];
    const float* g1     = (const float*)d_in[14];
    const float* be1    = (const float*)d_in[15];
    const float* w1     = (const float*)d_in[16];
    const float* b1     = (const float*)d_in[17];
    const float* w2     = (const float*)d_in[18];
    const float* b2     = (const float*)d_in[19];
    const float* g2     = (const float*)d_in[20];
    const float* be2    = (const float*)d_in[21];
    float* out = (float*)d_out;

    __nv_bfloat16 *p_q3, *p_src3, *p_msda3, *p_x3, *p_h3;
    __nv_bfloat16 *p_woff3, *p_wattn3, *p_wval3, *p_wout3, *p_w13, *p_w23;
    float *p_off, *p_aw, *p_val, *p_attn, *p_x, *p_ffn;
    cudaGetSymbolAddress((void**)&p_q3,    g_q3);
    cudaGetSymbolAddress((void**)&p_src3,  g_src3);
    cudaGetSymbolAddress((void**)&p_msda3, g_msda3);
    cudaGetSymbolAddress((void**)&p_x3,    g_x3);
    cudaGetSymbolAddress((void**)&p_h3,    g_h3);
    cudaGetSymbolAddress((void**)&p_woff3, g_woff3);
    cudaGetSymbolAddress((void**)&p_wattn3,g_wattn3);
    cudaGetSymbolAddress((void**)&p_wval3, g_wval3);
    cudaGetSymbolAddress((void**)&p_wout3, g_wout3);
    cudaGetSymbolAddress((void**)&p_w13,   g_w13);
    cudaGetSymbolAddress((void**)&p_w23,   g_w23);
    cudaGetSymbolAddress((void**)&p_off,   g_off);
    cudaGetSymbolAddress((void**)&p_aw,    g_aw);
    cudaGetSymbolAddress((void**)&p_val,   g_val);
    cudaGetSymbolAddress((void**)&p_attn,  g_attn);
    cudaGetSymbolAddress((void**)&p_x,     g_x);
    cudaGetSymbolAddress((void**)&p_ffn,   g_ffn);

    const int M = NTOK;  // 21760 = 170 * 128
    const dim3 blk(256);

    const int GSMEM = NST * STAGE_SZ;  // 98304
    cudaFuncSetAttribute(mma_gemm<0>, cudaFuncAttributeMaxDynamicSharedMemorySize, GSMEM);
    cudaFuncSetAttribute(mma_gemm<1>, cudaFuncAttributeMaxDynamicSharedMemorySize, GSMEM);

    // weight conversions
    wt3_kernel<<<(CCH * CCH + 255) / 256, blk>>>(w_off,  p_woff3,  CCH, CCH);
    wt3_kernel<<<(CCH * 128 + 255) / 256, blk>>>(w_attn, p_wattn3, CCH, 128);
    wt3_kernel<<<(CCH * CCH + 255) / 256, blk>>>(w_val,  p_wval3,  CCH, CCH);
    wt3_kernel<<<(CCH * CCH + 255) / 256, blk>>>(w_out,  p_wout3,  CCH, CCH);
    wt3_kernel<<<(CCH * DFF + 255) / 256, blk>>>(w1,     p_w13,    CCH, DFF);
    wt3_kernel<<<(DFF * CCH + 255) / 256, blk>>>(w2,     p_w23,    DFF, CCH);

    // q3 = triple(src + pos), src3 = triple(src)
    {
        int n2 = NTOK * CCH / 2;
        act3_kernel<<<(n2 + 255) / 256, blk>>>(src, pos,     p_q3,   CCH, n2);
        act3_kernel<<<(n2 + 255) / 256, blk>>>(src, nullptr, p_src3, CCH, n2);
    }

    // off = q @ w_off + b_off
    mma_gemm<0><<<dim3(2, M / 128), blk, GSMEM>>>(p_q3, p_woff3, b_off, p_off, nullptr, CCH, 3 * CCH);
    // logits = q @ w_attn + b_attn
    mma_gemm<0><<<dim3(1, M / 128), blk, GSMEM>>>(p_q3, p_wattn3, b_attn, p_aw, nullptr, 128, 3 * CCH);
    // value = src @ w_val + b_val
    mma_gemm<0><<<dim3(2, M / 128), blk, GSMEM>>>(p_src3, p_wval3, b_val, p_val, nullptr, CCH, 3 * CCH);
    // MSDA gather (softmax fused) -> msda3 (bf16 triple)
    msda_kernel<<<NTOK * NH * 32 / 256, blk>>>(p_val, p_off, p_aw, refp, p_msda3);
    // attn_out = msda @ w_out + b_out
    mma_gemm<0><<<dim3(2, M / 128), blk, GSMEM>>>(p_msda3, p_wout3, b_out, p_attn, nullptr, CCH, 3 * CCH);
    // x = LN(src + attn_out) -> fp32 + triple
    ln_kernel<<<(NTOK + 7) / 8, blk>>>(src, p_attn, g1, be1, p_x, p_x3, NTOK);
    // h = relu(x @ w1 + b1) -> bf16 triple
    mma_gemm<1><<<dim3(8, M / 128), blk, GSMEM>>>(p_x3, p_w13, b1, nullptr, p_h3, DFF, 3 * CCH);
    // ffn = h @ w2 + b2
    mma_gemm<0><<<dim3(2, M / 128), blk, GSMEM>>>(p_h3, p_w23, b2, p_ffn, nullptr, CCH, 3 * DFF);
    // out = LN(x + ffn)
    ln_kernel<<<(NTOK + 7) / 8, blk>>>(p_x, p_ffn, g2, be2, out, nullptr, NTOK);
}

// round 5
// speedup vs baseline: 2.0572x; 1.1019x over previous
#include <cuda_runtime.h>
#include <cuda_bf16.h>
#include <math.h>

// Problem constants
#define NB   4
#define LEN  5440
#define NTOK (NB * LEN)          // 21760
#define CCH  256
#define NH   8
#define DH   32
#define NL   4
#define NP   4
#define DFF  1024
#define LN_EPS 1e-5f

// ---------------------------------------------------------------------------
// Scratch (device globals)
// Activations bf16 "triples": [M][3K] = [hi | lo | hi]
// Weights transposed triples: [N][3K] = [hi | hi | lo]
// ---------------------------------------------------------------------------
__device__ __nv_bfloat16 g_q3   [NTOK * 3 * CCH];
__device__ __nv_bfloat16 g_src3 [NTOK * 3 * CCH];
__device__ __nv_bfloat16 g_msda3[NTOK * 3 * CCH];
__device__ __nv_bfloat16 g_x3   [NTOK * 3 * CCH];
__device__ __nv_bfloat16 g_h3   [NTOK * 3 * DFF];

__device__ float g_off [NTOK * CCH];
__device__ float g_aw  [NTOK * 128];
__device__ float g_val [NTOK * CCH];
__device__ float g_attn[NTOK * CCH];
__device__ float g_x   [NTOK * CCH];
__device__ float g_ffn [NTOK * CCH];

__device__ __nv_bfloat16 g_woff3 [CCH * 3 * CCH];
__device__ __nv_bfloat16 g_wattn3[128 * 3 * CCH];
__device__ __nv_bfloat16 g_wval3 [CCH * 3 * CCH];
__device__ __nv_bfloat16 g_wout3 [CCH * 3 * CCH];
__device__ __nv_bfloat16 g_w13   [DFF * 3 * CCH];
__device__ __nv_bfloat16 g_w23   [CCH * 3 * DFF];

// ---------------------------------------------------------------------------
// helpers
// ---------------------------------------------------------------------------
__device__ __forceinline__ void store_triple(__nv_bfloat16* p, int N, float a, float b) {
    __nv_bfloat16 ah = __float2bfloat16(a), bh = __float2bfloat16(b);
    float ar = a - __bfloat162float(ah);
    float br = b - __bfloat162float(bh);
    __nv_bfloat162 hi = __halves2bfloat162(ah, bh);
    __nv_bfloat162 lo = __halves2bfloat162(__float2bfloat16(ar), __float2bfloat16(br));
    *(__nv_bfloat162*)(p)         = hi;
    *(__nv_bfloat162*)(p + N)     = lo;
    *(__nv_bfloat162*)(p + 2 * N) = hi;
}

__device__ __forceinline__ void store_triple1(__nv_bfloat16* p, int N, float a) {
    __nv_bfloat16 ah = __float2bfloat16(a);
    float ar = a - __bfloat162float(ah);
    p[0]     = ah;
    p[N]     = __float2bfloat16(ar);
    p[2 * N] = ah;
}

__device__ __forceinline__ unsigned smem_u32(const void* p) {
    unsigned a;
    asm("{ .reg .u64 t; cvta.to.shared.u64 t, %1; cvt.u32.u64 %0, t; }" : "=r"(a) : "l"(p));
    return a;
}

__device__ __forceinline__ void cp_async16(unsigned dst, const void* src) {
    asm volatile("cp.async.cg.shared.global [%0], [%1], 16;\n" :: "r"(dst), "l"(src));
}
__device__ __forceinline__ void cp_commit() {
    asm volatile("cp.async.commit_group;\n" ::: "memory");
}
template<int N>
__device__ __forceinline__ void cp_wait() {
    asm volatile("cp.async.wait_group %0;\n" :: "n"(N) : "memory");
}

__device__ __forceinline__ void ldm4(unsigned& r0, unsigned& r1, unsigned& r2, unsigned& r3,
                                     unsigned a) {
    asm volatile("ldmatrix.sync.aligned.m8n8.x4.shared.b16 {%0,%1,%2,%3}, [%4];"
                 : "=r"(r0), "=r"(r1), "=r"(r2), "=r"(r3) : "r"(a));
}

__device__ __forceinline__ void mma_bf16(float c[4],
                                         unsigned a0, unsigned a1, unsigned a2, unsigned a3,
                                         unsigned b0, unsigned b1) {
    asm volatile(
        "mma.sync.aligned.m16n8k16.row.col.f32.bf16.bf16.f32 "
        "{%0,%1,%2,%3},{%4,%5,%6,%7},{%8,%9},{%0,%1,%2,%3};"
        : "+f"(c[0]), "+f"(c[1]), "+f"(c[2]), "+f"(c[3])
        : "r"(a0), "r"(a1), "r"(a2), "r"(a3), "r"(b0), "r"(b1));
}

// ---------------------------------------------------------------------------
// GEMM body. BM = MI*32 (MI m-subtiles of 16 per warp, 2 warp rows),
// BN = 128 fixed. 256 threads (8 warps, 2m x 4n). BK = 64 bf16.
// OUT_MODE 0: fp32 out. 1: relu + bf16-triple out (row stride 3N).
// Cf/C3/bias pre-offset so local col index is used directly; N = row stride.
// ---------------------------------------------------------------------------
#define NST 3

template<int MI>
__device__ __forceinline__ void gemm_load_stage(unsigned sb, int stage,
                                                const __nv_bfloat16* Ab,
                                                const __nv_bfloat16* Bb,
                                                int K3, int kt, int tid) {
    constexpr int BM = MI * 32;
    constexpr int A_BYTES = BM * 128;
    constexpr int STAGE_SZ = (BM + 128) * 128;
    const unsigned abase = sb + stage * STAGE_SZ;
    const unsigned bbase = abase + A_BYTES;
    const __nv_bfloat16* ag = Ab + kt * 64;
    const __nv_bfloat16* bg = Bb + kt * 64;
    #pragma unroll
    for (int i = 0; i < MI; i++) {
        int id = tid + i * 256;
        int r = id >> 3, c = id & 7;
        unsigned off = (unsigned)(r * 128 + ((c ^ (r & 7)) << 4));
        cp_async16(abase + off, ag + (size_t)r * K3 + c * 8);
    }
    #pragma unroll
    for (int i = 0; i < 4; i++) {
        int id = tid + i * 256;
        int r = id >> 3, c = id & 7;
        unsigned off = (unsigned)(r * 128 + ((c ^ (r & 7)) << 4));
        cp_async16(bbase + off, bg + (size_t)r * K3 + c * 8);
    }
    cp_commit();
}

template<int MI, int OUT_MODE>
__device__ __forceinline__ void gemm_body(const __nv_bfloat16* Ab, const __nv_bfloat16* Bb,
                                          const float* bias, float* Cf, __nv_bfloat16* C3,
                                          int N, int K3, int row_base, char* smem) {
    constexpr int BM = MI * 32;
    constexpr int A_BYTES = BM * 128;
    constexpr int STAGE_SZ = (BM + 128) * 128;
    const unsigned sb = smem_u32(smem);

    const int tid = threadIdx.x;
    const int warp = tid >> 5, lane = tid & 31;
    const int wm = warp & 1, wn = warp >> 1;
    const int KT = K3 >> 6;

    float acc[MI][4][4];
    #pragma unroll
    for (int i = 0; i < MI; i++)
        #pragma unroll
        for (int j = 0; j < 4; j++)
            #pragma unroll
            for (int r = 0; r < 4; r++) acc[i][j][r] = 0.f;

    gemm_load_stage<MI>(sb, 0, Ab, Bb, K3, 0, tid);
    gemm_load_stage<MI>(sb, 1, Ab, Bb, K3, 1, tid);

    const int a_row  = (lane & 15);
    const int a_csel = (lane >> 4);
    const int b_rsel = ((lane >> 4) << 3) + (lane & 7);
    const int b_csel = ((lane >> 3) & 1);

    for (int kt = 0; kt < KT; kt++) {
        const int stage = kt % NST;
        cp_wait<NST - 2>();
        __syncthreads();
        if (kt + NST - 1 < KT)
            gemm_load_stage<MI>(sb, (kt + NST - 1) % NST, Ab, Bb, K3, kt + NST - 1, tid);
        else
            cp_commit();

        const unsigned abase = sb + stage * STAGE_SZ;
        const unsigned bbase = abase + A_BYTES;

        #pragma unroll
        for (int kk = 0; kk < 4; kk++) {
            unsigned af[MI][4];
            #pragma unroll
            for (int mi = 0; mi < MI; mi++) {
                int row = wm * (MI * 16) + mi * 16 + a_row;
                int c = kk * 2 + a_csel;
                unsigned addr = abase + (unsigned)(row * 128 + ((c ^ (row & 7)) << 4));
                ldm4(af[mi][0], af[mi][1], af[mi][2], af[mi][3], addr);
            }
            unsigned bfr[2][4];
            #pragma unroll
            for (int nj2 = 0; nj2 < 2; nj2++) {
                int nrow = wn * 32 + nj2 * 16 + b_rsel;
                int c = kk * 2 + b_csel;
                unsigned addr = bbase + (unsigned)(nrow * 128 + ((c ^ (nrow & 7)) << 4));
                ldm4(bfr[nj2][0], bfr[nj2][1], bfr[nj2][2], bfr[nj2][3], addr);
            }
            #pragma unroll
            for (int mi = 0; mi < MI; mi++)
                #pragma unroll
                for (int nj = 0; nj < 4; nj++) {
                    const unsigned* b = bfr[nj >> 1];
                    unsigned b0 = (nj & 1) ? b[2] : b[0];
                    unsigned b1 = (nj & 1) ? b[3] : b[1];
                    mma_bf16(acc[mi][nj], af[mi][0], af[mi][1], af[mi][2], af[mi][3], b0, b1);
                }
        }
    }

    // epilogue
    const int col0 = wn * 32 + (lane & 3) * 2;
    #pragma unroll
    for (int mi = 0; mi < MI; mi++) {
        int row = row_base + wm * (MI * 16) + mi * 16 + (lane >> 2);
        #pragma unroll
        for (int nj = 0; nj < 4; nj++) {
            int col = col0 + nj * 8;
            float b0v = bias[col], b1v = bias[col + 1];
            float v00 = acc[mi][nj][0] + b0v, v01 = acc[mi][nj][1] + b1v;
            float v10 = acc[mi][nj][2] + b0v, v11 = acc[mi][nj][3] + b1v;
            if (OUT_MODE == 0) {
                *(float2*)(Cf + (size_t)row * N + col)       = make_float2(v00, v01);
                *(float2*)(Cf + (size_t)(row + 8) * N + col) = make_float2(v10, v11);
            } else {
                v00 = fmaxf(v00, 0.f); v01 = fmaxf(v01, 0.f);
                v10 = fmaxf(v10, 0.f); v11 = fmaxf(v11, 0.f);
                store_triple(C3 + (size_t)row * 3 * N + col, N, v00, v01);
                store_triple(C3 + (size_t)(row + 8) * 3 * N + col, N, v10, v11);
            }
        }
    }
}

// generic GEMM kernel
template<int MI, int OUT_MODE>
__global__ __launch_bounds__(256, 2)
void mma_gemm(const __nv_bfloat16* __restrict__ A, const __nv_bfloat16* __restrict__ Bt,
              const float* __restrict__ bias, float* __restrict__ Cf,
              __nv_bfloat16* __restrict__ C3, int N, int K3) {
    extern __shared__ __align__(1024) char smem[];
    const int bx = blockIdx.x, by = blockIdx.y;
    constexpr int BM = MI * 32;
    gemm_body<MI, OUT_MODE>(A + (size_t)by * BM * K3,
                            Bt + (size_t)bx * 128 * (size_t)K3,
                            bias + bx * 128,
                            Cf ? Cf + bx * 128 : nullptr,
                            C3 ? C3 + bx * 128 : nullptr,
                            N, K3, by * BM, smem);
}

// fused projection GEMM: bx selects {off0, off1, logits, val0, val1}
__global__ __launch_bounds__(256, 2)
void proj_gemm(const __nv_bfloat16* __restrict__ q3, const __nv_bfloat16* __restrict__ src3,
               const __nv_bfloat16* __restrict__ woff3, const __nv_bfloat16* __restrict__ wattn3,
               const __nv_bfloat16* __restrict__ wval3,
               const float* __restrict__ b_off, const float* __restrict__ b_attn,
               const float* __restrict__ b_val,
               float* __restrict__ c_off, float* __restrict__ c_aw, float* __restrict__ c_val) {
    extern __shared__ __align__(1024) char smem[];
    const int bx = blockIdx.x, by = blockIdx.y;
    const int K3 = 3 * CCH;

    const __nv_bfloat16* A;
    const __nv_bfloat16* B;
    const float* bias;
    float* C;
    int N;
    if (bx < 2) {
        A = q3; B = woff3 + (size_t)bx * 128 * K3; bias = b_off + bx * 128;
        C = c_off + bx * 128; N = CCH;
    } else if (bx == 2) {
        A = q3; B = wattn3; bias = b_attn; C = c_aw; N = 128;
    } else {
        int s = bx - 3;
        A = src3; B = wval3 + (size_t)s * 128 * K3; bias = b_val + s * 128;
        C = c_val + s * 128; N = CCH;
    }
    gemm_body<4, 0>(A + (size_t)by * 128 * K3, B, bias, C, nullptr, N, K3, by * 128, smem);
}

// ---------------------------------------------------------------------------
// activation triple conversion: O[row][3K] from A (optionally + B)
// ---------------------------------------------------------------------------
__global__ void act3_kernel(const float* __restrict__ A, const float* __restrict__ B,
                            __nv_bfloat16* __restrict__ O, int K, int n2) {
    int i = blockIdx.x * blockDim.x + threadIdx.x;
    if (i >= n2) return;
    float2 v = ((const float2*)A)[i];
    if (B) { float2 w = ((const float2*)B)[i]; v.x += w.x; v.y += w.y; }
    int row = i / (K / 2);
    int c2  = i % (K / 2);
    store_triple(O + (size_t)row * 3 * K + c2 * 2, K, v.x, v.y);
}

// ---------------------------------------------------------------------------
// tiled transpose weight triple: W[K][N] fp32 -> Bt[N][3K] bf16 [hi|hi|lo]
// block (32,8), 32x32 tile via smem; coalesced on both sides.
// ---------------------------------------------------------------------------
__global__ void wt3t_kernel(const float* __restrict__ W, __nv_bfloat16* __restrict__ Bt,
                            int K, int N) {
    __shared__ float tile[32][33];
    const int n0 = blockIdx.x * 32, k0 = blockIdx.y * 32;
    const int tx = threadIdx.x, ty = threadIdx.y;
    #pragma unroll
    for (int i = 0; i < 4; i++) {
        int k = ty + i * 8;
        tile[k][tx] = W[(size_t)(k0 + k) * N + n0 + tx];
    }
    __syncthreads();
    #pragma unroll
    for (int i = 0; i < 4; i++) {
        int n = ty + i * 8;                 // local n
        float v = tile[tx][n];              // (k=tx, n)
        __nv_bfloat16 h = __float2bfloat16(v);
        __nv_bfloat16 l = __float2bfloat16(v - __bfloat162float(h));
        __nv_bfloat16* p = Bt + (size_t)(n0 + n) * 3 * K + k0 + tx;
        p[0]     = h;
        p[K]     = h;
        p[2 * K] = l;
    }
}

// ---------------------------------------------------------------------------
// MSDA core with fused softmax: warp per (token, head), lane = channel.
// ---------------------------------------------------------------------------
__global__ void msda_kernel(const float* __restrict__ value,
                            const float* __restrict__ off,
                            const float* __restrict__ logits,
                            const float* __restrict__ refp,
                            __nv_bfloat16* __restrict__ out3) {
    const int gtid = blockIdx.x * blockDim.x + threadIdx.x;
    const int warp = gtid >> 5;
    const int lane = gtid & 31;
    if (warp >= NTOK * NH) return;

    const int h = warp & (NH - 1);
    const int t = warp >> 3;
    const int b = t / LEN;

    const float* lg = logits + (size_t)t * 128 + h * 16;
    float l0 = lg[lane & 15];
    float mx = l0;
    #pragma unroll
    for (int o = 1; o < 16; o <<= 1) mx = fmaxf(mx, __shfl_xor_sync(0xffffffffu, mx, o));
    float e = __expf(l0 - mx);
    float s = e;
    #pragma unroll
    for (int o = 1; o < 16; o <<= 1) s += __shfl_xor_sync(0xffffffffu, s, o);
    const float wgt = e / s;

    const float* off_row = off + (size_t)t * CCH + h * (NL * NP * 2);
    const float* ref_row = refp + (size_t)t * (NL * 2);
    const float* vbase   = value + ((size_t)b * LEN) * CCH + h * DH + lane;

    const int dims[NL]   = {64, 32, 16, 8};
    const int starts[NL] = {0, 4096, 5120, 5376};

    float acc = 0.f;

    #pragma unroll
    for (int l = 0; l < NL; l++) {
        const int Wl = dims[l], Hl = dims[l];
        const float fW = (float)Wl, fH = (float)Hl;
        const float rx = ref_row[2 * l];
        const float ry = ref_row[2 * l + 1];
        const float* vl = vbase + (size_t)starts[l] * CCH;

        #pragma unroll
        for (int p = 0; p < NP; p++) {
            const float ox = off_row[(l * NP + p) * 2];
            const float oy = off_row[(l * NP + p) * 2 + 1];
            const float px = (rx + ox / fW) * fW - 0.5f;
            const float py = (ry + oy / fH) * fH - 0.5f;
            const float fx = floorf(px), fy = floorf(py);
            const int x0 = (int)fx, y0 = (int)fy;
            const int x1 = x0 + 1,  y1 = y0 + 1;
            const float wx1 = px - fx, wy1 = py - fy;
            const float wx0 = 1.f - wx1, wy0 = 1.f - wy1;
            const float a = __shfl_sync(0xffffffffu, wgt, l * NP + p);
            const float w00 = a * wx0 * wy0, w10 = a * wx1 * wy0;
            const float w01 = a * wx0 * wy1, w11 = a * wx1 * wy1;

            const bool vx0 = (x0 >= 0) & (x0 < Wl);
            const bool vx1 = (x1 >= 0) & (x1 < Wl);
            const bool vy0 = (y0 >= 0) & (y0 < Hl);
            const bool vy1 = (y1 >= 0) & (y1 < Hl);
            const int cx0 = min(max(x0, 0), Wl - 1);
            const int cx1 = min(max(x1, 0), Wl - 1);
            const int cy0 = min(max(y0, 0), Hl - 1);
            const int cy1 = min(max(y1, 0), Hl - 1);

            if (vy0 & vx0) acc = fmaf(w00, vl[(size_t)(cy0 * Wl + cx0) * CCH], acc);
            if (vy0 & vx1) acc = fmaf(w10, vl[(size_t)(cy0 * Wl + cx1) * CCH], acc);
            if (vy1 & vx0) acc = fmaf(w01, vl[(size_t)(cy1 * Wl + cx0) * CCH], acc);
            if (vy1 & vx1) acc = fmaf(w11, vl[(size_t)(cy1 * Wl + cx1) * CCH], acc);
        }
    }
    const int c = h * DH + lane;
    store_triple1(out3 + (size_t)t * 3 * CCH + c, CCH, acc);
}

// ---------------------------------------------------------------------------
// LayerNorm over C=256 of (a+b): warp per row. Optional bf16-triple output.
// ---------------------------------------------------------------------------
__global__ void ln_kernel(const float* __restrict__ a, const float* __restrict__ b,
                          const float* __restrict__ g, const float* __restrict__ be,
                          float* __restrict__ out, __nv_bfloat16* __restrict__ out3,
                          int rows) {
    const int row = blockIdx.x * (blockDim.x >> 5) + (threadIdx.x >> 5);
    const int lane = threadIdx.x & 31;
    if (row >= rows) return;

    const float* pa = a + (size_t)row * CCH;
    const float* pb = b + (size_t)row * CCH;
    float v[8];
    float s = 0.f;
    #pragma unroll
    for (int j = 0; j < 8; j++) {
        int c = lane + 32 * j;
        v[j] = pa[c] + pb[c];
        s += v[j];
    }
    #pragma unroll
    for (int o = 16; o > 0; o >>= 1) s += __shfl_xor_sync(0xffffffffu, s, o);
    const float mean = s * (1.f / CCH);
    float s2 = 0.f;
    #pragma unroll
    for (int j = 0; j < 8; j++) { float d = v[j] - mean; s2 += d * d; }
    #pragma unroll
    for (int o = 16; o > 0; o >>= 1) s2 += __shfl_xor_sync(0xffffffffu, s2, o);
    const float inv = rsqrtf(s2 * (1.f / CCH) + LN_EPS);

    #pragma unroll
    for (int j = 0; j < 8; j++) {
        int c = lane + 32 * j;
        float y = (v[j] - mean) * inv * g[c] + be[c];
        if (out)  out[(size_t)row * CCH + c] = y;
        if (out3) store_triple1(out3 + (size_t)row * 3 * CCH + c, CCH, y);
    }
}

// ---------------------------------------------------------------------------
// launch
// ---------------------------------------------------------------------------
extern "C" void kernel_launch(void* const* d_in, const int* in_sizes, int n_in,
                              void* d_out, int out_size) {
    const float* src   = (const float*)d_in[0];
    const float* pos   = (const float*)d_in[1];
    const float* refp  = (const float*)d_in[2];
    const float* w_off  = (const float*)d_in[6];
    const float* b_off  = (const float*)d_in[7];
    const float* w_attn = (const float*)d_in[8];
    const float* b_attn = (const float*)d_in[9];
    const float* w_val  = (const float*)d_in[10];
    const float* b_val  = (const float*)d_in[11];
    const float* w_out  = (const float*)d_in[12];
    const float* b_out  = (const float*)d_in[13];
    const float* g1     = (const float*)d_in[14];
    const float* be1    = (const float*)d_in[15];
    const float* w1     = (const float*)d_in[16];
    const float* b1     = (const float*)d_in[17];
    const float* w2     = (const float*)d_in[18];
    const float* b2     = (const float*)d_in[19];
    const float* g2     = (const float*)d_in[20];
    const float* be2    = (const float*)d_in[21];
    float* out = (float*)d_out;

    __nv_bfloat16 *p_q3, *p_src3, *p_msda3, *p_x3, *p_h3;
    __nv_bfloat16 *p_woff3, *p_wattn3, *p_wval3, *p_wout3, *p_w13, *p_w23;
    float *p_off, *p_aw, *p_val, *p_attn, *p_x, *p_ffn;
    cudaGetSymbolAddress((void**)&p_q3,    g_q3);
    cudaGetSymbolAddress((void**)&p_src3,  g_src3);
    cudaGetSymbolAddress((void**)&p_msda3, g_msda3);
    cudaGetSymbolAddress((void**)&p_x3,    g_x3);
    cudaGetSymbolAddress((void**)&p_h3,    g_h3);
    cudaGetSymbolAddress((void**)&p_woff3, g_woff3);
    cudaGetSymbolAddress((void**)&p_wattn3,g_wattn3);
    cudaGetSymbolAddress((void**)&p_wval3, g_wval3);
    cudaGetSymbolAddress((void**)&p_wout3, g_wout3);
    cudaGetSymbolAddress((void**)&p_w13,   g_w13);
    cudaGetSymbolAddress((void**)&p_w23,   g_w23);
    cudaGetSymbolAddress((void**)&p_off,   g_off);
    cudaGetSymbolAddress((void**)&p_aw,    g_aw);
    cudaGetSymbolAddress((void**)&p_val,   g_val);
    cudaGetSymbolAddress((void**)&p_attn,  g_attn);
    cudaGetSymbolAddress((void**)&p_x,     g_x);
    cudaGetSymbolAddress((void**)&p_ffn,   g_ffn);

    const int M = NTOK;  // 21760 = 170 * 128
    const dim3 blk(256);

    const int SM4 = NST * (256 * 128);  // 98304  (BM=128)
    const int SM2 = NST * (192 * 128);  // 73728  (BM=64)
    cudaFuncSetAttribute(proj_gemm,       cudaFuncAttributeMaxDynamicSharedMemorySize, SM4);
    cudaFuncSetAttribute(mma_gemm<4, 1>,  cudaFuncAttributeMaxDynamicSharedMemorySize, SM4);
    cudaFuncSetAttribute(mma_gemm<2, 0>,  cudaFuncAttributeMaxDynamicSharedMemorySize, SM2);

    // weight conversions (tiled transpose)
    wt3t_kernel<<<dim3(CCH / 32, CCH / 32), dim3(32, 8)>>>(w_off,  p_woff3,  CCH, CCH);
    wt3t_kernel<<<dim3(128 / 32, CCH / 32), dim3(32, 8)>>>(w_attn, p_wattn3, CCH, 128);
    wt3t_kernel<<<dim3(CCH / 32, CCH / 32), dim3(32, 8)>>>(w_val,  p_wval3,  CCH, CCH);
    wt3t_kernel<<<dim3(CCH / 32, CCH / 32), dim3(32, 8)>>>(w_out,  p_wout3,  CCH, CCH);
    wt3t_kernel<<<dim3(DFF / 32, CCH / 32), dim3(32, 8)>>>(w1,     p_w13,    CCH, DFF);
    wt3t_kernel<<<dim3(CCH / 32, DFF / 32), dim3(32, 8)>>>(w2,     p_w23,    DFF, CCH);

    // q3 = triple(src + pos), src3 = triple(src)
    {
        int n2 = NTOK * CCH / 2;
        act3_kernel<<<(n2 + 255) / 256, blk>>>(src, pos,     p_q3,   CCH, n2);
        act3_kernel<<<(n2 + 255) / 256, blk>>>(src, nullptr, p_src3, CCH, n2);
    }

    // fused projections: off / logits / value   (850 CTAs)
    proj_gemm<<<dim3(5, M / 128), blk, SM4>>>(p_q3, p_src3, p_woff3, p_wattn3, p_wval3,
                                              b_off, b_attn, b_val, p_off, p_aw, p_val);
    // MSDA gather (softmax fused) -> msda3 (bf16 triple)
    msda_kernel<<<NTOK * NH * 32 / 256, blk>>>(p_val, p_off, p_aw, refp, p_msda3);
    // attn_out = msda @ w_out + b_out   (BM=64: 680 CTAs)
    mma_gemm<2, 0><<<dim3(2, M / 64), blk, SM2>>>(p_msda3, p_wout3, b_out, p_attn, nullptr, CCH, 3 * CCH);
    // x = LN(src + attn_out) -> fp32 + triple
    ln_kernel<<<(NTOK + 7) / 8, blk>>>(src, p_attn, g1, be1, p_x, p_x3, NTOK);
    // h = relu(x @ w1 + b1) -> bf16 triple   (1360 CTAs)
    mma_gemm<4, 1><<<dim3(8, M / 128), blk, SM4>>>(p_x3, p_w13, b1, nullptr, p_h3, DFF, 3 * CCH);
    // ffn = h @ w2 + b2   (BM=64: 680 CTAs)
    mma_gemm<2, 0><<<dim3(2, M / 64), blk, SM2>>>(p_h3, p_w23, b2, p_ffn, nullptr, CCH, 3 * DFF);
    // out = LN(x + ffn)
    ln_kernel<<<(NTOK + 7) / 8, blk>>>(p_x, p_ffn, g2, be2, out, nullptr, NTOK);
}

// round 6
// speedup vs baseline: 2.2238x; 1.0810x over previous
#include <cuda_runtime.h>
#include <cuda_bf16.h>
#include <math.h>

// Problem constants
#define NB   4
#define LEN  5440
#define NTOK (NB * LEN)          // 21760
#define CCH  256
#define NH   8
#define DH   32
#define NL   4
#define NP   4
#define DFF  1024
#define LN_EPS 1e-5f

// ---------------------------------------------------------------------------
// Scratch (device globals)
// Activations and transposed weights stored as bf16 "doubles":
//   [row][2K] = [hi(K) | lo(K)]
// GEMM computes hi*hi + lo*hi + hi*lo (lo*lo dropped, ~2^-18 relative).
// ---------------------------------------------------------------------------
__device__ __nv_bfloat16 g_q2   [NTOK * 2 * CCH];
__device__ __nv_bfloat16 g_src2 [NTOK * 2 * CCH];
__device__ __nv_bfloat16 g_msda2[NTOK * 2 * CCH];
__device__ __nv_bfloat16 g_x2   [NTOK * 2 * CCH];
__device__ __nv_bfloat16 g_h2   [NTOK * 2 * DFF];

__device__ float g_off [NTOK * CCH];
__device__ float g_aw  [NTOK * 128];
__device__ float g_val [NTOK * CCH];
__device__ float g_attn[NTOK * CCH];
__device__ float g_x   [NTOK * CCH];
__device__ float g_ffn [NTOK * CCH];

__device__ __nv_bfloat16 g_woff2 [CCH * 2 * CCH];
__device__ __nv_bfloat16 g_wattn2[128 * 2 * CCH];
__device__ __nv_bfloat16 g_wval2 [CCH * 2 * CCH];
__device__ __nv_bfloat16 g_wout2 [CCH * 2 * CCH];
__device__ __nv_bfloat16 g_w12   [DFF * 2 * CCH];
__device__ __nv_bfloat16 g_w22   [CCH * 2 * DFF];

// ---------------------------------------------------------------------------
// helpers
// ---------------------------------------------------------------------------
__device__ __forceinline__ void store_double(__nv_bfloat16* p, int K, float a, float b) {
    __nv_bfloat16 ah = __float2bfloat16(a), bh = __float2bfloat16(b);
    float ar = a - __bfloat162float(ah);
    float br = b - __bfloat162float(bh);
    *(__nv_bfloat162*)(p)     = __halves2bfloat162(ah, bh);
    *(__nv_bfloat162*)(p + K) = __halves2bfloat162(__float2bfloat16(ar), __float2bfloat16(br));
}

__device__ __forceinline__ void store_double1(__nv_bfloat16* p, int K, float a) {
    __nv_bfloat16 ah = __float2bfloat16(a);
    float ar = a - __bfloat162float(ah);
    p[0] = ah;
    p[K] = __float2bfloat16(ar);
}

__device__ __forceinline__ unsigned smem_u32(const void* p) {
    unsigned a;
    asm("{ .reg .u64 t; cvta.to.shared.u64 t, %1; cvt.u32.u64 %0, t; }" : "=r"(a) : "l"(p));
    return a;
}

__device__ __forceinline__ void cp_async16(unsigned dst, const void* src) {
    asm volatile("cp.async.cg.shared.global [%0], [%1], 16;\n" :: "r"(dst), "l"(src));
}
__device__ __forceinline__ void cp_commit() {
    asm volatile("cp.async.commit_group;\n" ::: "memory");
}
template<int N>
__device__ __forceinline__ void cp_wait() {
    asm volatile("cp.async.wait_group %0;\n" :: "n"(N) : "memory");
}

__device__ __forceinline__ void ldm4(unsigned& r0, unsigned& r1, unsigned& r2, unsigned& r3,
                                     unsigned a) {
    asm volatile("ldmatrix.sync.aligned.m8n8.x4.shared.b16 {%0,%1,%2,%3}, [%4];"
                 : "=r"(r0), "=r"(r1), "=r"(r2), "=r"(r3) : "r"(a));
}

__device__ __forceinline__ void mma_bf16(float c[4],
                                         unsigned a0, unsigned a1, unsigned a2, unsigned a3,
                                         unsigned b0, unsigned b1) {
    asm volatile(
        "mma.sync.aligned.m16n8k16.row.col.f32.bf16.bf16.f32 "
        "{%0,%1,%2,%3},{%4,%5,%6,%7},{%8,%9},{%0,%1,%2,%3};"
        : "+f"(c[0]), "+f"(c[1]), "+f"(c[2]), "+f"(c[3])
        : "r"(a0), "r"(a1), "r"(a2), "r"(a3), "r"(b0), "r"(b1));
}

// ---------------------------------------------------------------------------
// GEMM body. BM = MI*32, BN = 128. 256 threads (8 warps: 2m x 4n). 2 stages.
// Per K-chunk (64 orig cols): stage holds A_hi, A_lo (BM x 128B each),
// B_hi, B_lo (128 x 128B each). Three MMA passes reuse the fragments.
// OUT_MODE 0: fp32 out. 1: relu + bf16-double out (row stride 2N).
// Cf/C3/bias pre-offset by caller; N = logical output width (row stride unit).
// ---------------------------------------------------------------------------
#define NST 2

template<int MI>
__device__ __forceinline__ void gemm_load_stage(unsigned sb, int stage,
                                                const __nv_bfloat16* Ab,
                                                const __nv_bfloat16* Bb,
                                                int K2, int kt, int tid) {
    constexpr int BM = MI * 32;
    constexpr int A_BYTES = BM * 128;          // one tile
    constexpr int STAGE_SZ = (2 * BM + 256) * 128;
    const int K = K2 >> 1;
    const unsigned abase = sb + stage * STAGE_SZ;
    const unsigned bbase = abase + 2 * A_BYTES;
    const __nv_bfloat16* ah = Ab + kt * 64;
    const __nv_bfloat16* al = ah + K;
    const __nv_bfloat16* bh = Bb + kt * 64;
    const __nv_bfloat16* bl = bh + K;
    #pragma unroll
    for (int i = 0; i < MI; i++) {             // BM*8/256 = MI iters per tile
        int id = tid + i * 256;
        int r = id >> 3, c = id & 7;
        unsigned off = (unsigned)(r * 128 + ((c ^ (r & 7)) << 4));
        cp_async16(abase + off,            ah + (size_t)r * K2 + c * 8);
        cp_async16(abase + A_BYTES + off,  al + (size_t)r * K2 + c * 8);
    }
    #pragma unroll
    for (int i = 0; i < 4; i++) {              // 128*8/256 = 4 iters per tile
        int id = tid + i * 256;
        int r = id >> 3, c = id & 7;
        unsigned off = (unsigned)(r * 128 + ((c ^ (r & 7)) << 4));
        cp_async16(bbase + off,              bh + (size_t)r * K2 + c * 8);
        cp_async16(bbase + 128 * 128 + off,  bl + (size_t)r * K2 + c * 8);
    }
    cp_commit();
}

template<int MI, int OUT_MODE>
__device__ __forceinline__ void gemm_body(const __nv_bfloat16* Ab, const __nv_bfloat16* Bb,
                                          const float* bias, float* Cf, __nv_bfloat16* C3,
                                          int N, int K2, int row_base, char* smem) {
    constexpr int BM = MI * 32;
    constexpr int A_BYTES = BM * 128;
    constexpr int STAGE_SZ = (2 * BM + 256) * 128;
    const unsigned sb = smem_u32(smem);

    const int tid = threadIdx.x;
    const int warp = tid >> 5, lane = tid & 31;
    const int wm = warp & 1, wn = warp >> 1;
    const int KT = K2 >> 7;                    // original K / 64

    float acc[MI][4][4];
    #pragma unroll
    for (int i = 0; i < MI; i++)
        #pragma unroll
        for (int j = 0; j < 4; j++)
            #pragma unroll
            for (int r = 0; r < 4; r++) acc[i][j][r] = 0.f;

    gemm_load_stage<MI>(sb, 0, Ab, Bb, K2, 0, tid);

    const int a_row  = (lane & 15);
    const int a_csel = (lane >> 4);
    const int b_rsel = ((lane >> 4) << 3) + (lane & 7);
    const int b_csel = ((lane >> 3) & 1);

    for (int kt = 0; kt < KT; kt++) {
        const int stage = kt & 1;
        cp_wait<0>();
        __syncthreads();
        if (kt + 1 < KT)
            gemm_load_stage<MI>(sb, stage ^ 1, Ab, Bb, K2, kt + 1, tid);

        const unsigned ahb = sb + stage * STAGE_SZ;
        const unsigned alb = ahb + A_BYTES;
        const unsigned bhb = ahb + 2 * A_BYTES;
        const unsigned blb = bhb + 128 * 128;

        #pragma unroll
        for (int kk = 0; kk < 4; kk++) {
            const int c = kk * 2;
            unsigned ah[MI][4], al[MI][4], bh[2][4], bl[2][4];
            #pragma unroll
            for (int mi = 0; mi < MI; mi++) {
                int row = wm * (MI * 16) + mi * 16 + a_row;
                unsigned so = (unsigned)(row * 128 + (((c + a_csel) ^ (row & 7)) << 4));
                ldm4(ah[mi][0], ah[mi][1], ah[mi][2], ah[mi][3], ahb + so);
                ldm4(al[mi][0], al[mi][1], al[mi][2], al[mi][3], alb + so);
            }
            #pragma unroll
            for (int nj2 = 0; nj2 < 2; nj2++) {
                int nrow = wn * 32 + nj2 * 16 + b_rsel;
                unsigned so = (unsigned)(nrow * 128 + (((c + b_csel) ^ (nrow & 7)) << 4));
                ldm4(bh[nj2][0], bh[nj2][1], bh[nj2][2], bh[nj2][3], bhb + so);
                ldm4(bl[nj2][0], bl[nj2][1], bl[nj2][2], bl[nj2][3], blb + so);
            }
            #pragma unroll
            for (int mi = 0; mi < MI; mi++)
                #pragma unroll
                for (int nj = 0; nj < 4; nj++) {
                    const unsigned* bph = bh[nj >> 1];
                    const unsigned* bpl = bl[nj >> 1];
                    unsigned h0 = (nj & 1) ? bph[2] : bph[0];
                    unsigned h1 = (nj & 1) ? bph[3] : bph[1];
                    unsigned l0 = (nj & 1) ? bpl[2] : bpl[0];
                    unsigned l1 = (nj & 1) ? bpl[3] : bpl[1];
                    mma_bf16(acc[mi][nj], ah[mi][0], ah[mi][1], ah[mi][2], ah[mi][3], h0, h1);
                    mma_bf16(acc[mi][nj], al[mi][0], al[mi][1], al[mi][2], al[mi][3], h0, h1);
                    mma_bf16(acc[mi][nj], ah[mi][0], ah[mi][1], ah[mi][2], ah[mi][3], l0, l1);
                }
        }
    }

    // epilogue
    const int col0 = wn * 32 + (lane & 3) * 2;
    #pragma unroll
    for (int mi = 0; mi < MI; mi++) {
        int row = row_base + wm * (MI * 16) + mi * 16 + (lane >> 2);
        #pragma unroll
        for (int nj = 0; nj < 4; nj++) {
            int col = col0 + nj * 8;
            float b0v = bias[col], b1v = bias[col + 1];
            float v00 = acc[mi][nj][0] + b0v, v01 = acc[mi][nj][1] + b1v;
            float v10 = acc[mi][nj][2] + b0v, v11 = acc[mi][nj][3] + b1v;
            if (OUT_MODE == 0) {
                *(float2*)(Cf + (size_t)row * N + col)       = make_float2(v00, v01);
                *(float2*)(Cf + (size_t)(row + 8) * N + col) = make_float2(v10, v11);
            } else {
                v00 = fmaxf(v00, 0.f); v01 = fmaxf(v01, 0.f);
                v10 = fmaxf(v10, 0.f); v11 = fmaxf(v11, 0.f);
                store_double(C3 + (size_t)row * 2 * N + col, N, v00, v01);
                store_double(C3 + (size_t)(row + 8) * 2 * N + col, N, v10, v11);
            }
        }
    }
}

// generic GEMM kernel (BM = 64)
template<int OUT_MODE>
__global__ __launch_bounds__(256, 2)
void mma_gemm(const __nv_bfloat16* __restrict__ A, const __nv_bfloat16* __restrict__ Bt,
              const float* __restrict__ bias, float* __restrict__ Cf,
              __nv_bfloat16* __restrict__ C3, int N, int K2) {
    extern __shared__ __align__(1024) char smem[];
    const int bx = blockIdx.x, by = blockIdx.y;
    gemm_body<2, OUT_MODE>(A + (size_t)by * 64 * K2,
                           Bt + (size_t)bx * 128 * (size_t)K2,
                           bias + bx * 128,
                           Cf ? Cf + bx * 128 : nullptr,
                           C3 ? C3 + bx * 128 : nullptr,
                           N, K2, by * 64, smem);
}

// fused projection GEMM: bx selects {off0, off1, logits, val0, val1}
__global__ __launch_bounds__(256, 2)
void proj_gemm(const __nv_bfloat16* __restrict__ q2, const __nv_bfloat16* __restrict__ src2,
               const __nv_bfloat16* __restrict__ woff2, const __nv_bfloat16* __restrict__ wattn2,
               const __nv_bfloat16* __restrict__ wval2,
               const float* __restrict__ b_off, const float* __restrict__ b_attn,
               const float* __restrict__ b_val,
               float* __restrict__ c_off, float* __restrict__ c_aw, float* __restrict__ c_val) {
    extern __shared__ __align__(1024) char smem[];
    const int bx = blockIdx.x, by = blockIdx.y;
    const int K2 = 2 * CCH;

    const __nv_bfloat16* A;
    const __nv_bfloat16* B;
    const float* bias;
    float* C;
    int N;
    if (bx < 2) {
        A = q2; B = woff2 + (size_t)bx * 128 * K2; bias = b_off + bx * 128;
        C = c_off + bx * 128; N = CCH;
    } else if (bx == 2) {
        A = q2; B = wattn2; bias = b_attn; C = c_aw; N = 128;
    } else {
        int s = bx - 3;
        A = src2; B = wval2 + (size_t)s * 128 * K2; bias = b_val + s * 128;
        C = c_val + s * 128; N = CCH;
    }
    gemm_body<2, 0>(A + (size_t)by * 64 * K2, B, bias, C, nullptr, N, K2, by * 64, smem);
}

// ---------------------------------------------------------------------------
// activation double conversion: O[row][2K] from A (optionally + B)
// ---------------------------------------------------------------------------
__global__ void act2_kernel(const float* __restrict__ A, const float* __restrict__ B,
                            __nv_bfloat16* __restrict__ O, int K, int n2) {
    int i = blockIdx.x * blockDim.x + threadIdx.x;
    if (i >= n2) return;
    float2 v = ((const float2*)A)[i];
    if (B) { float2 w = ((const float2*)B)[i]; v.x += w.x; v.y += w.y; }
    int row = i / (K / 2);
    int c2  = i % (K / 2);
    store_double(O + (size_t)row * 2 * K + c2 * 2, K, v.x, v.y);
}

// ---------------------------------------------------------------------------
// tiled transpose weight double: W[K][N] fp32 -> Bt[N][2K] bf16 [hi|lo]
// ---------------------------------------------------------------------------
__global__ void wt2t_kernel(const float* __restrict__ W, __nv_bfloat16* __restrict__ Bt,
                            int K, int N) {
    __shared__ float tile[32][33];
    const int n0 = blockIdx.x * 32, k0 = blockIdx.y * 32;
    const int tx = threadIdx.x, ty = threadIdx.y;
    #pragma unroll
    for (int i = 0; i < 4; i++) {
        int k = ty + i * 8;
        tile[k][tx] = W[(size_t)(k0 + k) * N + n0 + tx];
    }
    __syncthreads();
    #pragma unroll
    for (int i = 0; i < 4; i++) {
        int n = ty + i * 8;
        float v = tile[tx][n];
        __nv_bfloat16 h = __float2bfloat16(v);
        __nv_bfloat16 l = __float2bfloat16(v - __bfloat162float(h));
        __nv_bfloat16* p = Bt + (size_t)(n0 + n) * 2 * K + k0 + tx;
        p[0] = h;
        p[K] = l;
    }
}

// ---------------------------------------------------------------------------
// MSDA core with fused softmax: warp per (token, head), lane = channel.
// ---------------------------------------------------------------------------
__global__ void msda_kernel(const float* __restrict__ value,
                            const float* __restrict__ off,
                            const float* __restrict__ logits,
                            const float* __restrict__ refp,
                            __nv_bfloat16* __restrict__ out2) {
    const int gtid = blockIdx.x * blockDim.x + threadIdx.x;
    const int warp = gtid >> 5;
    const int lane = gtid & 31;
    if (warp >= NTOK * NH) return;

    const int h = warp & (NH - 1);
    const int t = warp >> 3;
    const int b = t / LEN;

    const float* lg = logits + (size_t)t * 128 + h * 16;
    float l0 = lg[lane & 15];
    float mx = l0;
    #pragma unroll
    for (int o = 1; o < 16; o <<= 1) mx = fmaxf(mx, __shfl_xor_sync(0xffffffffu, mx, o));
    float e = __expf(l0 - mx);
    float s = e;
    #pragma unroll
    for (int o = 1; o < 16; o <<= 1) s += __shfl_xor_sync(0xffffffffu, s, o);
    const float wgt = e / s;

    const float* off_row = off + (size_t)t * CCH + h * (NL * NP * 2);
    const float* ref_row = refp + (size_t)t * (NL * 2);
    const float* vbase   = value + ((size_t)b * LEN) * CCH + h * DH + lane;

    const int dims[NL]   = {64, 32, 16, 8};
    const int starts[NL] = {0, 4096, 5120, 5376};

    float acc = 0.f;

    #pragma unroll
    for (int l = 0; l < NL; l++) {
        const int Wl = dims[l], Hl = dims[l];
        const float fW = (float)Wl, fH = (float)Hl;
        const float rx = ref_row[2 * l];
        const float ry = ref_row[2 * l + 1];
        const float* vl = vbase + (size_t)starts[l] * CCH;

        #pragma unroll
        for (int p = 0; p < NP; p++) {
            const float ox = off_row[(l * NP + p) * 2];
            const float oy = off_row[(l * NP + p) * 2 + 1];
            const float px = (rx + ox / fW) * fW - 0.5f;
            const float py = (ry + oy / fH) * fH - 0.5f;
            const float fx = floorf(px), fy = floorf(py);
            const int x0 = (int)fx, y0 = (int)fy;
            const int x1 = x0 + 1,  y1 = y0 + 1;
            const float wx1 = px - fx, wy1 = py - fy;
            const float wx0 = 1.f - wx1, wy0 = 1.f - wy1;
            const float a = __shfl_sync(0xffffffffu, wgt, l * NP + p);
            const float w00 = a * wx0 * wy0, w10 = a * wx1 * wy0;
            const float w01 = a * wx0 * wy1, w11 = a * wx1 * wy1;

            const bool vx0 = (x0 >= 0) & (x0 < Wl);
            const bool vx1 = (x1 >= 0) & (x1 < Wl);
            const bool vy0 = (y0 >= 0) & (y0 < Hl);
            const bool vy1 = (y1 >= 0) & (y1 < Hl);
            const int cx0 = min(max(x0, 0), Wl - 1);
            const int cx1 = min(max(x1, 0), Wl - 1);
            const int cy0 = min(max(y0, 0), Hl - 1);
            const int cy1 = min(max(y1, 0), Hl - 1);

            if (vy0 & vx0) acc = fmaf(w00, vl[(size_t)(cy0 * Wl + cx0) * CCH], acc);
            if (vy0 & vx1) acc = fmaf(w10, vl[(size_t)(cy0 * Wl + cx1) * CCH], acc);
            if (vy1 & vx0) acc = fmaf(w01, vl[(size_t)(cy1 * Wl + cx0) * CCH], acc);
            if (vy1 & vx1) acc = fmaf(w11, vl[(size_t)(cy1 * Wl + cx1) * CCH], acc);
        }
    }
    const int c = h * DH + lane;
    store_double1(out2 + (size_t)t * 2 * CCH + c, CCH, acc);
}

// ---------------------------------------------------------------------------
// LayerNorm over C=256 of (a+b): warp per row. Optional bf16-double output.
// ---------------------------------------------------------------------------
__global__ void ln_kernel(const float* __restrict__ a, const float* __restrict__ b,
                          const float* __restrict__ g, const float* __restrict__ be,
                          float* __restrict__ out, __nv_bfloat16* __restrict__ out2,
                          int rows) {
    const int row = blockIdx.x * (blockDim.x >> 5) + (threadIdx.x >> 5);
    const int lane = threadIdx.x & 31;
    if (row >= rows) return;

    const float* pa = a + (size_t)row * CCH;
    const float* pb = b + (size_t)row * CCH;
    float v[8];
    float s = 0.f;
    #pragma unroll
    for (int j = 0; j < 8; j++) {
        int c = lane + 32 * j;
        v[j] = pa[c] + pb[c];
        s += v[j];
    }
    #pragma unroll
    for (int o = 16; o > 0; o >>= 1) s += __shfl_xor_sync(0xffffffffu, s, o);
    const float mean = s * (1.f / CCH);
    float s2 = 0.f;
    #pragma unroll
    for (int j = 0; j < 8; j++) { float d = v[j] - mean; s2 += d * d; }
    #pragma unroll
    for (int o = 16; o > 0; o >>= 1) s2 += __shfl_xor_sync(0xffffffffu, s2, o);
    const float inv = rsqrtf(s2 * (1.f / CCH) + LN_EPS);

    #pragma unroll
    for (int j = 0; j < 8; j++) {
        int c = lane + 32 * j;
        float y = (v[j] - mean) * inv * g[c] + be[c];
        if (out)  out[(size_t)row * CCH + c] = y;
        if (out2) store_double1(out2 + (size_t)row * 2 * CCH + c, CCH, y);
    }
}

// ---------------------------------------------------------------------------
// launch
// ---------------------------------------------------------------------------
extern "C" void kernel_launch(void* const* d_in, const int* in_sizes, int n_in,
                              void* d_out, int out_size) {
    const float* src   = (const float*)d_in[0];
    const float* pos   = (const float*)d_in[1];
    const float* refp  = (const float*)d_in[2];
    const float* w_off  = (const float*)d_in[6];
    const float* b_off  = (const float*)d_in[7];
    const float* w_attn = (const float*)d_in[8];
    const float* b_attn = (const float*)d_in[9];
    const float* w_val  = (const float*)d_in[10];
    const float* b_val  = (const float*)d_in[11];
    const float* w_out  = (const float*)d_in[12];
    const float* b_out  = (const float*)d_in[13];
    const float* g1     = (const float*)d_in[14];
    const float* be1    = (const float*)d_in[15];
    const float* w1     = (const float*)d_in[16];
    const float* b1     = (const float*)d_in[17];
    const float* w2     = (const float*)d_in[18];
    const float* b2     = (const float*)d_in[19];
    const float* g2     = (const float*)d_in[20];
    const float* be2    = (const float*)d_in[21];
    float* out = (float*)d_out;

    __nv_bfloat16 *p_q2, *p_src2, *p_msda2, *p_x2, *p_h2;
    __nv_bfloat16 *p_woff2, *p_wattn2, *p_wval2, *p_wout2, *p_w12, *p_w22;
    float *p_off, *p_aw, *p_val, *p_attn, *p_x, *p_ffn;
    cudaGetSymbolAddress((void**)&p_q2,    g_q2);
    cudaGetSymbolAddress((void**)&p_src2,  g_src2);
    cudaGetSymbolAddress((void**)&p_msda2, g_msda2);
    cudaGetSymbolAddress((void**)&p_x2,    g_x2);
    cudaGetSymbolAddress((void**)&p_h2,    g_h2);
    cudaGetSymbolAddress((void**)&p_woff2, g_woff2);
    cudaGetSymbolAddress((void**)&p_wattn2,g_wattn2);
    cudaGetSymbolAddress((void**)&p_wval2, g_wval2);
    cudaGetSymbolAddress((void**)&p_wout2, g_wout2);
    cudaGetSymbolAddress((void**)&p_w12,   g_w12);
    cudaGetSymbolAddress((void**)&p_w22,   g_w22);
    cudaGetSymbolAddress((void**)&p_off,   g_off);
    cudaGetSymbolAddress((void**)&p_aw,    g_aw);
    cudaGetSymbolAddress((void**)&p_val,   g_val);
    cudaGetSymbolAddress((void**)&p_attn,  g_attn);
    cudaGetSymbolAddress((void**)&p_x,     g_x);
    cudaGetSymbolAddress((void**)&p_ffn,   g_ffn);

    const int M = NTOK;  // 21760 = 340 * 64
    const dim3 blk(256);

    const int SM2 = NST * ((2 * 64 + 256) * 128);  // 2 * 49152 = 98304
    cudaFuncSetAttribute(proj_gemm,    cudaFuncAttributeMaxDynamicSharedMemorySize, SM2);
    cudaFuncSetAttribute(mma_gemm<0>,  cudaFuncAttributeMaxDynamicSharedMemorySize, SM2);
    cudaFuncSetAttribute(mma_gemm<1>,  cudaFuncAttributeMaxDynamicSharedMemorySize, SM2);

    // weight conversions (tiled transpose)
    wt2t_kernel<<<dim3(CCH / 32, CCH / 32), dim3(32, 8)>>>(w_off,  p_woff2,  CCH, CCH);
    wt2t_kernel<<<dim3(128 / 32, CCH / 32), dim3(32, 8)>>>(w_attn, p_wattn2, CCH, 128);
    wt2t_kernel<<<dim3(CCH / 32, CCH / 32), dim3(32, 8)>>>(w_val,  p_wval2,  CCH, CCH);
    wt2t_kernel<<<dim3(CCH / 32, CCH / 32), dim3(32, 8)>>>(w_out,  p_wout2,  CCH, CCH);
    wt2t_kernel<<<dim3(DFF / 32, CCH / 32), dim3(32, 8)>>>(w1,     p_w12,    CCH, DFF);
    wt2t_kernel<<<dim3(CCH / 32, DFF / 32), dim3(32, 8)>>>(w2,     p_w22,    DFF, CCH);

    // q2 = double(src + pos), src2 = double(src)
    {
        int n2 = NTOK * CCH / 2;
        act2_kernel<<<(n2 + 255) / 256, blk>>>(src, pos,     p_q2,   CCH, n2);
        act2_kernel<<<(n2 + 255) / 256, blk>>>(src, nullptr, p_src2, CCH, n2);
    }

    // fused projections: off / logits / value   (1700 CTAs)
    proj_gemm<<<dim3(5, M / 64), blk, SM2>>>(p_q2, p_src2, p_woff2, p_wattn2, p_wval2,
                                             b_off, b_attn, b_val, p_off, p_aw, p_val);
    // MSDA gather (softmax fused) -> msda2 (bf16 double)
    msda_kernel<<<NTOK * NH * 32 / 256, blk>>>(p_val, p_off, p_aw, refp, p_msda2);
    // attn_out = msda @ w_out + b_out   (680 CTAs)
    mma_gemm<0><<<dim3(2, M / 64), blk, SM2>>>(p_msda2, p_wout2, b_out, p_attn, nullptr, CCH, 2 * CCH);
    // x = LN(src + attn_out) -> fp32 + double
    ln_kernel<<<(NTOK + 7) / 8, blk>>>(src, p_attn, g1, be1, p_x, p_x2, NTOK);
    // h = relu(x @ w1 + b1) -> bf16 double   (2720 CTAs)
    mma_gemm<1><<<dim3(8, M / 64), blk, SM2>>>(p_x2, p_w12, b1, nullptr, p_h2, DFF, 2 * CCH);
    // ffn = h @ w2 + b2   (680 CTAs)
    mma_gemm<0><<<dim3(2, M / 64), blk, SM2>>>(p_h2, p_w22, b2, p_ffn, nullptr, CCH, 2 * DFF);
    // out = LN(x + ffn)
    ln_kernel<<<(NTOK + 7) / 8, blk>>>(p_x, p_ffn, g2, be2, out, nullptr, NTOK);
}

// round 7
// speedup vs baseline: 2.7063x; 1.2170x over previous
#include <cuda_runtime.h>
#include <cuda_fp16.h>
#include <math.h>

// Problem constants
#define NB   4
#define LEN  5440
#define NTOK (NB * LEN)          // 21760
#define CCH  256
#define NH   8
#define DH   32
#define NL   4
#define NP   4
#define DFF  1024
#define LN_EPS 1e-5f

// ---------------------------------------------------------------------------
// Scratch. Activations as fp16 "pairs": [row][2K] = [hi(K) | lo(K)]
// (hi+lo captures ~22 mantissa bits). Weights as SINGLE fp16, transposed
// [N][K]. GEMM = A_hi*B + A_lo*B (2 passes); error ~2^-12 from B rounding.
// ---------------------------------------------------------------------------
__device__ __half g_q2   [NTOK * 2 * CCH];
__device__ __half g_src2 [NTOK * 2 * CCH];
__device__ __half g_msda2[NTOK * 2 * CCH];
__device__ __half g_x2   [NTOK * 2 * CCH];
__device__ __half g_h2   [NTOK * 2 * DFF];

__device__ float g_off [NTOK * CCH];
__device__ float g_aw  [NTOK * 128];
__device__ float g_val [NTOK * CCH];
__device__ float g_attn[NTOK * CCH];
__device__ float g_x   [NTOK * CCH];
__device__ float g_ffn [NTOK * CCH];

__device__ __half g_woffh [CCH * CCH];
__device__ __half g_wattnh[128 * CCH];
__device__ __half g_wvalh [CCH * CCH];
__device__ __half g_wouth [CCH * CCH];
__device__ __half g_w1h   [DFF * CCH];
__device__ __half g_w2h   [CCH * DFF];

// ---------------------------------------------------------------------------
// helpers
// ---------------------------------------------------------------------------
__device__ __forceinline__ void store_h2pair(__half* p, int K, float a, float b) {
    __half ah = __float2half_rn(a), bh = __float2half_rn(b);
    float ar = a - __half2float(ah);
    float br = b - __half2float(bh);
    *(__half2*)(p)     = __halves2half2(ah, bh);
    *(__half2*)(p + K) = __halves2half2(__float2half_rn(ar), __float2half_rn(br));
}

__device__ __forceinline__ void store_h1pair(__half* p, int K, float a) {
    __half ah = __float2half_rn(a);
    p[0] = ah;
    p[K] = __float2half_rn(a - __half2float(ah));
}

__device__ __forceinline__ unsigned smem_u32(const void* p) {
    unsigned a;
    asm("{ .reg .u64 t; cvta.to.shared.u64 t, %1; cvt.u32.u64 %0, t; }" : "=r"(a) : "l"(p));
    return a;
}

__device__ __forceinline__ void cp_async16(unsigned dst, const void* src) {
    asm volatile("cp.async.cg.shared.global [%0], [%1], 16;\n" :: "r"(dst), "l"(src));
}
__device__ __forceinline__ void cp_commit() {
    asm volatile("cp.async.commit_group;\n" ::: "memory");
}
template<int N>
__device__ __forceinline__ void cp_wait() {
    asm volatile("cp.async.wait_group %0;\n" :: "n"(N) : "memory");
}

__device__ __forceinline__ void ldm4(unsigned& r0, unsigned& r1, unsigned& r2, unsigned& r3,
                                     unsigned a) {
    asm volatile("ldmatrix.sync.aligned.m8n8.x4.shared.b16 {%0,%1,%2,%3}, [%4];"
                 : "=r"(r0), "=r"(r1), "=r"(r2), "=r"(r3) : "r"(a));
}

__device__ __forceinline__ void mma_f16(float c[4],
                                        unsigned a0, unsigned a1, unsigned a2, unsigned a3,
                                        unsigned b0, unsigned b1) {
    asm volatile(
        "mma.sync.aligned.m16n8k16.row.col.f32.f16.f16.f32 "
        "{%0,%1,%2,%3},{%4,%5,%6,%7},{%8,%9},{%0,%1,%2,%3};"
        : "+f"(c[0]), "+f"(c[1]), "+f"(c[2]), "+f"(c[3])
        : "r"(a0), "r"(a1), "r"(a2), "r"(a3), "r"(b0), "r"(b1));
}

// ---------------------------------------------------------------------------
// GEMM. BM=64 (MI=2), BN=128. 256 threads (8 warps: 2m x 4n). NST=3 stages.
// Stage: A_hi (64x128B) + A_lo (64x128B) + B (128x128B) = 32 KB.
// Per k16: 2 MMA passes (A_hi*B, A_lo*B).
// OUT_MODE 0: fp32 out. 1: relu + fp16-pair out (row stride 2N).
// A2 row stride = 2K; B row stride = K. Cf/C2/bias pre-offset by caller.
// ---------------------------------------------------------------------------
#define NST 3
#define GBM 64
#define A_BYTES (GBM * 128)
#define STAGE_SZ ((2 * GBM + 128) * 128)   // 32768

__device__ __forceinline__ void gemm_load_stage(unsigned sb, int stage,
                                                const __half* A2, const __half* B,
                                                int K, int kt, int tid) {
    const unsigned abase = sb + stage * STAGE_SZ;
    const unsigned bbase = abase + 2 * A_BYTES;
    const __half* ah = A2 + kt * 64;
    const __half* al = ah + K;
    const __half* bg = B + kt * 64;
    const int K2 = 2 * K;
    #pragma unroll
    for (int i = 0; i < 2; i++) {            // 64 rows x 8 chunks / 256 thr
        int id = tid + i * 256;
        int r = id >> 3, c = id & 7;
        unsigned off = (unsigned)(r * 128 + ((c ^ (r & 7)) << 4));
        cp_async16(abase + off,           ah + (size_t)r * K2 + c * 8);
        cp_async16(abase + A_BYTES + off, al + (size_t)r * K2 + c * 8);
    }
    #pragma unroll
    for (int i = 0; i < 4; i++) {            // 128 rows
        int id = tid + i * 256;
        int r = id >> 3, c = id & 7;
        unsigned off = (unsigned)(r * 128 + ((c ^ (r & 7)) << 4));
        cp_async16(bbase + off, bg + (size_t)r * K + c * 8);
    }
    cp_commit();
}

template<int OUT_MODE>
__device__ __forceinline__ void gemm_body(const __half* A2, const __half* B,
                                          const float* bias, float* Cf, __half* C2,
                                          int N, int K, int row_base, char* smem) {
    const unsigned sb = smem_u32(smem);
    const int tid = threadIdx.x;
    const int warp = tid >> 5, lane = tid & 31;
    const int wm = warp & 1, wn = warp >> 1;
    const int KT = K >> 6;

    float acc[2][4][4];
    #pragma unroll
    for (int i = 0; i < 2; i++)
        #pragma unroll
        for (int j = 0; j < 4; j++)
            #pragma unroll
            for (int r = 0; r < 4; r++) acc[i][j][r] = 0.f;

    gemm_load_stage(sb, 0, A2, B, K, 0, tid);
    if (KT > 1) gemm_load_stage(sb, 1, A2, B, K, 1, tid); else cp_commit();

    const int a_row  = (lane & 15);
    const int a_csel = (lane >> 4);
    const int b_rsel = ((lane >> 4) << 3) + (lane & 7);
    const int b_csel = ((lane >> 3) & 1);

    for (int kt = 0; kt < KT; kt++) {
        const int stage = kt % NST;
        cp_wait<1>();
        __syncthreads();
        if (kt + 2 < KT)
            gemm_load_stage(sb, (kt + 2) % NST, A2, B, K, kt + 2, tid);
        else
            cp_commit();

        const unsigned ahb = sb + stage * STAGE_SZ;
        const unsigned alb = ahb + A_BYTES;
        const unsigned bbb = ahb + 2 * A_BYTES;

        #pragma unroll
        for (int kk = 0; kk < 4; kk++) {
            const int c = kk * 2;
            unsigned ah[2][4], al[2][4], bf[2][4];
            #pragma unroll
            for (int mi = 0; mi < 2; mi++) {
                int row = wm * 32 + mi * 16 + a_row;
                unsigned so = (unsigned)(row * 128 + (((c + a_csel) ^ (row & 7)) << 4));
                ldm4(ah[mi][0], ah[mi][1], ah[mi][2], ah[mi][3], ahb + so);
                ldm4(al[mi][0], al[mi][1], al[mi][2], al[mi][3], alb + so);
            }
            #pragma unroll
            for (int nj2 = 0; nj2 < 2; nj2++) {
                int nrow = wn * 32 + nj2 * 16 + b_rsel;
                unsigned so = (unsigned)(nrow * 128 + (((c + b_csel) ^ (nrow & 7)) << 4));
                ldm4(bf[nj2][0], bf[nj2][1], bf[nj2][2], bf[nj2][3], bbb + so);
            }
            #pragma unroll
            for (int mi = 0; mi < 2; mi++)
                #pragma unroll
                for (int nj = 0; nj < 4; nj++) {
                    const unsigned* b = bf[nj >> 1];
                    unsigned b0 = (nj & 1) ? b[2] : b[0];
                    unsigned b1 = (nj & 1) ? b[3] : b[1];
                    mma_f16(acc[mi][nj], ah[mi][0], ah[mi][1], ah[mi][2], ah[mi][3], b0, b1);
                    mma_f16(acc[mi][nj], al[mi][0], al[mi][1], al[mi][2], al[mi][3], b0, b1);
                }
        }
    }

    // epilogue
    const int col0 = wn * 32 + (lane & 3) * 2;
    #pragma unroll
    for (int mi = 0; mi < 2; mi++) {
        int row = row_base + wm * 32 + mi * 16 + (lane >> 2);
        #pragma unroll
        for (int nj = 0; nj < 4; nj++) {
            int col = col0 + nj * 8;
            float b0v = bias[col], b1v = bias[col + 1];
            float v00 = acc[mi][nj][0] + b0v, v01 = acc[mi][nj][1] + b1v;
            float v10 = acc[mi][nj][2] + b0v, v11 = acc[mi][nj][3] + b1v;
            if (OUT_MODE == 0) {
                *(float2*)(Cf + (size_t)row * N + col)       = make_float2(v00, v01);
                *(float2*)(Cf + (size_t)(row + 8) * N + col) = make_float2(v10, v11);
            } else {
                v00 = fmaxf(v00, 0.f); v01 = fmaxf(v01, 0.f);
                v10 = fmaxf(v10, 0.f); v11 = fmaxf(v11, 0.f);
                store_h2pair(C2 + (size_t)row * 2 * N + col, N, v00, v01);
                store_h2pair(C2 + (size_t)(row + 8) * 2 * N + col, N, v10, v11);
            }
        }
    }
}

template<int OUT_MODE>
__global__ __launch_bounds__(256, 2)
void mma_gemm(const __half* __restrict__ A2, const __half* __restrict__ Bt,
              const float* __restrict__ bias, float* __restrict__ Cf,
              __half* __restrict__ C2, int N, int K) {
    extern __shared__ __align__(1024) char smem[];
    const int bx = blockIdx.x, by = blockIdx.y;
    gemm_body<OUT_MODE>(A2 + (size_t)by * GBM * 2 * K,
                        Bt + (size_t)bx * 128 * (size_t)K,
                        bias + bx * 128,
                        Cf ? Cf + bx * 128 : nullptr,
                        C2 ? C2 + bx * 128 : nullptr,
                        N, K, by * GBM, smem);
}

// fused projection GEMM: bx selects {off0, off1, logits, val0, val1}
__global__ __launch_bounds__(256, 2)
void proj_gemm(const __half* __restrict__ q2, const __half* __restrict__ src2,
               const __half* __restrict__ woffh, const __half* __restrict__ wattnh,
               const __half* __restrict__ wvalh,
               const float* __restrict__ b_off, const float* __restrict__ b_attn,
               const float* __restrict__ b_val,
               float* __restrict__ c_off, float* __restrict__ c_aw, float* __restrict__ c_val) {
    extern __shared__ __align__(1024) char smem[];
    const int bx = blockIdx.x, by = blockIdx.y;
    const int K = CCH;

    const __half* A;
    const __half* B;
    const float* bias;
    float* C;
    int N;
    if (bx < 2) {
        A = q2; B = woffh + (size_t)bx * 128 * K; bias = b_off + bx * 128;
        C = c_off + bx * 128; N = CCH;
    } else if (bx == 2) {
        A = q2; B = wattnh; bias = b_attn; C = c_aw; N = 128;
    } else {
        int s = bx - 3;
        A = src2; B = wvalh + (size_t)s * 128 * K; bias = b_val + s * 128;
        C = c_val + s * 128; N = CCH;
    }
    gemm_body<0>(A + (size_t)by * GBM * 2 * K, B, bias, C, nullptr, N, K, by * GBM, smem);
}

// ---------------------------------------------------------------------------
// fused activation conversion: q2 = pair(src+pos), src2 = pair(src)
// ---------------------------------------------------------------------------
__global__ void act_pair_kernel(const float* __restrict__ src, const float* __restrict__ pos,
                                __half* __restrict__ q2, __half* __restrict__ s2, int n2) {
    int i = blockIdx.x * blockDim.x + threadIdx.x;
    if (i >= n2) return;
    float2 s = ((const float2*)src)[i];
    float2 p = ((const float2*)pos)[i];
    int row = i / (CCH / 2);
    int c2  = (i % (CCH / 2)) * 2;
    store_h2pair(s2 + (size_t)row * 2 * CCH + c2, CCH, s.x, s.y);
    store_h2pair(q2 + (size_t)row * 2 * CCH + c2, CCH, s.x + p.x, s.y + p.y);
}

// ---------------------------------------------------------------------------
// tiled transpose weight: W[K][N] fp32 -> Bt[N][K] fp16
// ---------------------------------------------------------------------------
__global__ void wth_kernel(const float* __restrict__ W, __half* __restrict__ Bt,
                           int K, int N) {
    __shared__ float tile[32][33];
    const int n0 = blockIdx.x * 32, k0 = blockIdx.y * 32;
    const int tx = threadIdx.x, ty = threadIdx.y;
    #pragma unroll
    for (int i = 0; i < 4; i++) {
        int k = ty + i * 8;
        tile[k][tx] = W[(size_t)(k0 + k) * N + n0 + tx];
    }
    __syncthreads();
    #pragma unroll
    for (int i = 0; i < 4; i++) {
        int n = ty + i * 8;
        Bt[(size_t)(n0 + n) * K + k0 + tx] = __float2half_rn(tile[tx][n]);
    }
}

// ---------------------------------------------------------------------------
// MSDA with fused softmax. CTA = 8 consecutive tokens x ONE head
// (locality: nearby tokens + same head sample overlapping value lines -> L1).
// warp = one (token, head); lane = channel.
// ---------------------------------------------------------------------------
__global__ void msda_kernel(const float* __restrict__ value,
                            const float* __restrict__ off,
                            const float* __restrict__ logits,
                            const float* __restrict__ refp,
                            __half* __restrict__ out2) {
    const int warp = threadIdx.x >> 5;
    const int lane = threadIdx.x & 31;
    const int h  = blockIdx.x & (NH - 1);
    const int t  = (blockIdx.x >> 3) * 8 + warp;
    const int b  = t / LEN;

    const float* lg = logits + (size_t)t * 128 + h * 16;
    float l0 = lg[lane & 15];
    float mx = l0;
    #pragma unroll
    for (int o = 1; o < 16; o <<= 1) mx = fmaxf(mx, __shfl_xor_sync(0xffffffffu, mx, o));
    float e = __expf(l0 - mx);
    float s = e;
    #pragma unroll
    for (int o = 1; o < 16; o <<= 1) s += __shfl_xor_sync(0xffffffffu, s, o);
    const float wgt = e / s;

    const float* off_row = off + (size_t)t * CCH + h * (NL * NP * 2);
    const float* ref_row = refp + (size_t)t * (NL * 2);
    const float* vbase   = value + ((size_t)b * LEN) * CCH + h * DH + lane;

    const int dims[NL]   = {64, 32, 16, 8};
    const int starts[NL] = {0, 4096, 5120, 5376};

    float acc = 0.f;

    #pragma unroll
    for (int l = 0; l < NL; l++) {
        const int Wl = dims[l], Hl = dims[l];
        const float fW = (float)Wl, fH = (float)Hl;
        const float rx = ref_row[2 * l];
        const float ry = ref_row[2 * l + 1];
        const float* vl = vbase + (size_t)starts[l] * CCH;

        #pragma unroll
        for (int p = 0; p < NP; p++) {
            const float ox = off_row[(l * NP + p) * 2];
            const float oy = off_row[(l * NP + p) * 2 + 1];
            const float px = (rx + ox / fW) * fW - 0.5f;
            const float py = (ry + oy / fH) * fH - 0.5f;
            const float fx = floorf(px), fy = floorf(py);
            const int x0 = (int)fx, y0 = (int)fy;
            const int x1 = x0 + 1,  y1 = y0 + 1;
            const float wx1 = px - fx, wy1 = py - fy;
            const float wx0 = 1.f - wx1, wy0 = 1.f - wy1;
            const float a = __shfl_sync(0xffffffffu, wgt, l * NP + p);
            const float w00 = a * wx0 * wy0, w10 = a * wx1 * wy0;
            const float w01 = a * wx0 * wy1, w11 = a * wx1 * wy1;

            const bool vx0 = (x0 >= 0) & (x0 < Wl);
            const bool vx1 = (x1 >= 0) & (x1 < Wl);
            const bool vy0 = (y0 >= 0) & (y0 < Hl);
            const bool vy1 = (y1 >= 0) & (y1 < Hl);
            const int cx0 = min(max(x0, 0), Wl - 1);
            const int cx1 = min(max(x1, 0), Wl - 1);
            const int cy0 = min(max(y0, 0), Hl - 1);
            const int cy1 = min(max(y1, 0), Hl - 1);

            if (vy0 & vx0) acc = fmaf(w00, vl[(size_t)(cy0 * Wl + cx0) * CCH], acc);
            if (vy0 & vx1) acc = fmaf(w10, vl[(size_t)(cy0 * Wl + cx1) * CCH], acc);
            if (vy1 & vx0) acc = fmaf(w01, vl[(size_t)(cy1 * Wl + cx0) * CCH], acc);
            if (vy1 & vx1) acc = fmaf(w11, vl[(size_t)(cy1 * Wl + cx1) * CCH], acc);
        }
    }
    const int c = h * DH + lane;
    store_h1pair(out2 + (size_t)t * 2 * CCH + c, CCH, acc);
}

// ---------------------------------------------------------------------------
// LayerNorm over C=256 of (a+b): warp per row. Optional fp16-pair output.
// ---------------------------------------------------------------------------
__global__ void ln_kernel(const float* __restrict__ a, const float* __restrict__ b,
                          const float* __restrict__ g, const float* __restrict__ be,
                          float* __restrict__ out, __half* __restrict__ out2,
                          int rows) {
    const int row = blockIdx.x * (blockDim.x >> 5) + (threadIdx.x >> 5);
    const int lane = threadIdx.x & 31;
    if (row >= rows) return;

    const float* pa = a + (size_t)row * CCH;
    const float* pb = b + (size_t)row * CCH;
    float v[8];
    float s = 0.f;
    #pragma unroll
    for (int j = 0; j < 8; j++) {
        int c = lane + 32 * j;
        v[j] = pa[c] + pb[c];
        s += v[j];
    }
    #pragma unroll
    for (int o = 16; o > 0; o >>= 1) s += __shfl_xor_sync(0xffffffffu, s, o);
    const float mean = s * (1.f / CCH);
    float s2 = 0.f;
    #pragma unroll
    for (int j = 0; j < 8; j++) { float d = v[j] - mean; s2 += d * d; }
    #pragma unroll
    for (int o = 16; o > 0; o >>= 1) s2 += __shfl_xor_sync(0xffffffffu, s2, o);
    const float inv = rsqrtf(s2 * (1.f / CCH) + LN_EPS);

    #pragma unroll
    for (int j = 0; j < 8; j++) {
        int c = lane + 32 * j;
        float y = (v[j] - mean) * inv * g[c] + be[c];
        if (out)  out[(size_t)row * CCH + c] = y;
        if (out2) store_h1pair(out2 + (size_t)row * 2 * CCH + c, CCH, y);
    }
}

// ---------------------------------------------------------------------------
// launch
// ---------------------------------------------------------------------------
extern "C" void kernel_launch(void* const* d_in, const int* in_sizes, int n_in,
                              void* d_out, int out_size) {
    const float* src   = (const float*)d_in[0];
    const float* pos   = (const float*)d_in[1];
    const float* refp  = (const float*)d_in[2];
    const float* w_off  = (const float*)d_in[6];
    const float* b_off  = (const float*)d_in[7];
    const float* w_attn = (const float*)d_in[8];
    const float* b_attn = (const float*)d_in[9];
    const float* w_val  = (const float*)d_in[10];
    const float* b_val  = (const float*)d_in[11];
    const float* w_out  = (const float*)d_in[12];
    const float* b_out  = (const float*)d_in[13];
    const float* g1     = (const float*)d_in[14];
    const float* be1    = (const float*)d_in[15];
    const float* w1     = (const float*)d_in[16];
    const float* b1     = (const float*)d_in[17];
    const float* w2     = (const float*)d_in[18];
    const float* b2     = (const float*)d_in[19];
    const float* g2     = (const float*)d_in[20];
    const float* be2    = (const float*)d_in[21];
    float* out = (float*)d_out;

    __half *p_q2, *p_src2, *p_msda2, *p_x2, *p_h2;
    __half *p_woffh, *p_wattnh, *p_wvalh, *p_wouth, *p_w1h, *p_w2h;
    float *p_off, *p_aw, *p_val, *p_attn, *p_x, *p_ffn;
    cudaGetSymbolAddress((void**)&p_q2,    g_q2);
    cudaGetSymbolAddress((void**)&p_src2,  g_src2);
    cudaGetSymbolAddress((void**)&p_msda2, g_msda2);
    cudaGetSymbolAddress((void**)&p_x2,    g_x2);
    cudaGetSymbolAddress((void**)&p_h2,    g_h2);
    cudaGetSymbolAddress((void**)&p_woffh, g_woffh);
    cudaGetSymbolAddress((void**)&p_wattnh,g_wattnh);
    cudaGetSymbolAddress((void**)&p_wvalh, g_wvalh);
    cudaGetSymbolAddress((void**)&p_wouth, g_wouth);
    cudaGetSymbolAddress((void**)&p_w1h,   g_w1h);
    cudaGetSymbolAddress((void**)&p_w2h,   g_w2h);
    cudaGetSymbolAddress((void**)&p_off,   g_off);
    cudaGetSymbolAddress((void**)&p_aw,    g_aw);
    cudaGetSymbolAddress((void**)&p_val,   g_val);
    cudaGetSymbolAddress((void**)&p_attn,  g_attn);
    cudaGetSymbolAddress((void**)&p_x,     g_x);
    cudaGetSymbolAddress((void**)&p_ffn,   g_ffn);

    const int M = NTOK;  // 21760 = 340 * 64
    const dim3 blk(256);

    const int SM3 = NST * STAGE_SZ;  // 3 * 32768 = 98304
    cudaFuncSetAttribute(proj_gemm,    cudaFuncAttributeMaxDynamicSharedMemorySize, SM3);
    cudaFuncSetAttribute(mma_gemm<0>,  cudaFuncAttributeMaxDynamicSharedMemorySize, SM3);
    cudaFuncSetAttribute(mma_gemm<1>,  cudaFuncAttributeMaxDynamicSharedMemorySize, SM3);

    // weight conversions (tiled transpose, fp16 single)
    wth_kernel<<<dim3(CCH / 32, CCH / 32), dim3(32, 8)>>>(w_off,  p_woffh,  CCH, CCH);
    wth_kernel<<<dim3(128 / 32, CCH / 32), dim3(32, 8)>>>(w_attn, p_wattnh, CCH, 128);
    wth_kernel<<<dim3(CCH / 32, CCH / 32), dim3(32, 8)>>>(w_val,  p_wvalh,  CCH, CCH);
    wth_kernel<<<dim3(CCH / 32, CCH / 32), dim3(32, 8)>>>(w_out,  p_wouth,  CCH, CCH);
    wth_kernel<<<dim3(DFF / 32, CCH / 32), dim3(32, 8)>>>(w1,     p_w1h,    CCH, DFF);
    wth_kernel<<<dim3(CCH / 32, DFF / 32), dim3(32, 8)>>>(w2,     p_w2h,    DFF, CCH);

    // q2 = pair(src+pos), src2 = pair(src) in one kernel
    {
        int n2 = NTOK * CCH / 2;
        act_pair_kernel<<<(n2 + 255) / 256, blk>>>(src, pos, p_q2, p_src2, n2);
    }

    // fused projections: off / logits / value   (1700 CTAs)
    proj_gemm<<<dim3(5, M / 64), blk, SM3>>>(p_q2, p_src2, p_woffh, p_wattnh, p_wvalh,
                                             b_off, b_attn, b_val, p_off, p_aw, p_val);
    // MSDA gather (softmax fused), token-major CTA map
    msda_kernel<<<NTOK, blk>>>(p_val, p_off, p_aw, refp, p_msda2);
    // attn_out = msda @ w_out + b_out   (680 CTAs)
    mma_gemm<0><<<dim3(2, M / 64), blk, SM3>>>(p_msda2, p_wouth, b_out, p_attn, nullptr, CCH, CCH);
    // x = LN(src + attn_out) -> fp32 + fp16 pair
    ln_kernel<<<(NTOK + 7) / 8, blk>>>(src, p_attn, g1, be1, p_x, p_x2, NTOK);
    // h = relu(x @ w1 + b1) -> fp16 pair   (2720 CTAs)
    mma_gemm<1><<<dim3(8, M / 64), blk, SM3>>>(p_x2, p_w1h, b1, nullptr, p_h2, DFF, CCH);
    // ffn = h @ w2 + b2   (680 CTAs)
    mma_gemm<0><<<dim3(2, M / 64), blk, SM3>>>(p_h2, p_w2h, b2, p_ffn, nullptr, CCH, DFF);
    // out = LN(x + ffn)
    ln_kernel<<<(NTOK + 7) / 8, blk>>>(p_x, p_ffn, g2, be2, out, nullptr, NTOK);
}

// round 8
// speedup vs baseline: 3.3030x; 1.2205x over previous
#include <cuda_runtime.h>
#include <cuda_fp16.h>
#include <math.h>

// Problem constants
#define NB   4
#define LEN  5440
#define NTOK (NB * LEN)          // 21760
#define CCH  256
#define NH   8
#define DH   32
#define NL   4
#define NP   4
#define DFF  1024
#define LN_EPS 1e-5f

// ---------------------------------------------------------------------------
// Scratch. Activations and weights as SINGLE fp16 (A error ~2^-12,
// B error ~2^-12; fp32 accumulate). Weights transposed [N][K].
// ---------------------------------------------------------------------------
__device__ __half g_q1   [NTOK * CCH];
__device__ __half g_src1 [NTOK * CCH];
__device__ __half g_msda1[NTOK * CCH];
__device__ __half g_x1   [NTOK * CCH];
__device__ __half g_h1   [NTOK * DFF];

__device__ float g_off [NTOK * CCH];
__device__ float g_aw  [NTOK * 128];
__device__ float g_val [NTOK * CCH];
__device__ float g_attn[NTOK * CCH];
__device__ float g_x   [NTOK * CCH];
__device__ float g_ffn [NTOK * CCH];

__device__ __half g_woffh [CCH * CCH];
__device__ __half g_wattnh[128 * CCH];
__device__ __half g_wvalh [CCH * CCH];
__device__ __half g_wouth [CCH * CCH];
__device__ __half g_w1h   [DFF * CCH];
__device__ __half g_w2h   [CCH * DFF];

// ---------------------------------------------------------------------------
// helpers
// ---------------------------------------------------------------------------
__device__ __forceinline__ unsigned smem_u32(const void* p) {
    unsigned a;
    asm("{ .reg .u64 t; cvta.to.shared.u64 t, %1; cvt.u32.u64 %0, t; }" : "=r"(a) : "l"(p));
    return a;
}

__device__ __forceinline__ void cp_async16(unsigned dst, const void* src) {
    asm volatile("cp.async.cg.shared.global [%0], [%1], 16;\n" :: "r"(dst), "l"(src));
}
__device__ __forceinline__ void cp_commit() {
    asm volatile("cp.async.commit_group;\n" ::: "memory");
}
template<int N>
__device__ __forceinline__ void cp_wait() {
    asm volatile("cp.async.wait_group %0;\n" :: "n"(N) : "memory");
}

__device__ __forceinline__ void ldm4(unsigned& r0, unsigned& r1, unsigned& r2, unsigned& r3,
                                     unsigned a) {
    asm volatile("ldmatrix.sync.aligned.m8n8.x4.shared.b16 {%0,%1,%2,%3}, [%4];"
                 : "=r"(r0), "=r"(r1), "=r"(r2), "=r"(r3) : "r"(a));
}

__device__ __forceinline__ void mma_f16(float c[4],
                                        unsigned a0, unsigned a1, unsigned a2, unsigned a3,
                                        unsigned b0, unsigned b1) {
    asm volatile(
        "mma.sync.aligned.m16n8k16.row.col.f32.f16.f16.f32 "
        "{%0,%1,%2,%3},{%4,%5,%6,%7},{%8,%9},{%0,%1,%2,%3};"
        : "+f"(c[0]), "+f"(c[1]), "+f"(c[2]), "+f"(c[3])
        : "r"(a0), "r"(a1), "r"(a2), "r"(a3), "r"(b0), "r"(b1));
}

// ---------------------------------------------------------------------------
// GEMM. BM=64, BN=128. 256 threads (8 warps: 2m x 4n). NST=4 stages.
// Stage: A (64x128B) + B (128x128B) = 24 KB. Single MMA pass per k16.
// OUT_MODE 0: fp32 out. 1: relu + fp16 out (row stride N).
// Cf/C2/bias pre-offset by caller.
// ---------------------------------------------------------------------------
#define NST 4
#define GBM 64
#define A_BYTES (GBM * 128)
#define STAGE_SZ ((GBM + 128) * 128)   // 24576

__device__ __forceinline__ void gemm_load_stage(unsigned sb, int stage,
                                                const __half* A, const __half* B,
                                                int K, int kt, int tid) {
    const unsigned abase = sb + stage * STAGE_SZ;
    const unsigned bbase = abase + A_BYTES;
    const __half* ag = A + kt * 64;
    const __half* bg = B + kt * 64;
    #pragma unroll
    for (int i = 0; i < 2; i++) {            // 64 rows x 8 chunks / 256 thr
        int id = tid + i * 256;
        int r = id >> 3, c = id & 7;
        unsigned off = (unsigned)(r * 128 + ((c ^ (r & 7)) << 4));
        cp_async16(abase + off, ag + (size_t)r * K + c * 8);
    }
    #pragma unroll
    for (int i = 0; i < 4; i++) {            // 128 rows
        int id = tid + i * 256;
        int r = id >> 3, c = id & 7;
        unsigned off = (unsigned)(r * 128 + ((c ^ (r & 7)) << 4));
        cp_async16(bbase + off, bg + (size_t)r * K + c * 8);
    }
    cp_commit();
}

template<int OUT_MODE>
__device__ __forceinline__ void gemm_body(const __half* A, const __half* B,
                                          const float* bias, float* Cf, __half* C2,
                                          int N, int K, int row_base, char* smem) {
    const unsigned sb = smem_u32(smem);
    const int tid = threadIdx.x;
    const int warp = tid >> 5, lane = tid & 31;
    const int wm = warp & 1, wn = warp >> 1;
    const int KT = K >> 6;

    float acc[2][4][4];
    #pragma unroll
    for (int i = 0; i < 2; i++)
        #pragma unroll
        for (int j = 0; j < 4; j++)
            #pragma unroll
            for (int r = 0; r < 4; r++) acc[i][j][r] = 0.f;

    #pragma unroll
    for (int s = 0; s < NST - 1; s++) {
        if (s < KT) gemm_load_stage(sb, s, A, B, K, s, tid);
        else        cp_commit();
    }

    const int a_row  = (lane & 15);
    const int a_csel = (lane >> 4);
    const int b_rsel = ((lane >> 4) << 3) + (lane & 7);
    const int b_csel = ((lane >> 3) & 1);

    for (int kt = 0; kt < KT; kt++) {
        const int stage = kt % NST;
        cp_wait<NST - 2>();
        __syncthreads();
        if (kt + NST - 1 < KT)
            gemm_load_stage(sb, (kt + NST - 1) % NST, A, B, K, kt + NST - 1, tid);
        else
            cp_commit();

        const unsigned ab = sb + stage * STAGE_SZ;
        const unsigned bb = ab + A_BYTES;

        #pragma unroll
        for (int kk = 0; kk < 4; kk++) {
            const int c = kk * 2;
            unsigned af[2][4], bf[2][4];
            #pragma unroll
            for (int mi = 0; mi < 2; mi++) {
                int row = wm * 32 + mi * 16 + a_row;
                unsigned so = (unsigned)(row * 128 + (((c + a_csel) ^ (row & 7)) << 4));
                ldm4(af[mi][0], af[mi][1], af[mi][2], af[mi][3], ab + so);
            }
            #pragma unroll
            for (int nj2 = 0; nj2 < 2; nj2++) {
                int nrow = wn * 32 + nj2 * 16 + b_rsel;
                unsigned so = (unsigned)(nrow * 128 + (((c + b_csel) ^ (nrow & 7)) << 4));
                ldm4(bf[nj2][0], bf[nj2][1], bf[nj2][2], bf[nj2][3], bb + so);
            }
            #pragma unroll
            for (int mi = 0; mi < 2; mi++)
                #pragma unroll
                for (int nj = 0; nj < 4; nj++) {
                    const unsigned* b = bf[nj >> 1];
                    unsigned b0 = (nj & 1) ? b[2] : b[0];
                    unsigned b1 = (nj & 1) ? b[3] : b[1];
                    mma_f16(acc[mi][nj], af[mi][0], af[mi][1], af[mi][2], af[mi][3], b0, b1);
                }
        }
    }

    // epilogue
    const int col0 = wn * 32 + (lane & 3) * 2;
    #pragma unroll
    for (int mi = 0; mi < 2; mi++) {
        int row = row_base + wm * 32 + mi * 16 + (lane >> 2);
        #pragma unroll
        for (int nj = 0; nj < 4; nj++) {
            int col = col0 + nj * 8;
            float b0v = bias[col], b1v = bias[col + 1];
            float v00 = acc[mi][nj][0] + b0v, v01 = acc[mi][nj][1] + b1v;
            float v10 = acc[mi][nj][2] + b0v, v11 = acc[mi][nj][3] + b1v;
            if (OUT_MODE == 0) {
                *(float2*)(Cf + (size_t)row * N + col)       = make_float2(v00, v01);
                *(float2*)(Cf + (size_t)(row + 8) * N + col) = make_float2(v10, v11);
            } else {
                v00 = fmaxf(v00, 0.f); v01 = fmaxf(v01, 0.f);
                v10 = fmaxf(v10, 0.f); v11 = fmaxf(v11, 0.f);
                *(__half2*)(C2 + (size_t)row * N + col)       = __floats2half2_rn(v00, v01);
                *(__half2*)(C2 + (size_t)(row + 8) * N + col) = __floats2half2_rn(v10, v11);
            }
        }
    }
}

template<int OUT_MODE>
__global__ __launch_bounds__(256, 2)
void mma_gemm(const __half* __restrict__ A, const __half* __restrict__ Bt,
              const float* __restrict__ bias, float* __restrict__ Cf,
              __half* __restrict__ C2, int N, int K) {
    extern __shared__ __align__(1024) char smem[];
    const int bx = blockIdx.x, by = blockIdx.y;
    gemm_body<OUT_MODE>(A + (size_t)by * GBM * K,
                        Bt + (size_t)bx * 128 * (size_t)K,
                        bias + bx * 128,
                        Cf ? Cf + bx * 128 : nullptr,
                        C2 ? C2 + bx * 128 : nullptr,
                        N, K, by * GBM, smem);
}

// fused projection GEMM: bx selects {off0, off1, logits, val0, val1}
__global__ __launch_bounds__(256, 2)
void proj_gemm(const __half* __restrict__ q1, const __half* __restrict__ src1,
               const __half* __restrict__ woffh, const __half* __restrict__ wattnh,
               const __half* __restrict__ wvalh,
               const float* __restrict__ b_off, const float* __restrict__ b_attn,
               const float* __restrict__ b_val,
               float* __restrict__ c_off, float* __restrict__ c_aw, float* __restrict__ c_val) {
    extern __shared__ __align__(1024) char smem[];
    const int bx = blockIdx.x, by = blockIdx.y;
    const int K = CCH;

    const __half* A;
    const __half* B;
    const float* bias;
    float* C;
    int N;
    if (bx < 2) {
        A = q1; B = woffh + (size_t)bx * 128 * K; bias = b_off + bx * 128;
        C = c_off + bx * 128; N = CCH;
    } else if (bx == 2) {
        A = q1; B = wattnh; bias = b_attn; C = c_aw; N = 128;
    } else {
        int s = bx - 3;
        A = src1; B = wvalh + (size_t)s * 128 * K; bias = b_val + s * 128;
        C = c_val + s * 128; N = CCH;
    }
    gemm_body<0>(A + (size_t)by * GBM * K, B, bias, C, nullptr, N, K, by * GBM, smem);
}

// ---------------------------------------------------------------------------
// fused activation conversion: q1 = h(src+pos), src1 = h(src)
// ---------------------------------------------------------------------------
__global__ void act_h_kernel(const float* __restrict__ src, const float* __restrict__ pos,
                             __half* __restrict__ q1, __half* __restrict__ s1, int n2) {
    int i = blockIdx.x * blockDim.x + threadIdx.x;
    if (i >= n2) return;
    float2 s = ((const float2*)src)[i];
    float2 p = ((const float2*)pos)[i];
    ((__half2*)s1)[i] = __floats2half2_rn(s.x, s.y);
    ((__half2*)q1)[i] = __floats2half2_rn(s.x + p.x, s.y + p.y);
}

// ---------------------------------------------------------------------------
// merged weight transpose: all 6 weights in one launch.
// linear tile id -> (weight, tile). W[K][N] fp32 -> Bt[N][K] fp16.
// tile bases: off 0(64), attn 64(32), val 96(64), out 160(64), w1 224(256), w2 480(256)
// ---------------------------------------------------------------------------
__global__ void wtall_kernel(const float* __restrict__ w_off, const float* __restrict__ w_attn,
                             const float* __restrict__ w_val, const float* __restrict__ w_out,
                             const float* __restrict__ w1,    const float* __restrict__ w2,
                             __half* __restrict__ d_off, __half* __restrict__ d_attn,
                             __half* __restrict__ d_val, __half* __restrict__ d_out,
                             __half* __restrict__ d_w1,  __half* __restrict__ d_w2) {
    __shared__ float tile[32][33];
    int id = blockIdx.x;
    const float* W; __half* Bt; int K, N, nx, local;
    if      (id < 64)  { W = w_off;  Bt = d_off;  K = CCH; N = CCH; nx = 8;  local = id; }
    else if (id < 96)  { W = w_attn; Bt = d_attn; K = CCH; N = 128; nx = 4;  local = id - 64; }
    else if (id < 160) { W = w_val;  Bt = d_val;  K = CCH; N = CCH; nx = 8;  local = id - 96; }
    else if (id < 224) { W = w_out;  Bt = d_out;  K = CCH; N = CCH; nx = 8;  local = id - 160; }
    else if (id < 480) { W = w1;     Bt = d_w1;   K = CCH; N = DFF; nx = 32; local = id - 224; }
    else               { W = w2;     Bt = d_w2;   K = DFF; N = CCH; nx = 8;  local = id - 480; }
    const int n0 = (local % nx) * 32, k0 = (local / nx) * 32;
    const int tx = threadIdx.x, ty = threadIdx.y;
    #pragma unroll
    for (int i = 0; i < 4; i++) {
        int k = ty + i * 8;
        tile[k][tx] = W[(size_t)(k0 + k) * N + n0 + tx];
    }
    __syncthreads();
    #pragma unroll
    for (int i = 0; i < 4; i++) {
        int n = ty + i * 8;
        Bt[(size_t)(n0 + n) * K + k0 + tx] = __float2half_rn(tile[tx][n]);
    }
}

// ---------------------------------------------------------------------------
// MSDA with fused softmax. CTA = 8 consecutive tokens x ONE head.
// warp = one (token, head); lane = channel. Output single fp16.
// ---------------------------------------------------------------------------
__global__ void msda_kernel(const float* __restrict__ value,
                            const float* __restrict__ off,
                            const float* __restrict__ logits,
                            const float* __restrict__ refp,
                            __half* __restrict__ out1) {
    const int warp = threadIdx.x >> 5;
    const int lane = threadIdx.x & 31;
    const int h  = blockIdx.x & (NH - 1);
    const int t  = (blockIdx.x >> 3) * 8 + warp;
    const int b  = t / LEN;

    const float* lg = logits + (size_t)t * 128 + h * 16;
    float l0 = lg[lane & 15];
    float mx = l0;
    #pragma unroll
    for (int o = 1; o < 16; o <<= 1) mx = fmaxf(mx, __shfl_xor_sync(0xffffffffu, mx, o));
    float e = __expf(l0 - mx);
    float s = e;
    #pragma unroll
    for (int o = 1; o < 16; o <<= 1) s += __shfl_xor_sync(0xffffffffu, s, o);
    const float wgt = e / s;

    const float* off_row = off + (size_t)t * CCH + h * (NL * NP * 2);
    const float* ref_row = refp + (size_t)t * (NL * 2);
    const float* vbase   = value + ((size_t)b * LEN) * CCH + h * DH + lane;

    const int dims[NL]   = {64, 32, 16, 8};
    const int starts[NL] = {0, 4096, 5120, 5376};

    float acc = 0.f;

    #pragma unroll
    for (int l = 0; l < NL; l++) {
        const int Wl = dims[l], Hl = dims[l];
        const float fW = (float)Wl, fH = (float)Hl;
        const float rx = ref_row[2 * l];
        const float ry = ref_row[2 * l + 1];
        const float* vl = vbase + (size_t)starts[l] * CCH;

        #pragma unroll
        for (int p = 0; p < NP; p++) {
            const float ox = off_row[(l * NP + p) * 2];
            const float oy = off_row[(l * NP + p) * 2 + 1];
            const float px = (rx + ox / fW) * fW - 0.5f;
            const float py = (ry + oy / fH) * fH - 0.5f;
            const float fx = floorf(px), fy = floorf(py);
            const int x0 = (int)fx, y0 = (int)fy;
            const int x1 = x0 + 1,  y1 = y0 + 1;
            const float wx1 = px - fx, wy1 = py - fy;
            const float wx0 = 1.f - wx1, wy0 = 1.f - wy1;
            const float a = __shfl_sync(0xffffffffu, wgt, l * NP + p);
            const float w00 = a * wx0 * wy0, w10 = a * wx1 * wy0;
            const float w01 = a * wx0 * wy1, w11 = a * wx1 * wy1;

            const bool vx0 = (x0 >= 0) & (x0 < Wl);
            const bool vx1 = (x1 >= 0) & (x1 < Wl);
            const bool vy0 = (y0 >= 0) & (y0 < Hl);
            const bool vy1 = (y1 >= 0) & (y1 < Hl);
            const int cx0 = min(max(x0, 0), Wl - 1);
            const int cx1 = min(max(x1, 0), Wl - 1);
            const int cy0 = min(max(y0, 0), Hl - 1);
            const int cy1 = min(max(y1, 0), Hl - 1);

            if (vy0 & vx0) acc = fmaf(w00, vl[(size_t)(cy0 * Wl + cx0) * CCH], acc);
            if (vy0 & vx1) acc = fmaf(w10, vl[(size_t)(cy0 * Wl + cx1) * CCH], acc);
            if (vy1 & vx0) acc = fmaf(w01, vl[(size_t)(cy1 * Wl + cx0) * CCH], acc);
            if (vy1 & vx1) acc = fmaf(w11, vl[(size_t)(cy1 * Wl + cx1) * CCH], acc);
        }
    }
    out1[(size_t)t * CCH + h * DH + lane] = __float2half_rn(acc);
}

// ---------------------------------------------------------------------------
// LayerNorm over C=256 of (a+b): warp per row. Optional fp16 output.
// ---------------------------------------------------------------------------
__global__ void ln_kernel(const float* __restrict__ a, const float* __restrict__ b,
                          const float* __restrict__ g, const float* __restrict__ be,
                          float* __restrict__ out, __half* __restrict__ out1,
                          int rows) {
    const int row = blockIdx.x * (blockDim.x >> 5) + (threadIdx.x >> 5);
    const int lane = threadIdx.x & 31;
    if (row >= rows) return;

    const float* pa = a + (size_t)row * CCH;
    const float* pb = b + (size_t)row * CCH;
    float v[8];
    float s = 0.f;
    #pragma unroll
    for (int j = 0; j < 8; j++) {
        int c = lane + 32 * j;
        v[j] = pa[c] + pb[c];
        s += v[j];
    }
    #pragma unroll
    for (int o = 16; o > 0; o >>= 1) s += __shfl_xor_sync(0xffffffffu, s, o);
    const float mean = s * (1.f / CCH);
    float s2 = 0.f;
    #pragma unroll
    for (int j = 0; j < 8; j++) { float d = v[j] - mean; s2 += d * d; }
    #pragma unroll
    for (int o = 16; o > 0; o >>= 1) s2 += __shfl_xor_sync(0xffffffffu, s2, o);
    const float inv = rsqrtf(s2 * (1.f / CCH) + LN_EPS);

    #pragma unroll
    for (int j = 0; j < 8; j++) {
        int c = lane + 32 * j;
        float y = (v[j] - mean) * inv * g[c] + be[c];
        if (out)  out[(size_t)row * CCH + c] = y;
        if (out1) out1[(size_t)row * CCH + c] = __float2half_rn(y);
    }
}

// ---------------------------------------------------------------------------
// launch
// ---------------------------------------------------------------------------
extern "C" void kernel_launch(void* const* d_in, const int* in_sizes, int n_in,
                              void* d_out, int out_size) {
    const float* src   = (const float*)d_in[0];
    const float* pos   = (const float*)d_in[1];
    const float* refp  = (const float*)d_in[2];
    const float* w_off  = (const float*)d_in[6];
    const float* b_off  = (const float*)d_in[7];
    const float* w_attn = (const float*)d_in[8];
    const float* b_attn = (const float*)d_in[9];
    const float* w_val  = (const float*)d_in[10];
    const float* b_val  = (const float*)d_in[11];
    const float* w_out  = (const float*)d_in[12];
    const float* b_out  = (const float*)d_in[13];
    const float* g1     = (const float*)d_in[14];
    const float* be1    = (const float*)d_in[15];
    const float* w1     = (const float*)d_in[16];
    const float* b1     = (const float*)d_in[17];
    const float* w2     = (const float*)d_in[18];
    const float* b2     = (const float*)d_in[19];
    const float* g2     = (const float*)d_in[20];
    const float* be2    = (const float*)d_in[21];
    float* out = (float*)d_out;

    __half *p_q1, *p_src1, *p_msda1, *p_x1, *p_h1;
    __half *p_woffh, *p_wattnh, *p_wvalh, *p_wouth, *p_w1h, *p_w2h;
    float *p_off, *p_aw, *p_val, *p_attn, *p_x, *p_ffn;
    cudaGetSymbolAddress((void**)&p_q1,    g_q1);
    cudaGetSymbolAddress((void**)&p_src1,  g_src1);
    cudaGetSymbolAddress((void**)&p_msda1, g_msda1);
    cudaGetSymbolAddress((void**)&p_x1,    g_x1);
    cudaGetSymbolAddress((void**)&p_h1,    g_h1);
    cudaGetSymbolAddress((void**)&p_woffh, g_woffh);
    cudaGetSymbolAddress((void**)&p_wattnh,g_wattnh);
    cudaGetSymbolAddress((void**)&p_wvalh, g_wvalh);
    cudaGetSymbolAddress((void**)&p_wouth, g_wouth);
    cudaGetSymbolAddress((void**)&p_w1h,   g_w1h);
    cudaGetSymbolAddress((void**)&p_w2h,   g_w2h);
    cudaGetSymbolAddress((void**)&p_off,   g_off);
    cudaGetSymbolAddress((void**)&p_aw,    g_aw);
    cudaGetSymbolAddress((void**)&p_val,   g_val);
    cudaGetSymbolAddress((void**)&p_attn,  g_attn);
    cudaGetSymbolAddress((void**)&p_x,     g_x);
    cudaGetSymbolAddress((void**)&p_ffn,   g_ffn);

    const int M = NTOK;  // 21760 = 340 * 64
    const dim3 blk(256);

    const int SM4 = NST * STAGE_SZ;  // 4 * 24576 = 98304
    cudaFuncSetAttribute(proj_gemm,    cudaFuncAttributeMaxDynamicSharedMemorySize, SM4);
    cudaFuncSetAttribute(mma_gemm<0>,  cudaFuncAttributeMaxDynamicSharedMemorySize, SM4);
    cudaFuncSetAttribute(mma_gemm<1>,  cudaFuncAttributeMaxDynamicSharedMemorySize, SM4);

    // all weight transposes in one launch (736 tiles)
    wtall_kernel<<<736, dim3(32, 8)>>>(w_off, w_attn, w_val, w_out, w1, w2,
                                       p_woffh, p_wattnh, p_wvalh, p_wouth, p_w1h, p_w2h);

    // q1 = h(src+pos), src1 = h(src)
    {
        int n2 = NTOK * CCH / 2;
        act_h_kernel<<<(n2 + 255) / 256, blk>>>(src, pos, p_q1, p_src1, n2);
    }

    // fused projections: off / logits / value   (1700 CTAs)
    proj_gemm<<<dim3(5, M / 64), blk, SM4>>>(p_q1, p_src1, p_woffh, p_wattnh, p_wvalh,
                                             b_off, b_attn, b_val, p_off, p_aw, p_val);
    // MSDA gather (softmax fused), token-major CTA map
    msda_kernel<<<NTOK, blk>>>(p_val, p_off, p_aw, refp, p_msda1);
    // attn_out = msda @ w_out + b_out   (680 CTAs)
    mma_gemm<0><<<dim3(2, M / 64), blk, SM4>>>(p_msda1, p_wouth, b_out, p_attn, nullptr, CCH, CCH);
    // x = LN(src + attn_out) -> fp32 + fp16
    ln_kernel<<<(NTOK + 7) / 8, blk>>>(src, p_attn, g1, be1, p_x, p_x1, NTOK);
    // h = relu(x @ w1 + b1) -> fp16   (2720 CTAs)
    mma_gemm<1><<<dim3(8, M / 64), blk, SM4>>>(p_x1, p_w1h, b1, nullptr, p_h1, DFF, CCH);
    // ffn = h @ w2 + b2   (680 CTAs)
    mma_gemm<0><<<dim3(2, M / 64), blk, SM4>>>(p_h1, p_w2h, b2, p_ffn, nullptr, CCH, DFF);
    // out = LN(x + ffn)
    ln_kernel<<<(NTOK + 7) / 8, blk>>>(p_x, p_ffn, g2, be2, out, nullptr, NTOK);
}

// round 9
// speedup vs baseline: 4.0802x; 1.2353x over previous
#include <cuda_runtime.h>
#include <cuda_fp16.h>
#include <math.h>

// Problem constants
#define NB   4
#define LEN  5440
#define NTOK (NB * LEN)          // 21760
#define CCH  256
#define NH   8
#define DH   32
#define NL   4
#define NP   4
#define DFF  1024
#define LN_EPS 1e-5f

// Padded value layout: per level pad 2 on all sides, fp16.
// dims (Hl+4)x(Wl+4): 68^2=4624, 36^2=1296, 20^2=400, 12^2=144 ; total 6464
#define PBATCH 6464
#define PB0 0
#define PB1 4624
#define PB2 5920
#define PB3 6320

// ---------------------------------------------------------------------------
// Scratch. Activations/weights single fp16 (fp32 accumulate in MMA).
// ---------------------------------------------------------------------------
__device__ __half g_q1   [NTOK * CCH];
__device__ __half g_src1 [NTOK * CCH];
__device__ __half g_msda1[NTOK * CCH];
__device__ __half g_x1   [NTOK * CCH];
__device__ __half g_h1   [NTOK * DFF];
__device__ __half g_valp [NB * PBATCH * CCH];   // padded fp16 value

__device__ float g_off [NTOK * CCH];
__device__ float g_aw  [NTOK * 128];
__device__ float g_attn[NTOK * CCH];
__device__ float g_x   [NTOK * CCH];
__device__ float g_ffn [NTOK * CCH];

__device__ __half g_woffh [CCH * CCH];
__device__ __half g_wattnh[128 * CCH];
__device__ __half g_wvalh [CCH * CCH];
__device__ __half g_wouth [CCH * CCH];
__device__ __half g_w1h   [DFF * CCH];
__device__ __half g_w2h   [CCH * DFF];

// ---------------------------------------------------------------------------
// helpers
// ---------------------------------------------------------------------------
__device__ __forceinline__ unsigned smem_u32(const void* p) {
    unsigned a;
    asm("{ .reg .u64 t; cvta.to.shared.u64 t, %1; cvt.u32.u64 %0, t; }" : "=r"(a) : "l"(p));
    return a;
}

__device__ __forceinline__ void cp_async16(unsigned dst, const void* src) {
    asm volatile("cp.async.cg.shared.global [%0], [%1], 16;\n" :: "r"(dst), "l"(src));
}
__device__ __forceinline__ void cp_commit() {
    asm volatile("cp.async.commit_group;\n" ::: "memory");
}
template<int N>
__device__ __forceinline__ void cp_wait() {
    asm volatile("cp.async.wait_group %0;\n" :: "n"(N) : "memory");
}

__device__ __forceinline__ void ldm4(unsigned& r0, unsigned& r1, unsigned& r2, unsigned& r3,
                                     unsigned a) {
    asm volatile("ldmatrix.sync.aligned.m8n8.x4.shared.b16 {%0,%1,%2,%3}, [%4];"
                 : "=r"(r0), "=r"(r1), "=r"(r2), "=r"(r3) : "r"(a));
}

__device__ __forceinline__ void mma_f16(float c[4],
                                        unsigned a0, unsigned a1, unsigned a2, unsigned a3,
                                        unsigned b0, unsigned b1) {
    asm volatile(
        "mma.sync.aligned.m16n8k16.row.col.f32.f16.f16.f32 "
        "{%0,%1,%2,%3},{%4,%5,%6,%7},{%8,%9},{%0,%1,%2,%3};"
        : "+f"(c[0]), "+f"(c[1]), "+f"(c[2]), "+f"(c[3])
        : "r"(a0), "r"(a1), "r"(a2), "r"(a3), "r"(b0), "r"(b1));
}

// token -> padded value row base (channel 0)
__device__ __forceinline__ __half* valp_row(__half* Vp, int t) {
    int b = t / LEN;
    int pos = t - b * LEN;
    int base, W4, ys, m, loc;
    if (pos < 4096)      { loc = pos;        base = PB0; W4 = 68; ys = 6; m = 63; }
    else if (pos < 5120) { loc = pos - 4096; base = PB1; W4 = 36; ys = 5; m = 31; }
    else if (pos < 5376) { loc = pos - 5120; base = PB2; W4 = 20; ys = 4; m = 15; }
    else                 { loc = pos - 5376; base = PB3; W4 = 12; ys = 3; m = 7; }
    int y = loc >> ys, x = loc & m;
    return Vp + ((size_t)b * PBATCH + base + (y + 2) * W4 + (x + 2)) * CCH;
}

// ---------------------------------------------------------------------------
// GEMM. BM=64, BN=128. 256 threads (8 warps: 2m x 4n). NST=4 stages.
// OUT_MODE 0: fp32 out (pre-offset). 1: relu + fp16 out (pre-offset, stride N).
// OUT_MODE 2: fp16 into padded value layout (C2 = raw base, col_base = channel).
// ---------------------------------------------------------------------------
#define NST 4
#define GBM 64
#define A_BYTES (GBM * 128)
#define STAGE_SZ ((GBM + 128) * 128)   // 24576

__device__ __forceinline__ void gemm_load_stage(unsigned sb, int stage,
                                                const __half* A, const __half* B,
                                                int K, int kt, int tid) {
    const unsigned abase = sb + stage * STAGE_SZ;
    const unsigned bbase = abase + A_BYTES;
    const __half* ag = A + kt * 64;
    const __half* bg = B + kt * 64;
    #pragma unroll
    for (int i = 0; i < 2; i++) {
        int id = tid + i * 256;
        int r = id >> 3, c = id & 7;
        unsigned off = (unsigned)(r * 128 + ((c ^ (r & 7)) << 4));
        cp_async16(abase + off, ag + (size_t)r * K + c * 8);
    }
    #pragma unroll
    for (int i = 0; i < 4; i++) {
        int id = tid + i * 256;
        int r = id >> 3, c = id & 7;
        unsigned off = (unsigned)(r * 128 + ((c ^ (r & 7)) << 4));
        cp_async16(bbase + off, bg + (size_t)r * K + c * 8);
    }
    cp_commit();
}

template<int OUT_MODE>
__device__ __forceinline__ void gemm_body(const __half* A, const __half* B,
                                          const float* bias, float* Cf, __half* C2,
                                          int N, int K, int row_base, int col_base,
                                          char* smem) {
    const unsigned sb = smem_u32(smem);
    const int tid = threadIdx.x;
    const int warp = tid >> 5, lane = tid & 31;
    const int wm = warp & 1, wn = warp >> 1;
    const int KT = K >> 6;

    float acc[2][4][4];
    #pragma unroll
    for (int i = 0; i < 2; i++)
        #pragma unroll
        for (int j = 0; j < 4; j++)
            #pragma unroll
            for (int r = 0; r < 4; r++) acc[i][j][r] = 0.f;

    #pragma unroll
    for (int s = 0; s < NST - 1; s++) {
        if (s < KT) gemm_load_stage(sb, s, A, B, K, s, tid);
        else        cp_commit();
    }

    const int a_row  = (lane & 15);
    const int a_csel = (lane >> 4);
    const int b_rsel = ((lane >> 4) << 3) + (lane & 7);
    const int b_csel = ((lane >> 3) & 1);

    for (int kt = 0; kt < KT; kt++) {
        const int stage = kt % NST;
        cp_wait<NST - 2>();
        __syncthreads();
        if (kt + NST - 1 < KT)
            gemm_load_stage(sb, (kt + NST - 1) % NST, A, B, K, kt + NST - 1, tid);
        else
            cp_commit();

        const unsigned ab = sb + stage * STAGE_SZ;
        const unsigned bb = ab + A_BYTES;

        #pragma unroll
        for (int kk = 0; kk < 4; kk++) {
            const int c = kk * 2;
            unsigned af[2][4], bf[2][4];
            #pragma unroll
            for (int mi = 0; mi < 2; mi++) {
                int row = wm * 32 + mi * 16 + a_row;
                unsigned so = (unsigned)(row * 128 + (((c + a_csel) ^ (row & 7)) << 4));
                ldm4(af[mi][0], af[mi][1], af[mi][2], af[mi][3], ab + so);
            }
            #pragma unroll
            for (int nj2 = 0; nj2 < 2; nj2++) {
                int nrow = wn * 32 + nj2 * 16 + b_rsel;
                unsigned so = (unsigned)(nrow * 128 + (((c + b_csel) ^ (nrow & 7)) << 4));
                ldm4(bf[nj2][0], bf[nj2][1], bf[nj2][2], bf[nj2][3], bb + so);
            }
            #pragma unroll
            for (int mi = 0; mi < 2; mi++)
                #pragma unroll
                for (int nj = 0; nj < 4; nj++) {
                    const unsigned* b = bf[nj >> 1];
                    unsigned b0 = (nj & 1) ? b[2] : b[0];
                    unsigned b1 = (nj & 1) ? b[3] : b[1];
                    mma_f16(acc[mi][nj], af[mi][0], af[mi][1], af[mi][2], af[mi][3], b0, b1);
                }
        }
    }

    // epilogue
    const int col0 = wn * 32 + (lane & 3) * 2;
    #pragma unroll
    for (int mi = 0; mi < 2; mi++) {
        int row = row_base + wm * 32 + mi * 16 + (lane >> 2);
        __half *p0 = nullptr, *p1 = nullptr;
        if (OUT_MODE == 2) {
            p0 = valp_row(C2, row) + col_base;
            p1 = valp_row(C2, row + 8) + col_base;
        }
        #pragma unroll
        for (int nj = 0; nj < 4; nj++) {
            int col = col0 + nj * 8;
            float b0v = bias[col], b1v = bias[col + 1];
            float v00 = acc[mi][nj][0] + b0v, v01 = acc[mi][nj][1] + b1v;
            float v10 = acc[mi][nj][2] + b0v, v11 = acc[mi][nj][3] + b1v;
            if (OUT_MODE == 0) {
                *(float2*)(Cf + (size_t)row * N + col)       = make_float2(v00, v01);
                *(float2*)(Cf + (size_t)(row + 8) * N + col) = make_float2(v10, v11);
            } else if (OUT_MODE == 1) {
                v00 = fmaxf(v00, 0.f); v01 = fmaxf(v01, 0.f);
                v10 = fmaxf(v10, 0.f); v11 = fmaxf(v11, 0.f);
                *(__half2*)(C2 + (size_t)row * N + col)       = __floats2half2_rn(v00, v01);
                *(__half2*)(C2 + (size_t)(row + 8) * N + col) = __floats2half2_rn(v10, v11);
            } else {
                *(__half2*)(p0 + col) = __floats2half2_rn(v00, v01);
                *(__half2*)(p1 + col) = __floats2half2_rn(v10, v11);
            }
        }
    }
}

template<int OUT_MODE>
__global__ __launch_bounds__(256, 2)
void mma_gemm(const __half* __restrict__ A, const __half* __restrict__ Bt,
              const float* __restrict__ bias, float* __restrict__ Cf,
              __half* __restrict__ C2, int N, int K) {
    extern __shared__ __align__(1024) char smem[];
    const int bx = blockIdx.x, by = blockIdx.y;
    gemm_body<OUT_MODE>(A + (size_t)by * GBM * K,
                        Bt + (size_t)bx * 128 * (size_t)K,
                        bias + bx * 128,
                        Cf ? Cf + bx * 128 : nullptr,
                        C2 ? C2 + bx * 128 : nullptr,
                        N, K, by * GBM, 0, smem);
}

// fused projection GEMM: bx selects {off0, off1, logits, val0, val1}
__global__ __launch_bounds__(256, 2)
void proj_gemm(const __half* __restrict__ q1, const __half* __restrict__ src1,
               const __half* __restrict__ woffh, const __half* __restrict__ wattnh,
               const __half* __restrict__ wvalh,
               const float* __restrict__ b_off, const float* __restrict__ b_attn,
               const float* __restrict__ b_val,
               float* __restrict__ c_off, float* __restrict__ c_aw,
               __half* __restrict__ valp) {
    extern __shared__ __align__(1024) char smem[];
    const int bx = blockIdx.x, by = blockIdx.y;
    const int K = CCH;

    if (bx < 2) {
        gemm_body<0>(q1 + (size_t)by * GBM * K, woffh + (size_t)bx * 128 * K,
                     b_off + bx * 128, c_off + bx * 128, nullptr,
                     CCH, K, by * GBM, 0, smem);
    } else if (bx == 2) {
        gemm_body<0>(q1 + (size_t)by * GBM * K, wattnh,
                     b_attn, c_aw, nullptr,
                     128, K, by * GBM, 0, smem);
    } else {
        int s = bx - 3;
        gemm_body<2>(src1 + (size_t)by * GBM * K, wvalh + (size_t)s * 128 * K,
                     b_val + s * 128, nullptr, valp,
                     CCH, K, by * GBM, s * 128, smem);
    }
}

// ---------------------------------------------------------------------------
// zero-fill padded value buffer (borders must be zero; interior overwritten)
// ---------------------------------------------------------------------------
__global__ void zero_kernel(float4* __restrict__ p, int n) {
    int i = blockIdx.x * blockDim.x + threadIdx.x;
    if (i < n) p[i] = make_float4(0.f, 0.f, 0.f, 0.f);
}

// ---------------------------------------------------------------------------
// fused activation conversion: q1 = h(src+pos), src1 = h(src)
// ---------------------------------------------------------------------------
__global__ void act_h_kernel(const float* __restrict__ src, const float* __restrict__ pos,
                             __half* __restrict__ q1, __half* __restrict__ s1, int n2) {
    int i = blockIdx.x * blockDim.x + threadIdx.x;
    if (i >= n2) return;
    float2 s = ((const float2*)src)[i];
    float2 p = ((const float2*)pos)[i];
    ((__half2*)s1)[i] = __floats2half2_rn(s.x, s.y);
    ((__half2*)q1)[i] = __floats2half2_rn(s.x + p.x, s.y + p.y);
}

// ---------------------------------------------------------------------------
// merged weight transpose: all 6 weights in one launch.
// ---------------------------------------------------------------------------
__global__ void wtall_kernel(const float* __restrict__ w_off, const float* __restrict__ w_attn,
                             const float* __restrict__ w_val, const float* __restrict__ w_out,
                             const float* __restrict__ w1,    const float* __restrict__ w2,
                             __half* __restrict__ d_off, __half* __restrict__ d_attn,
                             __half* __restrict__ d_val, __half* __restrict__ d_out,
                             __half* __restrict__ d_w1,  __half* __restrict__ d_w2) {
    __shared__ float tile[32][33];
    int id = blockIdx.x;
    const float* W; __half* Bt; int K, N, nx, local;
    if      (id < 64)  { W = w_off;  Bt = d_off;  K = CCH; N = CCH; nx = 8;  local = id; }
    else if (id < 96)  { W = w_attn; Bt = d_attn; K = CCH; N = 128; nx = 4;  local = id - 64; }
    else if (id < 160) { W = w_val;  Bt = d_val;  K = CCH; N = CCH; nx = 8;  local = id - 96; }
    else if (id < 224) { W = w_out;  Bt = d_out;  K = CCH; N = CCH; nx = 8;  local = id - 160; }
    else if (id < 480) { W = w1;     Bt = d_w1;   K = CCH; N = DFF; nx = 32; local = id - 224; }
    else               { W = w2;     Bt = d_w2;   K = DFF; N = CCH; nx = 8;  local = id - 480; }
    const int n0 = (local % nx) * 32, k0 = (local / nx) * 32;
    const int tx = threadIdx.x, ty = threadIdx.y;
    #pragma unroll
    for (int i = 0; i < 4; i++) {
        int k = ty + i * 8;
        tile[k][tx] = W[(size_t)(k0 + k) * N + n0 + tx];
    }
    __syncthreads();
    #pragma unroll
    for (int i = 0; i < 4; i++) {
        int n = ty + i * 8;
        Bt[(size_t)(n0 + n) * K + k0 + tx] = __float2half_rn(tile[tx][n]);
    }
}

// ---------------------------------------------------------------------------
// MSDA, padded fp16 value: no validity predicates, single clamp per axis.
// CTA = 8 consecutive tokens x ONE head; warp = (token, head); lane = channel.
// ---------------------------------------------------------------------------
__global__ void msda_kernel(const __half* __restrict__ valp,
                            const float* __restrict__ off,
                            const float* __restrict__ logits,
                            const float* __restrict__ refp,
                            __half* __restrict__ out1) {
    const int warp = threadIdx.x >> 5;
    const int lane = threadIdx.x & 31;
    const int h  = blockIdx.x & (NH - 1);
    const int t  = (blockIdx.x >> 3) * 8 + warp;
    const int b  = t / LEN;

    const float* lg = logits + (size_t)t * 128 + h * 16;
    float l0 = lg[lane & 15];
    float mx = l0;
    #pragma unroll
    for (int o = 1; o < 16; o <<= 1) mx = fmaxf(mx, __shfl_xor_sync(0xffffffffu, mx, o));
    float e = __expf(l0 - mx);
    float s = e;
    #pragma unroll
    for (int o = 1; o < 16; o <<= 1) s += __shfl_xor_sync(0xffffffffu, s, o);
    const float wgt = e / s;

    const float2* off2 = (const float2*)(off + (size_t)t * CCH + h * (NL * NP * 2));
    const float2* ref2 = (const float2*)(refp + (size_t)t * (NL * 2));
    const __half* vbase = valp + ((size_t)b * PBATCH) * CCH + h * DH + lane;

    const int dims[NL]  = {64, 32, 16, 8};
    const int w4s[NL]   = {68, 36, 20, 12};
    const int bases[NL] = {PB0, PB1, PB2, PB3};

    float acc = 0.f;

    #pragma unroll
    for (int l = 0; l < NL; l++) {
        const int Wl = dims[l], W4 = w4s[l];
        const float fW = (float)Wl;
        float2 r = ref2[l];
        const __half* vl = vbase + (size_t)bases[l] * CCH;

        #pragma unroll
        for (int p = 0; p < NP; p++) {
            float2 o = off2[l * NP + p];
            const float px = fmaf(r.x, fW, o.x - 0.5f);
            const float py = fmaf(r.y, fW, o.y - 0.5f);
            const float fx = floorf(px), fy = floorf(py);
            const int x0 = (int)fx, y0 = (int)fy;
            const float wx1 = px - fx, wy1 = py - fy;
            const float wx0 = 1.f - wx1, wy0 = 1.f - wy1;
            const int x0c = min(max(x0, -2), Wl);
            const int y0c = min(max(y0, -2), Wl);
            const float a = __shfl_sync(0xffffffffu, wgt, l * NP + p);
            const float u0 = a * wy0, u1 = a * wy1;
            const int r0 = (y0c + 2) * W4 + (x0c + 2);
            const __half* q = vl + (size_t)r0 * CCH;
            acc = fmaf(u0 * wx0, __half2float(q[0]), acc);
            acc = fmaf(u0 * wx1, __half2float(q[CCH]), acc);
            acc = fmaf(u1 * wx0, __half2float(q[(size_t)W4 * CCH]), acc);
            acc = fmaf(u1 * wx1, __half2float(q[(size_t)(W4 + 1) * CCH]), acc);
        }
    }
    out1[(size_t)t * CCH + h * DH + lane] = __float2half_rn(acc);
}

// ---------------------------------------------------------------------------
// LayerNorm over C=256 of (a+b): warp per row. Optional fp16 output.
// ---------------------------------------------------------------------------
__global__ void ln_kernel(const float* __restrict__ a, const float* __restrict__ b,
                          const float* __restrict__ g, const float* __restrict__ be,
                          float* __restrict__ out, __half* __restrict__ out1,
                          int rows) {
    const int row = blockIdx.x * (blockDim.x >> 5) + (threadIdx.x >> 5);
    const int lane = threadIdx.x & 31;
    if (row >= rows) return;

    const float* pa = a + (size_t)row * CCH;
    const float* pb = b + (size_t)row * CCH;
    float v[8];
    float s = 0.f;
    #pragma unroll
    for (int j = 0; j < 8; j++) {
        int c = lane + 32 * j;
        v[j] = pa[c] + pb[c];
        s += v[j];
    }
    #pragma unroll
    for (int o = 16; o > 0; o >>= 1) s += __shfl_xor_sync(0xffffffffu, s, o);
    const float mean = s * (1.f / CCH);
    float s2 = 0.f;
    #pragma unroll
    for (int j = 0; j < 8; j++) { float d = v[j] - mean; s2 += d * d; }
    #pragma unroll
    for (int o = 16; o > 0; o >>= 1) s2 += __shfl_xor_sync(0xffffffffu, s2, o);
    const float inv = rsqrtf(s2 * (1.f / CCH) + LN_EPS);

    #pragma unroll
    for (int j = 0; j < 8; j++) {
        int c = lane + 32 * j;
        float y = (v[j] - mean) * inv * g[c] + be[c];
        if (out)  out[(size_t)row * CCH + c] = y;
        if (out1) out1[(size_t)row * CCH + c] = __float2half_rn(y);
    }
}

// ---------------------------------------------------------------------------
// launch
// ---------------------------------------------------------------------------
extern "C" void kernel_launch(void* const* d_in, const int* in_sizes, int n_in,
                              void* d_out, int out_size) {
    const float* src   = (const float*)d_in[0];
    const float* pos   = (const float*)d_in[1];
    const float* refp  = (const float*)d_in[2];
    const float* w_off  = (const float*)d_in[6];
    const float* b_off  = (const float*)d_in[7];
    const float* w_attn = (const float*)d_in[8];
    const float* b_attn = (const float*)d_in[9];
    const float* w_val  = (const float*)d_in[10];
    const float* b_val  = (const float*)d_in[11];
    const float* w_out  = (const float*)d_in[12];
    const float* b_out  = (const float*)d_in[13];
    const float* g1     = (const float*)d_in[14];
    const float* be1    = (const float*)d_in[15];
    const float* w1     = (const float*)d_in[16];
    const float* b1     = (const float*)d_in[17];
    const float* w2     = (const float*)d_in[18];
    const float* b2     = (const float*)d_in[19];
    const float* g2     = (const float*)d_in[20];
    const float* be2    = (const float*)d_in[21];
    float* out = (float*)d_out;

    __half *p_q1, *p_src1, *p_msda1, *p_x1, *p_h1, *p_valp;
    __half *p_woffh, *p_wattnh, *p_wvalh, *p_wouth, *p_w1h, *p_w2h;
    float *p_off, *p_aw, *p_attn, *p_x, *p_ffn;
    cudaGetSymbolAddress((void**)&p_q1,    g_q1);
    cudaGetSymbolAddress((void**)&p_src1,  g_src1);
    cudaGetSymbolAddress((void**)&p_msda1, g_msda1);
    cudaGetSymbolAddress((void**)&p_x1,    g_x1);
    cudaGetSymbolAddress((void**)&p_h1,    g_h1);
    cudaGetSymbolAddress((void**)&p_valp,  g_valp);
    cudaGetSymbolAddress((void**)&p_woffh, g_woffh);
    cudaGetSymbolAddress((void**)&p_wattnh,g_wattnh);
    cudaGetSymbolAddress((void**)&p_wvalh, g_wvalh);
    cudaGetSymbolAddress((void**)&p_wouth, g_wouth);
    cudaGetSymbolAddress((void**)&p_w1h,   g_w1h);
    cudaGetSymbolAddress((void**)&p_w2h,   g_w2h);
    cudaGetSymbolAddress((void**)&p_off,   g_off);
    cudaGetSymbolAddress((void**)&p_aw,    g_aw);
    cudaGetSymbolAddress((void**)&p_attn,  g_attn);
    cudaGetSymbolAddress((void**)&p_x,     g_x);
    cudaGetSymbolAddress((void**)&p_ffn,   g_ffn);

    const int M = NTOK;  // 21760 = 340 * 64
    const dim3 blk(256);

    const int SM4 = NST * STAGE_SZ;  // 98304
    cudaFuncSetAttribute(proj_gemm,    cudaFuncAttributeMaxDynamicSharedMemorySize, SM4);
    cudaFuncSetAttribute(mma_gemm<0>,  cudaFuncAttributeMaxDynamicSharedMemorySize, SM4);
    cudaFuncSetAttribute(mma_gemm<1>,  cudaFuncAttributeMaxDynamicSharedMemorySize, SM4);

    // zero padded value buffer (borders must be 0)
    {
        int n4 = NB * PBATCH * CCH * 2 / 16;   // halves -> float4
        zero_kernel<<<(n4 + 255) / 256, blk>>>((float4*)p_valp, n4);
    }
    // all weight transposes in one launch
    wtall_kernel<<<736, dim3(32, 8)>>>(w_off, w_attn, w_val, w_out, w1, w2,
                                       p_woffh, p_wattnh, p_wvalh, p_wouth, p_w1h, p_w2h);
    // q1 = h(src+pos), src1 = h(src)
    {
        int n2 = NTOK * CCH / 2;
        act_h_kernel<<<(n2 + 255) / 256, blk>>>(src, pos, p_q1, p_src1, n2);
    }

    // fused projections: off / logits / value(padded fp16)
    proj_gemm<<<dim3(5, M / 64), blk, SM4>>>(p_q1, p_src1, p_woffh, p_wattnh, p_wvalh,
                                             b_off, b_attn, b_val, p_off, p_aw, p_valp);
    // MSDA gather (softmax fused), padded value
    msda_kernel<<<NTOK, blk>>>(p_valp, p_off, p_aw, refp, p_msda1);
    // attn_out = msda @ w_out + b_out
    mma_gemm<0><<<dim3(2, M / 64), blk, SM4>>>(p_msda1, p_wouth, b_out, p_attn, nullptr, CCH, CCH);
    // x = LN(src + attn_out) -> fp32 + fp16
    ln_kernel<<<(NTOK + 7) / 8, blk>>>(src, p_attn, g1, be1, p_x, p_x1, NTOK);
    // h = relu(x @ w1 + b1) -> fp16
    mma_gemm<1><<<dim3(8, M / 64), blk, SM4>>>(p_x1, p_w1h, b1, nullptr, p_h1, DFF, CCH);
    // ffn = h @ w2 + b2
    mma_gemm<0><<<dim3(2, M / 64), blk, SM4>>>(p_h1, p_w2h, b2, p_ffn, nullptr, CCH, DFF);
    // out = LN(x + ffn)
    ln_kernel<<<(NTOK + 7) / 8, blk>>>(p_x, p_ffn, g2, be2, out, nullptr, NTOK);
}

// round 10
// speedup vs baseline: 4.3548x; 1.0673x over previous
#include <cuda_runtime.h>
#include <cuda_fp16.h>
#include <math.h>

// Problem constants
#define NB   4
#define LEN  5440
#define NTOK (NB * LEN)          // 21760
#define CCH  256
#define NH   8
#define DH   32
#define NL   4
#define NP   4
#define DFF  1024
#define LN_EPS 1e-5f

// Padded value layout: per level pad 2 on all sides, fp16.
// dims (Hl+4)x(Wl+4): 68^2=4624, 36^2=1296, 20^2=400, 12^2=144 ; total 6464
#define PBATCH 6464
#define PB0 0
#define PB1 4624
#define PB2 5920
#define PB3 6320

// ---------------------------------------------------------------------------
// Scratch. Activations/weights single fp16 (fp32 accumulate in MMA).
// ---------------------------------------------------------------------------
__device__ __half g_q1   [NTOK * CCH];
__device__ __half g_src1 [NTOK * CCH];
__device__ __half g_msda1[NTOK * CCH];
__device__ __half g_x1   [NTOK * CCH];
__device__ __half g_h1   [NTOK * DFF];
__device__ __half g_valp [NB * PBATCH * CCH];   // padded fp16 value

__device__ float g_off [NTOK * CCH];
__device__ float g_aw  [NTOK * 128];
__device__ float g_attn[NTOK * CCH];
__device__ float g_x   [NTOK * CCH];
__device__ float g_ffn [NTOK * CCH];

__device__ __half g_woffh [CCH * CCH];
__device__ __half g_wattnh[128 * CCH];
__device__ __half g_wvalh [CCH * CCH];
__device__ __half g_wouth [CCH * CCH];
__device__ __half g_w1h   [DFF * CCH];
__device__ __half g_w2h   [CCH * DFF];

// ---------------------------------------------------------------------------
// helpers
// ---------------------------------------------------------------------------
__device__ __forceinline__ unsigned smem_u32(const void* p) {
    unsigned a;
    asm("{ .reg .u64 t; cvta.to.shared.u64 t, %1; cvt.u32.u64 %0, t; }" : "=r"(a) : "l"(p));
    return a;
}

__device__ __forceinline__ void cp_async16(unsigned dst, const void* src) {
    asm volatile("cp.async.cg.shared.global [%0], [%1], 16;\n" :: "r"(dst), "l"(src));
}
__device__ __forceinline__ void cp_commit() {
    asm volatile("cp.async.commit_group;\n" ::: "memory");
}
template<int N>
__device__ __forceinline__ void cp_wait() {
    asm volatile("cp.async.wait_group %0;\n" :: "n"(N) : "memory");
}

__device__ __forceinline__ void ldm4(unsigned& r0, unsigned& r1, unsigned& r2, unsigned& r3,
                                     unsigned a) {
    asm volatile("ldmatrix.sync.aligned.m8n8.x4.shared.b16 {%0,%1,%2,%3}, [%4];"
                 : "=r"(r0), "=r"(r1), "=r"(r2), "=r"(r3) : "r"(a));
}

__device__ __forceinline__ void mma_f16(float c[4],
                                        unsigned a0, unsigned a1, unsigned a2, unsigned a3,
                                        unsigned b0, unsigned b1) {
    asm volatile(
        "mma.sync.aligned.m16n8k16.row.col.f32.f16.f16.f32 "
        "{%0,%1,%2,%3},{%4,%5,%6,%7},{%8,%9},{%0,%1,%2,%3};"
        : "+f"(c[0]), "+f"(c[1]), "+f"(c[2]), "+f"(c[3])
        : "r"(a0), "r"(a1), "r"(a2), "r"(a3), "r"(b0), "r"(b1));
}

// token -> padded value row base (channel 0)
__device__ __forceinline__ __half* valp_row(__half* Vp, int t) {
    int b = t / LEN;
    int pos = t - b * LEN;
    int base, W4, ys, m, loc;
    if (pos < 4096)      { loc = pos;        base = PB0; W4 = 68; ys = 6; m = 63; }
    else if (pos < 5120) { loc = pos - 4096; base = PB1; W4 = 36; ys = 5; m = 31; }
    else if (pos < 5376) { loc = pos - 5120; base = PB2; W4 = 20; ys = 4; m = 15; }
    else                 { loc = pos - 5376; base = PB3; W4 = 12; ys = 3; m = 7; }
    int y = loc >> ys, x = loc & m;
    return Vp + ((size_t)b * PBATCH + base + (y + 2) * W4 + (x + 2)) * CCH;
}

// ---------------------------------------------------------------------------
// GEMM. BM=64, BN=128. 256 threads (8 warps: 2m x 4n). NST=4 stages.
// OUT_MODE 0: fp32 out (pre-offset). 1: relu + fp16 out (pre-offset, stride N).
// OUT_MODE 2: fp16 into padded value layout (C2 = raw base, col_base = channel).
// ---------------------------------------------------------------------------
#define NST 4
#define GBM 64
#define A_BYTES (GBM * 128)
#define STAGE_SZ ((GBM + 128) * 128)   // 24576

__device__ __forceinline__ void gemm_load_stage(unsigned sb, int stage,
                                                const __half* A, const __half* B,
                                                int K, int kt, int tid) {
    const unsigned abase = sb + stage * STAGE_SZ;
    const unsigned bbase = abase + A_BYTES;
    const __half* ag = A + kt * 64;
    const __half* bg = B + kt * 64;
    #pragma unroll
    for (int i = 0; i < 2; i++) {
        int id = tid + i * 256;
        int r = id >> 3, c = id & 7;
        unsigned off = (unsigned)(r * 128 + ((c ^ (r & 7)) << 4));
        cp_async16(abase + off, ag + (size_t)r * K + c * 8);
    }
    #pragma unroll
    for (int i = 0; i < 4; i++) {
        int id = tid + i * 256;
        int r = id >> 3, c = id & 7;
        unsigned off = (unsigned)(r * 128 + ((c ^ (r & 7)) << 4));
        cp_async16(bbase + off, bg + (size_t)r * K + c * 8);
    }
    cp_commit();
}

template<int OUT_MODE>
__device__ __forceinline__ void gemm_body(const __half* A, const __half* B,
                                          const float* bias, float* Cf, __half* C2,
                                          int N, int K, int row_base, int col_base,
                                          char* smem) {
    const unsigned sb = smem_u32(smem);
    const int tid = threadIdx.x;
    const int warp = tid >> 5, lane = tid & 31;
    const int wm = warp & 1, wn = warp >> 1;
    const int KT = K >> 6;

    float acc[2][4][4];
    #pragma unroll
    for (int i = 0; i < 2; i++)
        #pragma unroll
        for (int j = 0; j < 4; j++)
            #pragma unroll
            for (int r = 0; r < 4; r++) acc[i][j][r] = 0.f;

    #pragma unroll
    for (int s = 0; s < NST - 1; s++) {
        if (s < KT) gemm_load_stage(sb, s, A, B, K, s, tid);
        else        cp_commit();
    }

    const int a_row  = (lane & 15);
    const int a_csel = (lane >> 4);
    const int b_rsel = ((lane >> 4) << 3) + (lane & 7);
    const int b_csel = ((lane >> 3) & 1);

    for (int kt = 0; kt < KT; kt++) {
        const int stage = kt % NST;
        cp_wait<NST - 2>();
        __syncthreads();
        if (kt + NST - 1 < KT)
            gemm_load_stage(sb, (kt + NST - 1) % NST, A, B, K, kt + NST - 1, tid);
        else
            cp_commit();

        const unsigned ab = sb + stage * STAGE_SZ;
        const unsigned bb = ab + A_BYTES;

        #pragma unroll
        for (int kk = 0; kk < 4; kk++) {
            const int c = kk * 2;
            unsigned af[2][4], bf[2][4];
            #pragma unroll
            for (int mi = 0; mi < 2; mi++) {
                int row = wm * 32 + mi * 16 + a_row;
                unsigned so = (unsigned)(row * 128 + (((c + a_csel) ^ (row & 7)) << 4));
                ldm4(af[mi][0], af[mi][1], af[mi][2], af[mi][3], ab + so);
            }
            #pragma unroll
            for (int nj2 = 0; nj2 < 2; nj2++) {
                int nrow = wn * 32 + nj2 * 16 + b_rsel;
                unsigned so = (unsigned)(nrow * 128 + (((c + b_csel) ^ (nrow & 7)) << 4));
                ldm4(bf[nj2][0], bf[nj2][1], bf[nj2][2], bf[nj2][3], bb + so);
            }
            #pragma unroll
            for (int mi = 0; mi < 2; mi++)
                #pragma unroll
                for (int nj = 0; nj < 4; nj++) {
                    const unsigned* b = bf[nj >> 1];
                    unsigned b0 = (nj & 1) ? b[2] : b[0];
                    unsigned b1 = (nj & 1) ? b[3] : b[1];
                    mma_f16(acc[mi][nj], af[mi][0], af[mi][1], af[mi][2], af[mi][3], b0, b1);
                }
        }
    }

    // epilogue
    const int col0 = wn * 32 + (lane & 3) * 2;
    #pragma unroll
    for (int mi = 0; mi < 2; mi++) {
        int row = row_base + wm * 32 + mi * 16 + (lane >> 2);
        __half *p0 = nullptr, *p1 = nullptr;
        if (OUT_MODE == 2) {
            p0 = valp_row(C2, row) + col_base;
            p1 = valp_row(C2, row + 8) + col_base;
        }
        #pragma unroll
        for (int nj = 0; nj < 4; nj++) {
            int col = col0 + nj * 8;
            float b0v = bias[col], b1v = bias[col + 1];
            float v00 = acc[mi][nj][0] + b0v, v01 = acc[mi][nj][1] + b1v;
            float v10 = acc[mi][nj][2] + b0v, v11 = acc[mi][nj][3] + b1v;
            if (OUT_MODE == 0) {
                *(float2*)(Cf + (size_t)row * N + col)       = make_float2(v00, v01);
                *(float2*)(Cf + (size_t)(row + 8) * N + col) = make_float2(v10, v11);
            } else if (OUT_MODE == 1) {
                v00 = fmaxf(v00, 0.f); v01 = fmaxf(v01, 0.f);
                v10 = fmaxf(v10, 0.f); v11 = fmaxf(v11, 0.f);
                *(__half2*)(C2 + (size_t)row * N + col)       = __floats2half2_rn(v00, v01);
                *(__half2*)(C2 + (size_t)(row + 8) * N + col) = __floats2half2_rn(v10, v11);
            } else {
                *(__half2*)(p0 + col) = __floats2half2_rn(v00, v01);
                *(__half2*)(p1 + col) = __floats2half2_rn(v10, v11);
            }
        }
    }
}

template<int OUT_MODE>
__global__ __launch_bounds__(256, 2)
void mma_gemm(const __half* __restrict__ A, const __half* __restrict__ Bt,
              const float* __restrict__ bias, float* __restrict__ Cf,
              __half* __restrict__ C2, int N, int K) {
    extern __shared__ __align__(1024) char smem[];
    const int bx = blockIdx.x, by = blockIdx.y;
    gemm_body<OUT_MODE>(A + (size_t)by * GBM * K,
                        Bt + (size_t)bx * 128 * (size_t)K,
                        bias + bx * 128,
                        Cf ? Cf + bx * 128 : nullptr,
                        C2 ? C2 + bx * 128 : nullptr,
                        N, K, by * GBM, 0, smem);
}

// fused projection GEMM: bx selects {off0, off1, logits, val0, val1}
__global__ __launch_bounds__(256, 2)
void proj_gemm(const __half* __restrict__ q1, const __half* __restrict__ src1,
               const __half* __restrict__ woffh, const __half* __restrict__ wattnh,
               const __half* __restrict__ wvalh,
               const float* __restrict__ b_off, const float* __restrict__ b_attn,
               const float* __restrict__ b_val,
               float* __restrict__ c_off, float* __restrict__ c_aw,
               __half* __restrict__ valp) {
    extern __shared__ __align__(1024) char smem[];
    const int bx = blockIdx.x, by = blockIdx.y;
    const int K = CCH;

    if (bx < 2) {
        gemm_body<0>(q1 + (size_t)by * GBM * K, woffh + (size_t)bx * 128 * K,
                     b_off + bx * 128, c_off + bx * 128, nullptr,
                     CCH, K, by * GBM, 0, smem);
    } else if (bx == 2) {
        gemm_body<0>(q1 + (size_t)by * GBM * K, wattnh,
                     b_attn, c_aw, nullptr,
                     128, K, by * GBM, 0, smem);
    } else {
        int s = bx - 3;
        gemm_body<2>(src1 + (size_t)by * GBM * K, wvalh + (size_t)s * 128 * K,
                     b_val + s * 128, nullptr, valp,
                     CCH, K, by * GBM, s * 128, smem);
    }
}

// ---------------------------------------------------------------------------
// zero-fill padded value buffer (borders must be zero; interior overwritten)
// ---------------------------------------------------------------------------
__global__ void zero_kernel(float4* __restrict__ p, int n) {
    int i = blockIdx.x * blockDim.x + threadIdx.x;
    if (i < n) p[i] = make_float4(0.f, 0.f, 0.f, 0.f);
}

// ---------------------------------------------------------------------------
// fused activation conversion: q1 = h(src+pos), src1 = h(src)
// ---------------------------------------------------------------------------
__global__ void act_h_kernel(const float* __restrict__ src, const float* __restrict__ pos,
                             __half* __restrict__ q1, __half* __restrict__ s1, int n2) {
    int i = blockIdx.x * blockDim.x + threadIdx.x;
    if (i >= n2) return;
    float2 s = ((const float2*)src)[i];
    float2 p = ((const float2*)pos)[i];
    ((__half2*)s1)[i] = __floats2half2_rn(s.x, s.y);
    ((__half2*)q1)[i] = __floats2half2_rn(s.x + p.x, s.y + p.y);
}

// ---------------------------------------------------------------------------
// merged weight transpose: all 6 weights in one launch.
// ---------------------------------------------------------------------------
__global__ void wtall_kernel(const float* __restrict__ w_off, const float* __restrict__ w_attn,
                             const float* __restrict__ w_val, const float* __restrict__ w_out,
                             const float* __restrict__ w1,    const float* __restrict__ w2,
                             __half* __restrict__ d_off, __half* __restrict__ d_attn,
                             __half* __restrict__ d_val, __half* __restrict__ d_out,
                             __half* __restrict__ d_w1,  __half* __restrict__ d_w2) {
    __shared__ float tile[32][33];
    int id = blockIdx.x;
    const float* W; __half* Bt; int K, N, nx, local;
    if      (id < 64)  { W = w_off;  Bt = d_off;  K = CCH; N = CCH; nx = 8;  local = id; }
    else if (id < 96)  { W = w_attn; Bt = d_attn; K = CCH; N = 128; nx = 4;  local = id - 64; }
    else if (id < 160) { W = w_val;  Bt = d_val;  K = CCH; N = CCH; nx = 8;  local = id - 96; }
    else if (id < 224) { W = w_out;  Bt = d_out;  K = CCH; N = CCH; nx = 8;  local = id - 160; }
    else if (id < 480) { W = w1;     Bt = d_w1;   K = CCH; N = DFF; nx = 32; local = id - 224; }
    else               { W = w2;     Bt = d_w2;   K = DFF; N = CCH; nx = 8;  local = id - 480; }
    const int n0 = (local % nx) * 32, k0 = (local / nx) * 32;
    const int tx = threadIdx.x, ty = threadIdx.y;
    #pragma unroll
    for (int i = 0; i < 4; i++) {
        int k = ty + i * 8;
        tile[k][tx] = W[(size_t)(k0 + k) * N + n0 + tx];
    }
    __syncthreads();
    #pragma unroll
    for (int i = 0; i < 4; i++) {
        int n = ty + i * 8;
        Bt[(size_t)(n0 + n) * K + k0 + tx] = __float2half_rn(tile[tx][n]);
    }
}

// ---------------------------------------------------------------------------
// MSDA, padded fp16 value. Lane-parallel point metadata:
// lane p (p = lane & 15) computes point p's cell index + 4 combined weights
// ONCE; the gather loop broadcasts them via shuffles with literal source lane
// (so per-level widths are compile-time). Gather: 4 loads + 4 FMAs per point.
// CTA = 8 consecutive tokens x ONE head; warp = (token, head); lane = channel.
// ---------------------------------------------------------------------------
__global__ void msda_kernel(const __half* __restrict__ valp,
                            const float* __restrict__ off,
                            const float* __restrict__ logits,
                            const float* __restrict__ refp,
                            __half* __restrict__ out1) {
    const int warp = threadIdx.x >> 5;
    const int lane = threadIdx.x & 31;
    const int h  = blockIdx.x & (NH - 1);
    const int t  = (blockIdx.x >> 3) * 8 + warp;
    const int b  = t / LEN;
    const int p  = lane & 15;

    // softmax over 16 logits (lane p owns point p; lanes 16-31 mirror)
    const float* lg = logits + (size_t)t * 128 + h * 16;
    float l0 = lg[p];
    float mx = l0;
    #pragma unroll
    for (int o = 1; o < 16; o <<= 1) mx = fmaxf(mx, __shfl_xor_sync(0xffffffffu, mx, o));
    float e = __expf(l0 - mx);
    float s = e;
    #pragma unroll
    for (int o = 1; o < 16; o <<= 1) s += __shfl_xor_sync(0xffffffffu, s, o);
    const float wgt = e / s;

    // per-point metadata computed by lane p
    const int l  = p >> 2;
    const int Wl = 64 >> l;
    const int W4 = Wl + 4;
    const int base = (l == 0) ? PB0 : (l == 1) ? PB1 : (l == 2) ? PB2 : PB3;
    const float2* off2 = (const float2*)(off + (size_t)t * CCH + h * (NL * NP * 2));
    const float2* ref2 = (const float2*)(refp + (size_t)t * (NL * 2));
    float2 o2 = off2[p];
    float2 r2 = ref2[l];
    const float fW = (float)Wl;
    const float px = fmaf(r2.x, fW, o2.x - 0.5f);
    const float py = fmaf(r2.y, fW, o2.y - 0.5f);
    const float fx = floorf(px), fy = floorf(py);
    const int x0 = (int)fx, y0 = (int)fy;
    const float wx1 = px - fx, wy1 = py - fy;
    const float wx0 = 1.f - wx1, wy0 = 1.f - wy1;
    const int x0c = min(max(x0, -2), Wl);
    const int y0c = min(max(y0, -2), Wl);
    const int rcell = base + (y0c + 2) * W4 + (x0c + 2);
    const float w00 = wgt * wx0 * wy0;
    const float w10 = wgt * wx1 * wy0;
    const float w01 = wgt * wx0 * wy1;
    const float w11 = wgt * wx1 * wy1;

    const __half* vbase = valp + ((size_t)b * PBATCH) * CCH + h * DH + lane;
    float acc = 0.f;

    #pragma unroll
    for (int q = 0; q < 16; q++) {
        const int W4q = (64 >> (q >> 2)) + 4;   // literal per unrolled q
        const int rc  = __shfl_sync(0xffffffffu, rcell, q);
        const float a00 = __shfl_sync(0xffffffffu, w00, q);
        const float a10 = __shfl_sync(0xffffffffu, w10, q);
        const float a01 = __shfl_sync(0xffffffffu, w01, q);
        const float a11 = __shfl_sync(0xffffffffu, w11, q);
        const __half* qp = vbase + (size_t)rc * CCH;
        acc = fmaf(a00, __half2float(qp[0]), acc);
        acc = fmaf(a10, __half2float(qp[CCH]), acc);
        acc = fmaf(a01, __half2float(qp[(size_t)W4q * CCH]), acc);
        acc = fmaf(a11, __half2float(qp[(size_t)(W4q + 1) * CCH]), acc);
    }
    out1[(size_t)t * CCH + h * DH + lane] = __float2half_rn(acc);
}

// ---------------------------------------------------------------------------
// LayerNorm over C=256 of (a+b): warp per row. Optional fp16 output.
// ---------------------------------------------------------------------------
__global__ void ln_kernel(const float* __restrict__ a, const float* __restrict__ b,
                          const float* __restrict__ g, const float* __restrict__ be,
                          float* __restrict__ out, __half* __restrict__ out1,
                          int rows) {
    const int row = blockIdx.x * (blockDim.x >> 5) + (threadIdx.x >> 5);
    const int lane = threadIdx.x & 31;
    if (row >= rows) return;

    const float* pa = a + (size_t)row * CCH;
    const float* pb = b + (size_t)row * CCH;
    float v[8];
    float s = 0.f;
    #pragma unroll
    for (int j = 0; j < 8; j++) {
        int c = lane + 32 * j;
        v[j] = pa[c] + pb[c];
        s += v[j];
    }
    #pragma unroll
    for (int o = 16; o > 0; o >>= 1) s += __shfl_xor_sync(0xffffffffu, s, o);
    const float mean = s * (1.f / CCH);
    float s2 = 0.f;
    #pragma unroll
    for (int j = 0; j < 8; j++) { float d = v[j] - mean; s2 += d * d; }
    #pragma unroll
    for (int o = 16; o > 0; o >>= 1) s2 += __shfl_xor_sync(0xffffffffu, s2, o);
    const float inv = rsqrtf(s2 * (1.f / CCH) + LN_EPS);

    #pragma unroll
    for (int j = 0; j < 8; j++) {
        int c = lane + 32 * j;
        float y = (v[j] - mean) * inv * g[c] + be[c];
        if (out)  out[(size_t)row * CCH + c] = y;
        if (out1) out1[(size_t)row * CCH + c] = __float2half_rn(y);
    }
}

// ---------------------------------------------------------------------------
// launch
// ---------------------------------------------------------------------------
extern "C" void kernel_launch(void* const* d_in, const int* in_sizes, int n_in,
                              void* d_out, int out_size) {
    const float* src   = (const float*)d_in[0];
    const float* pos   = (const float*)d_in[1];
    const float* refp  = (const float*)d_in[2];
    const float* w_off  = (const float*)d_in[6];
    const float* b_off  = (const float*)d_in[7];
    const float* w_attn = (const float*)d_in[8];
    const float* b_attn = (const float*)d_in[9];
    const float* w_val  = (const float*)d_in[10];
    const float* b_val  = (const float*)d_in[11];
    const float* w_out  = (const float*)d_in[12];
    const float* b_out  = (const float*)d_in[13];
    const float* g1     = (const float*)d_in[14];
    const float* be1    = (const float*)d_in[15];
    const float* w1     = (const float*)d_in[16];
    const float* b1     = (const float*)d_in[17];
    const float* w2     = (const float*)d_in[18];
    const float* b2     = (const float*)d_in[19];
    const float* g2     = (const float*)d_in[20];
    const float* be2    = (const float*)d_in[21];
    float* out = (float*)d_out;

    __half *p_q1, *p_src1, *p_msda1, *p_x1, *p_h1, *p_valp;
    __half *p_woffh, *p_wattnh, *p_wvalh, *p_wouth, *p_w1h, *p_w2h;
    float *p_off, *p_aw, *p_attn, *p_x, *p_ffn;
    cudaGetSymbolAddress((void**)&p_q1,    g_q1);
    cudaGetSymbolAddress((void**)&p_src1,  g_src1);
    cudaGetSymbolAddress((void**)&p_msda1, g_msda1);
    cudaGetSymbolAddress((void**)&p_x1,    g_x1);
    cudaGetSymbolAddress((void**)&p_h1,    g_h1);
    cudaGetSymbolAddress((void**)&p_valp,  g_valp);
    cudaGetSymbolAddress((void**)&p_woffh, g_woffh);
    cudaGetSymbolAddress((void**)&p_wattnh,g_wattnh);
    cudaGetSymbolAddress((void**)&p_wvalh, g_wvalh);
    cudaGetSymbolAddress((void**)&p_wouth, g_wouth);
    cudaGetSymbolAddress((void**)&p_w1h,   g_w1h);
    cudaGetSymbolAddress((void**)&p_w2h,   g_w2h);
    cudaGetSymbolAddress((void**)&p_off,   g_off);
    cudaGetSymbolAddress((void**)&p_aw,    g_aw);
    cudaGetSymbolAddress((void**)&p_attn,  g_attn);
    cudaGetSymbolAddress((void**)&p_x,     g_x);
    cudaGetSymbolAddress((void**)&p_ffn,   g_ffn);

    const int M = NTOK;  // 21760 = 340 * 64
    const dim3 blk(256);

    const int SM4 = NST * STAGE_SZ;  // 98304
    cudaFuncSetAttribute(proj_gemm,    cudaFuncAttributeMaxDynamicSharedMemorySize, SM4);
    cudaFuncSetAttribute(mma_gemm<0>,  cudaFuncAttributeMaxDynamicSharedMemorySize, SM4);
    cudaFuncSetAttribute(mma_gemm<1>,  cudaFuncAttributeMaxDynamicSharedMemorySize, SM4);

    // zero padded value buffer (borders must be 0)
    {
        int n4 = NB * PBATCH * CCH * 2 / 16;
        zero_kernel<<<(n4 + 255) / 256, blk>>>((float4*)p_valp, n4);
    }
    // all weight transposes in one launch
    wtall_kernel<<<736, dim3(32, 8)>>>(w_off, w_attn, w_val, w_out, w1, w2,
                                       p_woffh, p_wattnh, p_wvalh, p_wouth, p_w1h, p_w2h);
    // q1 = h(src+pos), src1 = h(src)
    {
        int n2 = NTOK * CCH / 2;
        act_h_kernel<<<(n2 + 255) / 256, blk>>>(src, pos, p_q1, p_src1, n2);
    }

    // fused projections: off / logits / value(padded fp16)
    proj_gemm<<<dim3(5, M / 64), blk, SM4>>>(p_q1, p_src1, p_woffh, p_wattnh, p_wvalh,
                                             b_off, b_attn, b_val, p_off, p_aw, p_valp);
    // MSDA gather (softmax fused, lane-parallel metadata)
    msda_kernel<<<NTOK, blk>>>(p_valp, p_off, p_aw, refp, p_msda1);
    // attn_out = msda @ w_out + b_out
    mma_gemm<0><<<dim3(2, M / 64), blk, SM4>>>(p_msda1, p_wouth, b_out, p_attn, nullptr, CCH, CCH);
    // x = LN(src + attn_out) -> fp32 + fp16
    ln_kernel<<<(NTOK + 7) / 8, blk>>>(src, p_attn, g1, be1, p_x, p_x1, NTOK);
    // h = relu(x @ w1 + b1) -> fp16
    mma_gemm<1><<<dim3(8, M / 64), blk, SM4>>>(p_x1, p_w1h, b1, nullptr, p_h1, DFF, CCH);
    // ffn = h @ w2 + b2
    mma_gemm<0><<<dim3(2, M / 64), blk, SM4>>>(p_h1, p_w2h, b2, p_ffn, nullptr, CCH, DFF);
    // out = LN(x + ffn)
    ln_kernel<<<(NTOK + 7) / 8, blk>>>(p_x, p_ffn, g2, be2, out, nullptr, NTOK);
}

// round 11
// speedup vs baseline: 5.2440x; 1.2042x over previous
#include <cuda_runtime.h>
#include <cuda_fp16.h>
#include <math.h>

// Problem constants
#define NB   4
#define LEN  5440
#define NTOK (NB * LEN)          // 21760
#define CCH  256
#define NH   8
#define DH   32
#define NL   4
#define NP   4
#define DFF  1024
#define LN_EPS 1e-5f

// Padded value layout: per level pad 2 on all sides, fp16.
// dims (Hl+4)x(Wl+4): 68^2=4624, 36^2=1296, 20^2=400, 12^2=144 ; total 6464
#define PBATCH 6464
#define PB0 0
#define PB1 4624
#define PB2 5920
#define PB3 6320

// ---------------------------------------------------------------------------
// Scratch. Activations/weights single fp16 (fp32 accumulate in MMA).
// ---------------------------------------------------------------------------
__device__ __half g_q1   [NTOK * CCH];
__device__ __half g_src1 [NTOK * CCH];
__device__ __half g_msda1[NTOK * CCH];
__device__ __half g_x1   [NTOK * CCH];
__device__ __half g_h1   [NTOK * DFF];
__device__ __half g_valp [NB * PBATCH * CCH];   // padded fp16 value

__device__ float g_off [NTOK * CCH];
__device__ float g_aw  [NTOK * 128];
__device__ float g_attn[NTOK * CCH];
__device__ float g_x   [NTOK * CCH];
__device__ float g_ffn [NTOK * CCH];

__device__ __half g_woffh [CCH * CCH];
__device__ __half g_wattnh[128 * CCH];
__device__ __half g_wvalh [CCH * CCH];
__device__ __half g_wouth [CCH * CCH];
__device__ __half g_w1h   [DFF * CCH];
__device__ __half g_w2h   [CCH * DFF];

// ---------------------------------------------------------------------------
// helpers
// ---------------------------------------------------------------------------
__device__ __forceinline__ unsigned smem_u32(const void* p) {
    unsigned a;
    asm("{ .reg .u64 t; cvta.to.shared.u64 t, %1; cvt.u32.u64 %0, t; }" : "=r"(a) : "l"(p));
    return a;
}

__device__ __forceinline__ void cp_async16(unsigned dst, const void* src) {
    asm volatile("cp.async.cg.shared.global [%0], [%1], 16;\n" :: "r"(dst), "l"(src));
}
__device__ __forceinline__ void cp_commit() {
    asm volatile("cp.async.commit_group;\n" ::: "memory");
}
template<int N>
__device__ __forceinline__ void cp_wait() {
    asm volatile("cp.async.wait_group %0;\n" :: "n"(N) : "memory");
}

__device__ __forceinline__ void ldm4(unsigned& r0, unsigned& r1, unsigned& r2, unsigned& r3,
                                     unsigned a) {
    asm volatile("ldmatrix.sync.aligned.m8n8.x4.shared.b16 {%0,%1,%2,%3}, [%4];"
                 : "=r"(r0), "=r"(r1), "=r"(r2), "=r"(r3) : "r"(a));
}

__device__ __forceinline__ void mma_f16(float c[4],
                                        unsigned a0, unsigned a1, unsigned a2, unsigned a3,
                                        unsigned b0, unsigned b1) {
    asm volatile(
        "mma.sync.aligned.m16n8k16.row.col.f32.f16.f16.f32 "
        "{%0,%1,%2,%3},{%4,%5,%6,%7},{%8,%9},{%0,%1,%2,%3};"
        : "+f"(c[0]), "+f"(c[1]), "+f"(c[2]), "+f"(c[3])
        : "r"(a0), "r"(a1), "r"(a2), "r"(a3), "r"(b0), "r"(b1));
}

// token -> padded value row base (channel 0)
__device__ __forceinline__ __half* valp_row(__half* Vp, int t) {
    int b = t / LEN;
    int pos = t - b * LEN;
    int base, W4, ys, m, loc;
    if (pos < 4096)      { loc = pos;        base = PB0; W4 = 68; ys = 6; m = 63; }
    else if (pos < 5120) { loc = pos - 4096; base = PB1; W4 = 36; ys = 5; m = 31; }
    else if (pos < 5376) { loc = pos - 5120; base = PB2; W4 = 20; ys = 4; m = 15; }
    else                 { loc = pos - 5376; base = PB3; W4 = 12; ys = 3; m = 7; }
    int y = loc >> ys, x = loc & m;
    return Vp + ((size_t)b * PBATCH + base + (y + 2) * W4 + (x + 2)) * CCH;
}

// ---------------------------------------------------------------------------
// GEMM. BM=64, BN=128. 256 threads (8 warps: 2m x 4n). NST=4 stages.
// OUT_MODE 0: fp32 out (pre-offset). 1: relu + fp16 out (pre-offset, stride N).
// OUT_MODE 2: fp16 into padded value layout (C2 = raw base, col_base = channel).
// ---------------------------------------------------------------------------
#define NST 4
#define GBM 64
#define A_BYTES (GBM * 128)
#define STAGE_SZ ((GBM + 128) * 128)   // 24576

__device__ __forceinline__ void gemm_load_stage(unsigned sb, int stage,
                                                const __half* A, const __half* B,
                                                int K, int kt, int tid) {
    const unsigned abase = sb + stage * STAGE_SZ;
    const unsigned bbase = abase + A_BYTES;
    const __half* ag = A + kt * 64;
    const __half* bg = B + kt * 64;
    #pragma unroll
    for (int i = 0; i < 2; i++) {
        int id = tid + i * 256;
        int r = id >> 3, c = id & 7;
        unsigned off = (unsigned)(r * 128 + ((c ^ (r & 7)) << 4));
        cp_async16(abase + off, ag + (size_t)r * K + c * 8);
    }
    #pragma unroll
    for (int i = 0; i < 4; i++) {
        int id = tid + i * 256;
        int r = id >> 3, c = id & 7;
        unsigned off = (unsigned)(r * 128 + ((c ^ (r & 7)) << 4));
        cp_async16(bbase + off, bg + (size_t)r * K + c * 8);
    }
    cp_commit();
}

template<int OUT_MODE>
__device__ __forceinline__ void gemm_body(const __half* A, const __half* B,
                                          const float* bias, float* Cf, __half* C2,
                                          int N, int K, int row_base, int col_base,
                                          char* smem) {
    const unsigned sb = smem_u32(smem);
    const int tid = threadIdx.x;
    const int warp = tid >> 5, lane = tid & 31;
    const int wm = warp & 1, wn = warp >> 1;
    const int KT = K >> 6;

    float acc[2][4][4];
    #pragma unroll
    for (int i = 0; i < 2; i++)
        #pragma unroll
        for (int j = 0; j < 4; j++)
            #pragma unroll
            for (int r = 0; r < 4; r++) acc[i][j][r] = 0.f;

    #pragma unroll
    for (int s = 0; s < NST - 1; s++) {
        if (s < KT) gemm_load_stage(sb, s, A, B, K, s, tid);
        else        cp_commit();
    }

    const int a_row  = (lane & 15);
    const int a_csel = (lane >> 4);
    const int b_rsel = ((lane >> 4) << 3) + (lane & 7);
    const int b_csel = ((lane >> 3) & 1);

    for (int kt = 0; kt < KT; kt++) {
        const int stage = kt % NST;
        cp_wait<NST - 2>();
        __syncthreads();
        if (kt + NST - 1 < KT)
            gemm_load_stage(sb, (kt + NST - 1) % NST, A, B, K, kt + NST - 1, tid);
        else
            cp_commit();

        const unsigned ab = sb + stage * STAGE_SZ;
        const unsigned bb = ab + A_BYTES;

        #pragma unroll
        for (int kk = 0; kk < 4; kk++) {
            const int c = kk * 2;
            unsigned af[2][4], bf[2][4];
            #pragma unroll
            for (int mi = 0; mi < 2; mi++) {
                int row = wm * 32 + mi * 16 + a_row;
                unsigned so = (unsigned)(row * 128 + (((c + a_csel) ^ (row & 7)) << 4));
                ldm4(af[mi][0], af[mi][1], af[mi][2], af[mi][3], ab + so);
            }
            #pragma unroll
            for (int nj2 = 0; nj2 < 2; nj2++) {
                int nrow = wn * 32 + nj2 * 16 + b_rsel;
                unsigned so = (unsigned)(nrow * 128 + (((c + b_csel) ^ (nrow & 7)) << 4));
                ldm4(bf[nj2][0], bf[nj2][1], bf[nj2][2], bf[nj2][3], bb + so);
            }
            #pragma unroll
            for (int mi = 0; mi < 2; mi++)
                #pragma unroll
                for (int nj = 0; nj < 4; nj++) {
                    const unsigned* b = bf[nj >> 1];
                    unsigned b0 = (nj & 1) ? b[2] : b[0];
                    unsigned b1 = (nj & 1) ? b[3] : b[1];
                    mma_f16(acc[mi][nj], af[mi][0], af[mi][1], af[mi][2], af[mi][3], b0, b1);
                }
        }
    }

    // epilogue
    const int col0 = wn * 32 + (lane & 3) * 2;
    #pragma unroll
    for (int mi = 0; mi < 2; mi++) {
        int row = row_base + wm * 32 + mi * 16 + (lane >> 2);
        __half *p0 = nullptr, *p1 = nullptr;
        if (OUT_MODE == 2) {
            p0 = valp_row(C2, row) + col_base;
            p1 = valp_row(C2, row + 8) + col_base;
        }
        #pragma unroll
        for (int nj = 0; nj < 4; nj++) {
            int col = col0 + nj * 8;
            float b0v = bias[col], b1v = bias[col + 1];
            float v00 = acc[mi][nj][0] + b0v, v01 = acc[mi][nj][1] + b1v;
            float v10 = acc[mi][nj][2] + b0v, v11 = acc[mi][nj][3] + b1v;
            if (OUT_MODE == 0) {
                *(float2*)(Cf + (size_t)row * N + col)       = make_float2(v00, v01);
                *(float2*)(Cf + (size_t)(row + 8) * N + col) = make_float2(v10, v11);
            } else if (OUT_MODE == 1) {
                v00 = fmaxf(v00, 0.f); v01 = fmaxf(v01, 0.f);
                v10 = fmaxf(v10, 0.f); v11 = fmaxf(v11, 0.f);
                *(__half2*)(C2 + (size_t)row * N + col)       = __floats2half2_rn(v00, v01);
                *(__half2*)(C2 + (size_t)(row + 8) * N + col) = __floats2half2_rn(v10, v11);
            } else {
                *(__half2*)(p0 + col) = __floats2half2_rn(v00, v01);
                *(__half2*)(p1 + col) = __floats2half2_rn(v10, v11);
            }
        }
    }
}

template<int OUT_MODE>
__global__ __launch_bounds__(256, 2)
void mma_gemm(const __half* __restrict__ A, const __half* __restrict__ Bt,
              const float* __restrict__ bias, float* __restrict__ Cf,
              __half* __restrict__ C2, int N, int K) {
    extern __shared__ __align__(1024) char smem[];
    const int bx = blockIdx.x, by = blockIdx.y;
    gemm_body<OUT_MODE>(A + (size_t)by * GBM * K,
                        Bt + (size_t)bx * 128 * (size_t)K,
                        bias + bx * 128,
                        Cf ? Cf + bx * 128 : nullptr,
                        C2 ? C2 + bx * 128 : nullptr,
                        N, K, by * GBM, 0, smem);
}

// fused projection GEMM: bx selects {off0, off1, logits, val0, val1}
__global__ __launch_bounds__(256, 2)
void proj_gemm(const __half* __restrict__ q1, const __half* __restrict__ src1,
               const __half* __restrict__ woffh, const __half* __restrict__ wattnh,
               const __half* __restrict__ wvalh,
               const float* __restrict__ b_off, const float* __restrict__ b_attn,
               const float* __restrict__ b_val,
               float* __restrict__ c_off, float* __restrict__ c_aw,
               __half* __restrict__ valp) {
    extern __shared__ __align__(1024) char smem[];
    const int bx = blockIdx.x, by = blockIdx.y;
    const int K = CCH;

    if (bx < 2) {
        gemm_body<0>(q1 + (size_t)by * GBM * K, woffh + (size_t)bx * 128 * K,
                     b_off + bx * 128, c_off + bx * 128, nullptr,
                     CCH, K, by * GBM, 0, smem);
    } else if (bx == 2) {
        gemm_body<0>(q1 + (size_t)by * GBM * K, wattnh,
                     b_attn, c_aw, nullptr,
                     128, K, by * GBM, 0, smem);
    } else {
        int s = bx - 3;
        gemm_body<2>(src1 + (size_t)by * GBM * K, wvalh + (size_t)s * 128 * K,
                     b_val + s * 128, nullptr, valp,
                     CCH, K, by * GBM, s * 128, smem);
    }
}

// ---------------------------------------------------------------------------
// zero-fill padded value buffer (borders must be zero; interior overwritten)
// ---------------------------------------------------------------------------
__global__ void zero_kernel(float4* __restrict__ p, int n) {
    int i = blockIdx.x * blockDim.x + threadIdx.x;
    if (i < n) p[i] = make_float4(0.f, 0.f, 0.f, 0.f);
}

// ---------------------------------------------------------------------------
// fused activation conversion: q1 = h(src+pos), src1 = h(src)
// ---------------------------------------------------------------------------
__global__ void act_h_kernel(const float* __restrict__ src, const float* __restrict__ pos,
                             __half* __restrict__ q1, __half* __restrict__ s1, int n2) {
    int i = blockIdx.x * blockDim.x + threadIdx.x;
    if (i >= n2) return;
    float2 s = ((const float2*)src)[i];
    float2 p = ((const float2*)pos)[i];
    ((__half2*)s1)[i] = __floats2half2_rn(s.x, s.y);
    ((__half2*)q1)[i] = __floats2half2_rn(s.x + p.x, s.y + p.y);
}

// ---------------------------------------------------------------------------
// merged weight transpose: all 6 weights in one launch.
// ---------------------------------------------------------------------------
__global__ void wtall_kernel(const float* __restrict__ w_off, const float* __restrict__ w_attn,
                             const float* __restrict__ w_val, const float* __restrict__ w_out,
                             const float* __restrict__ w1,    const float* __restrict__ w2,
                             __half* __restrict__ d_off, __half* __restrict__ d_attn,
                             __half* __restrict__ d_val, __half* __restrict__ d_out,
                             __half* __restrict__ d_w1,  __half* __restrict__ d_w2) {
    __shared__ float tile[32][33];
    int id = blockIdx.x;
    const float* W; __half* Bt; int K, N, nx, local;
    if      (id < 64)  { W = w_off;  Bt = d_off;  K = CCH; N = CCH; nx = 8;  local = id; }
    else if (id < 96)  { W = w_attn; Bt = d_attn; K = CCH; N = 128; nx = 4;  local = id - 64; }
    else if (id < 160) { W = w_val;  Bt = d_val;  K = CCH; N = CCH; nx = 8;  local = id - 96; }
    else if (id < 224) { W = w_out;  Bt = d_out;  K = CCH; N = CCH; nx = 8;  local = id - 160; }
    else if (id < 480) { W = w1;     Bt = d_w1;   K = CCH; N = DFF; nx = 32; local = id - 224; }
    else               { W = w2;     Bt = d_w2;   K = DFF; N = CCH; nx = 8;  local = id - 480; }
    const int n0 = (local % nx) * 32, k0 = (local / nx) * 32;
    const int tx = threadIdx.x, ty = threadIdx.y;
    #pragma unroll
    for (int i = 0; i < 4; i++) {
        int k = ty + i * 8;
        tile[k][tx] = W[(size_t)(k0 + k) * N + n0 + tx];
    }
    __syncthreads();
    #pragma unroll
    for (int i = 0; i < 4; i++) {
        int n = ty + i * 8;
        Bt[(size_t)(n0 + n) * K + k0 + tx] = __float2half_rn(tile[tx][n]);
    }
}

// ---------------------------------------------------------------------------
// MSDA, padded fp16 value, half2 channels: ONE warp serves TWO heads.
// Lanes 0-15: head 2hp (lane p = point id, also channel-pair id);
// lanes 16-31: head 2hp+1. Each lane computes its head's point-p metadata;
// gather broadcasts from source lane q | (lane & 16). Lane loads __half2
// (channels 2p, 2p+1 of its head). CTA = 2 tokens x 4 head-pairs (8 warps).
// ---------------------------------------------------------------------------
__global__ void msda_kernel(const __half* __restrict__ valp,
                            const float* __restrict__ off,
                            const float* __restrict__ logits,
                            const float* __restrict__ refp,
                            __half* __restrict__ out1) {
    const int warp = threadIdx.x >> 5;
    const int lane = threadIdx.x & 31;
    const int hp = warp & 3;                      // head pair 0..3
    const int t  = blockIdx.x * 2 + (warp >> 2);
    const int b  = t / LEN;
    const int p  = lane & 15;                     // point id / channel-pair id
    const int h  = hp * 2 + (lane >> 4);          // this lane's head
    const int hsel = lane & 16;

    // softmax over this head's 16 logits (xor offsets 1..8 stay in half-warp)
    const float* lg = logits + (size_t)t * 128 + h * 16;
    float l0 = lg[p];
    float mx = l0;
    #pragma unroll
    for (int o = 1; o < 16; o <<= 1) mx = fmaxf(mx, __shfl_xor_sync(0xffffffffu, mx, o));
    float e = __expf(l0 - mx);
    float s = e;
    #pragma unroll
    for (int o = 1; o < 16; o <<= 1) s += __shfl_xor_sync(0xffffffffu, s, o);
    const float wgt = e / s;

    // metadata for point p of head h
    const int l  = p >> 2;
    const int Wl = 64 >> l;
    const int W4 = Wl + 4;
    const int base = (l == 0) ? PB0 : (l == 1) ? PB1 : (l == 2) ? PB2 : PB3;
    const float2* off2 = (const float2*)(off + (size_t)t * CCH + h * (NL * NP * 2));
    const float2* ref2 = (const float2*)(refp + (size_t)t * (NL * 2));
    float2 o2 = off2[p];
    float2 r2 = ref2[l];
    const float fW = (float)Wl;
    const float px = fmaf(r2.x, fW, o2.x - 0.5f);
    const float py = fmaf(r2.y, fW, o2.y - 0.5f);
    const float fx = floorf(px), fy = floorf(py);
    const int x0 = (int)fx, y0 = (int)fy;
    const float wx1 = px - fx, wy1 = py - fy;
    const float wx0 = 1.f - wx1, wy0 = 1.f - wy1;
    const int x0c = min(max(x0, -2), Wl);
    const int y0c = min(max(y0, -2), Wl);
    const int rcell = base + (y0c + 2) * W4 + (x0c + 2);
    const float w00 = wgt * wx0 * wy0;
    const float w10 = wgt * wx1 * wy0;
    const float w01 = wgt * wx0 * wy1;
    const float w11 = wgt * wx1 * wy1;

    // gather: lane covers channels (2p, 2p+1) of head h
    const __half* vbase = valp + ((size_t)b * PBATCH) * CCH + h * DH + p * 2;
    float accx = 0.f, accy = 0.f;

    #pragma unroll
    for (int q = 0; q < 16; q++) {
        const int W4q = (64 >> (q >> 2)) + 4;     // literal per unrolled q
        const int src = q | hsel;
        const int rc  = __shfl_sync(0xffffffffu, rcell, src);
        const float a00 = __shfl_sync(0xffffffffu, w00, src);
        const float a10 = __shfl_sync(0xffffffffu, w10, src);
        const float a01 = __shfl_sync(0xffffffffu, w01, src);
        const float a11 = __shfl_sync(0xffffffffu, w11, src);
        const __half* qp = vbase + (size_t)rc * CCH;
        float2 v00 = __half22float2(*(const __half2*)(qp));
        float2 v10 = __half22float2(*(const __half2*)(qp + CCH));
        float2 v01 = __half22float2(*(const __half2*)(qp + (size_t)W4q * CCH));
        float2 v11 = __half22float2(*(const __half2*)(qp + (size_t)(W4q + 1) * CCH));
        accx = fmaf(a00, v00.x, accx); accy = fmaf(a00, v00.y, accy);
        accx = fmaf(a10, v10.x, accx); accy = fmaf(a10, v10.y, accy);
        accx = fmaf(a01, v01.x, accx); accy = fmaf(a01, v01.y, accy);
        accx = fmaf(a11, v11.x, accx); accy = fmaf(a11, v11.y, accy);
    }
    *(__half2*)(out1 + (size_t)t * CCH + h * DH + p * 2) = __floats2half2_rn(accx, accy);
}

// ---------------------------------------------------------------------------
// LayerNorm over C=256 of (a+b): warp per row. Optional fp16 output.
// ---------------------------------------------------------------------------
__global__ void ln_kernel(const float* __restrict__ a, const float* __restrict__ b,
                          const float* __restrict__ g, const float* __restrict__ be,
                          float* __restrict__ out, __half* __restrict__ out1,
                          int rows) {
    const int row = blockIdx.x * (blockDim.x >> 5) + (threadIdx.x >> 5);
    const int lane = threadIdx.x & 31;
    if (row >= rows) return;

    const float* pa = a + (size_t)row * CCH;
    const float* pb = b + (size_t)row * CCH;
    float v[8];
    float s = 0.f;
    #pragma unroll
    for (int j = 0; j < 8; j++) {
        int c = lane + 32 * j;
        v[j] = pa[c] + pb[c];
        s += v[j];
    }
    #pragma unroll
    for (int o = 16; o > 0; o >>= 1) s += __shfl_xor_sync(0xffffffffu, s, o);
    const float mean = s * (1.f / CCH);
    float s2 = 0.f;
    #pragma unroll
    for (int j = 0; j < 8; j++) { float d = v[j] - mean; s2 += d * d; }
    #pragma unroll
    for (int o = 16; o > 0; o >>= 1) s2 += __shfl_xor_sync(0xffffffffu, s2, o);
    const float inv = rsqrtf(s2 * (1.f / CCH) + LN_EPS);

    #pragma unroll
    for (int j = 0; j < 8; j++) {
        int c = lane + 32 * j;
        float y = (v[j] - mean) * inv * g[c] + be[c];
        if (out)  out[(size_t)row * CCH + c] = y;
        if (out1) out1[(size_t)row * CCH + c] = __float2half_rn(y);
    }
}

// ---------------------------------------------------------------------------
// launch
// ---------------------------------------------------------------------------
extern "C" void kernel_launch(void* const* d_in, const int* in_sizes, int n_in,
                              void* d_out, int out_size) {
    const float* src   = (const float*)d_in[0];
    const float* pos   = (const float*)d_in[1];
    const float* refp  = (const float*)d_in[2];
    const float* w_off  = (const float*)d_in[6];
    const float* b_off  = (const float*)d_in[7];
    const float* w_attn = (const float*)d_in[8];
    const float* b_attn = (const float*)d_in[9];
    const float* w_val  = (const float*)d_in[10];
    const float* b_val  = (const float*)d_in[11];
    const float* w_out  = (const float*)d_in[12];
    const float* b_out  = (const float*)d_in[13];
    const float* g1     = (const float*)d_in[14];
    const float* be1    = (const float*)d_in[15];
    const float* w1     = (const float*)d_in[16];
    const float* b1     = (const float*)d_in[17];
    const float* w2     = (const float*)d_in[18];
    const float* b2     = (const float*)d_in[19];
    const float* g2     = (const float*)d_in[20];
    const float* be2    = (const float*)d_in[21];
    float* out = (float*)d_out;

    __half *p_q1, *p_src1, *p_msda1, *p_x1, *p_h1, *p_valp;
    __half *p_woffh, *p_wattnh, *p_wvalh, *p_wouth, *p_w1h, *p_w2h;
    float *p_off, *p_aw, *p_attn, *p_x, *p_ffn;
    cudaGetSymbolAddress((void**)&p_q1,    g_q1);
    cudaGetSymbolAddress((void**)&p_src1,  g_src1);
    cudaGetSymbolAddress((void**)&p_msda1, g_msda1);
    cudaGetSymbolAddress((void**)&p_x1,    g_x1);
    cudaGetSymbolAddress((void**)&p_h1,    g_h1);
    cudaGetSymbolAddress((void**)&p_valp,  g_valp);
    cudaGetSymbolAddress((void**)&p_woffh, g_woffh);
    cudaGetSymbolAddress((void**)&p_wattnh,g_wattnh);
    cudaGetSymbolAddress((void**)&p_wvalh, g_wvalh);
    cudaGetSymbolAddress((void**)&p_wouth, g_wouth);
    cudaGetSymbolAddress((void**)&p_w1h,   g_w1h);
    cudaGetSymbolAddress((void**)&p_w2h,   g_w2h);
    cudaGetSymbolAddress((void**)&p_off,   g_off);
    cudaGetSymbolAddress((void**)&p_aw,    g_aw);
    cudaGetSymbolAddress((void**)&p_attn,  g_attn);
    cudaGetSymbolAddress((void**)&p_x,     g_x);
    cudaGetSymbolAddress((void**)&p_ffn,   g_ffn);

    const int M = NTOK;  // 21760 = 340 * 64
    const dim3 blk(256);

    const int SM4 = NST * STAGE_SZ;  // 98304
    cudaFuncSetAttribute(proj_gemm,    cudaFuncAttributeMaxDynamicSharedMemorySize, SM4);
    cudaFuncSetAttribute(mma_gemm<0>,  cudaFuncAttributeMaxDynamicSharedMemorySize, SM4);
    cudaFuncSetAttribute(mma_gemm<1>,  cudaFuncAttributeMaxDynamicSharedMemorySize, SM4);

    // zero padded value buffer (borders must be 0)
    {
        int n4 = NB * PBATCH * CCH * 2 / 16;
        zero_kernel<<<(n4 + 255) / 256, blk>>>((float4*)p_valp, n4);
    }
    // all weight transposes in one launch
    wtall_kernel<<<736, dim3(32, 8)>>>(w_off, w_attn, w_val, w_out, w1, w2,
                                       p_woffh, p_wattnh, p_wvalh, p_wouth, p_w1h, p_w2h);
    // q1 = h(src+pos), src1 = h(src)
    {
        int n2 = NTOK * CCH / 2;
        act_h_kernel<<<(n2 + 255) / 256, blk>>>(src, pos, p_q1, p_src1, n2);
    }

    // fused projections: off / logits / value(padded fp16)
    proj_gemm<<<dim3(5, M / 64), blk, SM4>>>(p_q1, p_src1, p_woffh, p_wattnh, p_wvalh,
                                             b_off, b_attn, b_val, p_off, p_aw, p_valp);
    // MSDA gather (softmax fused, half2 channels, 2 heads per warp)
    msda_kernel<<<NTOK / 2, blk>>>(p_valp, p_off, p_aw, refp, p_msda1);
    // attn_out = msda @ w_out + b_out
    mma_gemm<0><<<dim3(2, M / 64), blk, SM4>>>(p_msda1, p_wouth, b_out, p_attn, nullptr, CCH, CCH);
    // x = LN(src + attn_out) -> fp32 + fp16
    ln_kernel<<<(NTOK + 7) / 8, blk>>>(src, p_attn, g1, be1, p_x, p_x1, NTOK);
    // h = relu(x @ w1 + b1) -> fp16
    mma_gemm<1><<<dim3(8, M / 64), blk, SM4>>>(p_x1, p_w1h, b1, nullptr, p_h1, DFF, CCH);
    // ffn = h @ w2 + b2
    mma_gemm<0><<<dim3(2, M / 64), blk, SM4>>>(p_h1, p_w2h, b2, p_ffn, nullptr, CCH, DFF);
    // out = LN(x + ffn)
    ln_kernel<<<(NTOK + 7) / 8, blk>>>(p_x, p_ffn, g2, be2, out, nullptr, NTOK);
}